// round 3
// baseline (speedup 1.0000x reference)
#include <cuda_runtime.h>
#include <cuda_bf16.h>
#include <math.h>

// ----------------------------------------------------------------------------
// Problem constants (fixed by the reference)
// ----------------------------------------------------------------------------
#define NN     50000     // nodes
#define EE     200000    // directed edges (before self loops)
#define HEADS  4
#define GG     512
#define HID    1024
#define OUTD   128
#define D1     78        // conv1 per-head channels
#define D2     312       // conv2 per-head channels
#define D3     1248      // conv3 channels (1 head)
#define NEG    0.2f

// ----------------------------------------------------------------------------
// Scratch (device globals -> no allocations, referenced directly in kernels)
// ----------------------------------------------------------------------------
__device__ float g_bufA[(size_t)NN * D3];   // layer output ping
__device__ float g_bufB[(size_t)NN * D3];   // h = x @ W pong
__device__ float g_asrc[(size_t)NN * HEADS];
__device__ float g_adst[(size_t)NN * HEADS];
__device__ int   g_counts[NN];
__device__ int   g_cursor[NN];
__device__ int   g_ptr[NN + 1];
__device__ int   g_csrsrc[EE];
__device__ float g_pool[GG * D3];
__device__ float g_fc1[GG * HID];

__device__ __forceinline__ float lrelu(float x) { return x > 0.f ? x : NEG * x; }

// Operand selection: resolve scratch-buffer addresses ON DEVICE so we never
// need cudaGetSymbolAddress on the host.
__device__ __forceinline__ const float* sel_cf(int sel, const float* ext) {
    switch (sel) {
        case 1: return g_bufA;
        case 2: return g_bufB;
        case 3: return g_pool;
        case 4: return g_fc1;
        default: return ext;
    }
}
__device__ __forceinline__ float* sel_f(int sel, float* ext) {
    switch (sel) {
        case 1: return g_bufA;
        case 2: return g_bufB;
        case 3: return g_pool;
        case 4: return g_fc1;
        default: return ext;
    }
}

// ----------------------------------------------------------------------------
// CSR construction  (edge_index is INT32: JAX x64 is disabled by default)
// ----------------------------------------------------------------------------
__global__ void zero_counts_kernel() {
    int i = blockIdx.x * blockDim.x + threadIdx.x;
    if (i < NN) { g_counts[i] = 0; g_cursor[i] = 0; }
}

__global__ void hist_kernel(const int* __restrict__ ei) {
    int e = blockIdx.x * blockDim.x + threadIdx.x;
    if (e < EE) {
        int c = ei[EE + e];
        atomicAdd(&g_counts[c], 1);
    }
}

__global__ void scan_kernel() {
    __shared__ int sh[1024];
    __shared__ int s_off;
    int tid = threadIdx.x;
    if (tid == 0) { s_off = 0; g_ptr[0] = 0; }
    __syncthreads();
    for (int base = 0; base < NN; base += 1024) {
        int v = (base + tid < NN) ? g_counts[base + tid] : 0;
        sh[tid] = v;
        __syncthreads();
        for (int s = 1; s < 1024; s <<= 1) {
            int t = (tid >= s) ? sh[tid - s] : 0;
            __syncthreads();
            sh[tid] += t;
            __syncthreads();
        }
        int off = s_off;
        if (base + tid < NN) g_ptr[base + tid + 1] = off + sh[tid];
        __syncthreads();
        if (tid == 0) s_off = off + sh[1023];
        __syncthreads();
    }
}

__global__ void csr_fill_kernel(const int* __restrict__ ei) {
    int e = blockIdx.x * blockDim.x + threadIdx.x;
    if (e < EE) {
        int r = ei[e];
        int c = ei[EE + e];
        int pos = g_ptr[c] + atomicAdd(&g_cursor[c], 1);
        g_csrsrc[pos] = r;
    }
}

// ----------------------------------------------------------------------------
// SGEMM: C[M,N] = A[M,K] @ B[K,N] (+bias, relu optional)
// 128x128 tile, BK=8, 256 threads, 8x8 microtile
// ----------------------------------------------------------------------------
__global__ void __launch_bounds__(256)
sgemm128(const float* Aext, int Asel, const float* __restrict__ B,
         float* Cext, int Csel, int M, int N, int K,
         const float* __restrict__ bias, int fuse)
{
    const float* A = sel_cf(Asel, Aext);
    float* Cm = sel_f(Csel, Cext);

    __shared__ float As[8][128];
    __shared__ float Bs[8][132];   // +4 pad to break conflicts

    int tid = threadIdx.x;
    int bm = blockIdx.y * 128, bn = blockIdx.x * 128;
    int tx = tid & 15, ty = tid >> 4;

    float acc[8][8];
#pragma unroll
    for (int i = 0; i < 8; i++)
#pragma unroll
        for (int j = 0; j < 8; j++) acc[i][j] = 0.f;

    for (int k0 = 0; k0 < K; k0 += 8) {
        // A tile: 128(m) x 8(k), scalar loads (K may be unaligned)
#pragma unroll
        for (int i = 0; i < 4; i++) {
            int flat = tid * 4 + i;
            int m = flat >> 3, kk = flat & 7;
            int gm = bm + m, gk = k0 + kk;
            float v = 0.f;
            if (gm < M && gk < K) v = A[(size_t)gm * K + gk];
            As[kk][m] = v;
        }
        // B tile: 8(k) x 128(n)
        {
            int kk = tid >> 5;
            int n4 = (tid & 31) * 4;
            int gk = k0 + kk, gn = bn + n4;
            float v0 = 0.f, v1 = 0.f, v2 = 0.f, v3 = 0.f;
            if (gk < K) {
                const float* brow = B + (size_t)gk * N;
                if (gn + 3 < N) {
                    v0 = brow[gn]; v1 = brow[gn + 1];
                    v2 = brow[gn + 2]; v3 = brow[gn + 3];
                } else {
                    if (gn + 0 < N) v0 = brow[gn + 0];
                    if (gn + 1 < N) v1 = brow[gn + 1];
                    if (gn + 2 < N) v2 = brow[gn + 2];
                    if (gn + 3 < N) v3 = brow[gn + 3];
                }
            }
            Bs[kk][n4 + 0] = v0; Bs[kk][n4 + 1] = v1;
            Bs[kk][n4 + 2] = v2; Bs[kk][n4 + 3] = v3;
        }
        __syncthreads();

#pragma unroll
        for (int kk = 0; kk < 8; kk++) {
            float a[8], b[8];
#pragma unroll
            for (int i = 0; i < 8; i++) a[i] = As[kk][ty * 8 + i];
#pragma unroll
            for (int j = 0; j < 8; j++) b[j] = Bs[kk][tx * 8 + j];
#pragma unroll
            for (int i = 0; i < 8; i++)
#pragma unroll
                for (int j = 0; j < 8; j++)
                    acc[i][j] = fmaf(a[i], b[j], acc[i][j]);
        }
        __syncthreads();
    }

#pragma unroll
    for (int i = 0; i < 8; i++) {
        int gm = bm + ty * 8 + i;
        if (gm >= M) continue;
#pragma unroll
        for (int j = 0; j < 8; j++) {
            int gn = bn + tx * 8 + j;
            if (gn >= N) continue;
            float v = acc[i][j];
            if (fuse) { v += bias[gn]; v = fmaxf(v, 0.f); }
            Cm[(size_t)gm * N + gn] = v;
        }
    }
}

// ----------------------------------------------------------------------------
// Per-node attention scores from g_bufB: one warp per node
// ----------------------------------------------------------------------------
__global__ void attn_scores(const float* __restrict__ att_s,
                            const float* __restrict__ att_d,
                            int H, int C)
{
    int warp = (blockIdx.x * blockDim.x + threadIdx.x) >> 5;
    int lane = threadIdx.x & 31;
    if (warp >= NN) return;
    for (int h = 0; h < H; h++) {
        const float* hr = g_bufB + (size_t)warp * H * C + (size_t)h * C;
        float ss = 0.f, sd = 0.f;
        for (int c = lane; c < C; c += 32) {
            float hv = hr[c];
            ss = fmaf(hv, att_s[h * C + c], ss);
            sd = fmaf(hv, att_d[h * C + c], sd);
        }
#pragma unroll
        for (int o = 16; o; o >>= 1) {
            ss += __shfl_down_sync(0xFFFFFFFFu, ss, o);
            sd += __shfl_down_sync(0xFFFFFFFFu, sd, o);
        }
        if (lane == 0) {
            g_asrc[warp * H + h] = ss;
            g_adst[warp * H + h] = sd;
        }
    }
}

// ----------------------------------------------------------------------------
// GAT aggregation: per target node, softmax over incoming edges (+self loop),
// weighted sum of source features (from g_bufB), +bias, ReLU -> g_bufA.
// One 128-thread block per node.
// ----------------------------------------------------------------------------
template<int H, int C, int NCH>
__global__ void __launch_bounds__(128)
gat_agg(const float* __restrict__ bias)
{
    constexpr int HC = H * C;
    constexpr int CHUNK = 64;
    int i = blockIdx.x;
    int tid = threadIdx.x;

    __shared__ float s_alpha[CHUNK][H];
    __shared__ int   s_src[CHUNK];

    const float* hbuf = g_bufB;
    float* out = g_bufA;

    float adsti[H], m[H], den[H], eself[H], aself[H];
#pragma unroll
    for (int h = 0; h < H; h++) adsti[h] = g_adst[i * H + h];
#pragma unroll
    for (int h = 0; h < H; h++) {
        eself[h] = lrelu(g_asrc[i * H + h] + adsti[h]);
        m[h] = eself[h];
    }

    int beg = g_ptr[i];
    int deg = g_ptr[i + 1] - beg;

    // pass 1: max (all threads redundantly; addresses are warp-uniform)
    for (int j = 0; j < deg; j++) {
        int s = g_csrsrc[beg + j];
#pragma unroll
        for (int h = 0; h < H; h++) {
            float e = lrelu(g_asrc[s * H + h] + adsti[h]);
            m[h] = fmaxf(m[h], e);
        }
    }
    // pass 2: denom
#pragma unroll
    for (int h = 0; h < H; h++) den[h] = __expf(eself[h] - m[h]);
    for (int j = 0; j < deg; j++) {
        int s = g_csrsrc[beg + j];
#pragma unroll
        for (int h = 0; h < H; h++) {
            float e = lrelu(g_asrc[s * H + h] + adsti[h]);
            den[h] += __expf(e - m[h]);
        }
    }
#pragma unroll
    for (int h = 0; h < H; h++)
        aself[h] = __expf(eself[h] - m[h]) / (den[h] + 1e-16f);

    // accumulators: self contribution first
    float acc[NCH];
    int   hidx[NCH];
#pragma unroll
    for (int t = 0; t < NCH; t++) {
        int c = tid + t * 128;
        hidx[t] = c / C;
        acc[t] = (c < HC) ? aself[hidx[t]] * hbuf[(size_t)i * HC + c] : 0.f;
    }

    // pass 3: chunked edge accumulation
    for (int cb = 0; cb < deg; cb += CHUNK) {
        int cn = min(CHUNK, deg - cb);
        __syncthreads();
        if (tid < cn) {
            int s = g_csrsrc[beg + cb + tid];
            s_src[tid] = s;
#pragma unroll
            for (int h = 0; h < H; h++) {
                float e = lrelu(g_asrc[s * H + h] + adsti[h]);
                s_alpha[tid][h] = __expf(e - m[h]) / (den[h] + 1e-16f);
            }
        }
        __syncthreads();
        for (int j = 0; j < cn; j++) {
            const float* hr = hbuf + (size_t)s_src[j] * HC;
            float al[H];
#pragma unroll
            for (int h = 0; h < H; h++) al[h] = s_alpha[j][h];
#pragma unroll
            for (int t = 0; t < NCH; t++) {
                int c = tid + t * 128;
                if (c < HC) acc[t] = fmaf(al[hidx[t]], hr[c], acc[t]);
            }
        }
    }

#pragma unroll
    for (int t = 0; t < NCH; t++) {
        int c = tid + t * 128;
        if (c < HC) {
            float v = acc[t] + bias[c];
            out[(size_t)i * HC + c] = fmaxf(v, 0.f);
        }
    }
}

// ----------------------------------------------------------------------------
// Global max pool over sorted batch (int32): g_bufA -> g_pool
// ----------------------------------------------------------------------------
__global__ void pool_max(const int* __restrict__ batch)
{
    int g = blockIdx.x;
    int c = blockIdx.y * 128 + threadIdx.x;

    int lo = 0, hi = NN;
    while (lo < hi) { int mid = (lo + hi) >> 1; if (batch[mid] < g) lo = mid + 1; else hi = mid; }
    int start = lo;
    lo = start; hi = NN;
    while (lo < hi) { int mid = (lo + hi) >> 1; if (batch[mid] < g + 1) lo = mid + 1; else hi = mid; }
    int end = lo;

    if (c < D3) {
        float mv = 0.f;  // inputs are post-ReLU (>=0), so identity 0 is exact
        for (int n = start; n < end; n++)
            mv = fmaxf(mv, g_bufA[(size_t)n * D3 + c]);
        g_pool[g * D3 + c] = mv;
    }
}

// ----------------------------------------------------------------------------
// launch
// ----------------------------------------------------------------------------
extern "C" void kernel_launch(void* const* d_in, const int* in_sizes, int n_in,
                              void* d_out, int out_size)
{
    const float* x     = (const float*)d_in[0];
    const int*   ei    = (const int*)d_in[1];     // int32 (JAX x64 disabled)
    const int*   batch = (const int*)d_in[2];     // int32
    const float* W1 = (const float*)d_in[3];
    const float* as1 = (const float*)d_in[4];
    const float* ad1 = (const float*)d_in[5];
    const float* b1 = (const float*)d_in[6];
    const float* W2 = (const float*)d_in[7];
    const float* as2 = (const float*)d_in[8];
    const float* ad2 = (const float*)d_in[9];
    const float* b2 = (const float*)d_in[10];
    const float* W3 = (const float*)d_in[11];
    const float* as3 = (const float*)d_in[12];
    const float* ad3 = (const float*)d_in[13];
    const float* b3 = (const float*)d_in[14];
    const float* fc1_w = (const float*)d_in[15];
    const float* fc1_b = (const float*)d_in[16];
    const float* fc2_w = (const float*)d_in[17];
    const float* fc2_b = (const float*)d_in[18];
    float* outp = (float*)d_out;

    // --- CSR build (edges fixed across layers) ---
    zero_counts_kernel<<<(NN + 255) / 256, 256>>>();
    hist_kernel<<<(EE + 255) / 256, 256>>>(ei);
    scan_kernel<<<1, 1024>>>();
    csr_fill_kernel<<<(EE + 255) / 256, 256>>>(ei);

    dim3 blk(256);
    // --- layer 1: g_bufB = x @ W1 [N,312] ---
    {
        dim3 grid((312 + 127) / 128, (NN + 127) / 128);
        sgemm128<<<grid, blk>>>(x, 0, W1, nullptr, 2, NN, 312, 78, nullptr, 0);
        attn_scores<<<(NN * 32 + 127) / 128, 128>>>(as1, ad1, HEADS, D1);
        gat_agg<HEADS, D1, 3><<<NN, 128>>>(b1);
    }
    // --- layer 2: g_bufB = g_bufA @ W2 [N,1248] ---
    {
        dim3 grid((1248 + 127) / 128, (NN + 127) / 128);
        sgemm128<<<grid, blk>>>(nullptr, 1, W2, nullptr, 2, NN, 1248, 312, nullptr, 0);
        attn_scores<<<(NN * 32 + 127) / 128, 128>>>(as2, ad2, HEADS, D2);
        gat_agg<HEADS, D2, 10><<<NN, 128>>>(b2);
    }
    // --- layer 3: g_bufB = g_bufA @ W3 [N,1248], 1 head ---
    {
        dim3 grid((1248 + 127) / 128, (NN + 127) / 128);
        sgemm128<<<grid, blk>>>(nullptr, 1, W3, nullptr, 2, NN, 1248, 1248, nullptr, 0);
        attn_scores<<<(NN * 32 + 127) / 128, 128>>>(as3, ad3, 1, D3);
        gat_agg<1, D3, 10><<<NN, 128>>>(b3);
    }
    // --- pool + FC ---
    {
        dim3 pg(GG, (D3 + 127) / 128);
        pool_max<<<pg, 128>>>(batch);
        dim3 g1((HID + 127) / 128, (GG + 127) / 128);
        sgemm128<<<g1, blk>>>(nullptr, 3, fc1_w, nullptr, 4, GG, HID, D3, fc1_b, 1);
        dim3 g2((OUTD + 127) / 128, (GG + 127) / 128);
        sgemm128<<<g2, blk>>>(nullptr, 4, fc2_w, outp, 0, GG, OUTD, HID, fc2_b, 1);
    }
    (void)n_in; (void)in_sizes; (void)out_size;
}

// round 4
// speedup vs baseline: 1.2807x; 1.2807x over previous
#include <cuda_runtime.h>
#include <cuda_bf16.h>
#include <math.h>

// ----------------------------------------------------------------------------
// Problem constants (fixed by the reference)
// ----------------------------------------------------------------------------
#define NN     50000     // nodes
#define EE     200000    // directed edges (before self loops)
#define HEADS  4
#define GG     512
#define HID    1024
#define OUTD   128
#define D1     78        // conv1 per-head channels
#define D2     312       // conv2 per-head channels
#define D3     1248      // conv3 channels (1 head)
#define NEG    0.2f

// ----------------------------------------------------------------------------
// Scratch (device globals -> no allocations, referenced directly in kernels)
// ----------------------------------------------------------------------------
__device__ float g_bufA[(size_t)NN * D3];   // layer output ping
__device__ float g_bufB[(size_t)NN * D3];   // h = x @ W pong
__device__ float g_asrc[(size_t)NN * HEADS];
__device__ float g_adst[(size_t)NN * HEADS];
__device__ int   g_counts[NN];
__device__ int   g_cursor[NN];
__device__ int   g_ptr[NN + 1];
__device__ int   g_csrsrc[EE];
__device__ float g_pool[GG * D3];
__device__ float g_fc1[GG * HID];

__device__ __forceinline__ float lrelu(float x) { return x > 0.f ? x : NEG * x; }

// Operand selection on-device (no cudaGetSymbolAddress on host).
__device__ __forceinline__ const float* sel_cf(int sel, const float* ext) {
    switch (sel) {
        case 1: return g_bufA;
        case 2: return g_bufB;
        case 3: return g_pool;
        case 4: return g_fc1;
        default: return ext;
    }
}
__device__ __forceinline__ float* sel_f(int sel, float* ext) {
    switch (sel) {
        case 1: return g_bufA;
        case 2: return g_bufB;
        case 3: return g_pool;
        case 4: return g_fc1;
        default: return ext;
    }
}

// ----------------------------------------------------------------------------
// CSR construction (edge_index is int32)
// ----------------------------------------------------------------------------
__global__ void zero_counts_kernel() {
    int i = blockIdx.x * blockDim.x + threadIdx.x;
    if (i < NN) { g_counts[i] = 0; g_cursor[i] = 0; }
}

__global__ void hist_kernel(const int* __restrict__ ei) {
    int e = blockIdx.x * blockDim.x + threadIdx.x;
    if (e < EE) atomicAdd(&g_counts[ei[EE + e]], 1);
}

__global__ void scan_kernel() {
    __shared__ int sh[1024];
    __shared__ int s_off;
    int tid = threadIdx.x;
    if (tid == 0) { s_off = 0; g_ptr[0] = 0; }
    __syncthreads();
    for (int base = 0; base < NN; base += 1024) {
        int v = (base + tid < NN) ? g_counts[base + tid] : 0;
        sh[tid] = v;
        __syncthreads();
        for (int s = 1; s < 1024; s <<= 1) {
            int t = (tid >= s) ? sh[tid - s] : 0;
            __syncthreads();
            sh[tid] += t;
            __syncthreads();
        }
        int off = s_off;
        if (base + tid < NN) g_ptr[base + tid + 1] = off + sh[tid];
        __syncthreads();
        if (tid == 0) s_off = off + sh[1023];
        __syncthreads();
    }
}

__global__ void csr_fill_kernel(const int* __restrict__ ei) {
    int e = blockIdx.x * blockDim.x + threadIdx.x;
    if (e < EE) {
        int r = ei[e];
        int c = ei[EE + e];
        int pos = g_ptr[c] + atomicAdd(&g_cursor[c], 1);
        g_csrsrc[pos] = r;
    }
}

// ----------------------------------------------------------------------------
// Generic SGEMM (slow path, any K) — used only for layer-1 (K=78)
// ----------------------------------------------------------------------------
__global__ void __launch_bounds__(256)
sgemm128(const float* Aext, int Asel, const float* __restrict__ B,
         float* Cext, int Csel, int M, int N, int K,
         const float* __restrict__ bias, int fuse)
{
    const float* A = sel_cf(Asel, Aext);
    float* Cm = sel_f(Csel, Cext);

    __shared__ float As[8][128];
    __shared__ float Bs[8][132];

    int tid = threadIdx.x;
    int bm = blockIdx.y * 128, bn = blockIdx.x * 128;
    int tx = tid & 15, ty = tid >> 4;

    float acc[8][8];
#pragma unroll
    for (int i = 0; i < 8; i++)
#pragma unroll
        for (int j = 0; j < 8; j++) acc[i][j] = 0.f;

    for (int k0 = 0; k0 < K; k0 += 8) {
#pragma unroll
        for (int i = 0; i < 4; i++) {
            int flat = tid * 4 + i;
            int m = flat >> 3, kk = flat & 7;
            int gm = bm + m, gk = k0 + kk;
            float v = 0.f;
            if (gm < M && gk < K) v = A[(size_t)gm * K + gk];
            As[kk][m] = v;
        }
        {
            int kk = tid >> 5;
            int n4 = (tid & 31) * 4;
            int gk = k0 + kk, gn = bn + n4;
            float v0 = 0.f, v1 = 0.f, v2 = 0.f, v3 = 0.f;
            if (gk < K) {
                const float* brow = B + (size_t)gk * N;
                if (gn + 3 < N) {
                    v0 = brow[gn]; v1 = brow[gn + 1];
                    v2 = brow[gn + 2]; v3 = brow[gn + 3];
                } else {
                    if (gn + 0 < N) v0 = brow[gn + 0];
                    if (gn + 1 < N) v1 = brow[gn + 1];
                    if (gn + 2 < N) v2 = brow[gn + 2];
                    if (gn + 3 < N) v3 = brow[gn + 3];
                }
            }
            Bs[kk][n4 + 0] = v0; Bs[kk][n4 + 1] = v1;
            Bs[kk][n4 + 2] = v2; Bs[kk][n4 + 3] = v3;
        }
        __syncthreads();

#pragma unroll
        for (int kk = 0; kk < 8; kk++) {
            float a[8], b[8];
#pragma unroll
            for (int i = 0; i < 8; i++) a[i] = As[kk][ty * 8 + i];
#pragma unroll
            for (int j = 0; j < 8; j++) b[j] = Bs[kk][tx * 8 + j];
#pragma unroll
            for (int i = 0; i < 8; i++)
#pragma unroll
                for (int j = 0; j < 8; j++)
                    acc[i][j] = fmaf(a[i], b[j], acc[i][j]);
        }
        __syncthreads();
    }

#pragma unroll
    for (int i = 0; i < 8; i++) {
        int gm = bm + ty * 8 + i;
        if (gm >= M) continue;
#pragma unroll
        for (int j = 0; j < 8; j++) {
            int gn = bn + tx * 8 + j;
            if (gn >= N) continue;
            float v = acc[i][j];
            if (fuse) { v += bias[gn]; v = fmaxf(v, 0.f); }
            Cm[(size_t)gm * N + gn] = v;
        }
    }
}

// ----------------------------------------------------------------------------
// Fast SGEMM: double-buffered, float4 loads. Requires K % 8 == 0 && K % 4 == 0.
// 128x128 tile, BK=8, 256 threads, 8x8 microtile.
// ----------------------------------------------------------------------------
__global__ void __launch_bounds__(256)
sgemm_db(const float* Aext, int Asel, const float* __restrict__ B,
         float* Cext, int Csel, int M, int N, int K,
         const float* __restrict__ bias, int fuse)
{
    const float* A = sel_cf(Asel, Aext);
    float* Cm = sel_f(Csel, Cext);

    __shared__ float As[2][8][128];
    __shared__ float Bs[2][8][132];

    int tid = threadIdx.x;
    int bm = blockIdx.y * 128, bn = blockIdx.x * 128;
    int tx = tid & 15, ty = tid >> 4;

    // load mapping
    int arow = tid >> 1;          // 0..127 (m)
    int akc  = (tid & 1) * 4;     // k sub-chunk 0 or 4
    int brow = tid >> 5;          // 0..7 (k)
    int bcol = (tid & 31) * 4;    // 0..124 (n)

    int gmA = bm + arow;
    int gnB = bn + bcol;
    bool aok = (gmA < M);
    bool b4  = (gnB + 3 < N);

    float acc[8][8];
#pragma unroll
    for (int i = 0; i < 8; i++)
#pragma unroll
        for (int j = 0; j < 8; j++) acc[i][j] = 0.f;

    int steps = K >> 3;

    // prologue: stage 0
    {
        float4 av = make_float4(0.f, 0.f, 0.f, 0.f);
        if (aok) av = *(const float4*)&A[(size_t)gmA * K + akc];
        float4 bv = make_float4(0.f, 0.f, 0.f, 0.f);
        const float* brp = &B[(size_t)brow * N];
        if (b4) bv = *(const float4*)&brp[gnB];
        else {
            if (gnB + 0 < N) bv.x = brp[gnB + 0];
            if (gnB + 1 < N) bv.y = brp[gnB + 1];
            if (gnB + 2 < N) bv.z = brp[gnB + 2];
        }
        As[0][akc + 0][arow] = av.x;
        As[0][akc + 1][arow] = av.y;
        As[0][akc + 2][arow] = av.z;
        As[0][akc + 3][arow] = av.w;
        *(float4*)&Bs[0][brow][bcol] = bv;
    }
    __syncthreads();

    for (int s = 0; s < steps; s++) {
        int cur = s & 1, nxt = cur ^ 1;
        bool has = (s + 1 < steps);

        float4 av2 = make_float4(0.f, 0.f, 0.f, 0.f);
        float4 bv2 = make_float4(0.f, 0.f, 0.f, 0.f);
        if (has) {
            int k0 = (s + 1) << 3;
            if (aok) av2 = *(const float4*)&A[(size_t)gmA * K + k0 + akc];
            const float* brp = &B[(size_t)(k0 + brow) * N];
            if (b4) bv2 = *(const float4*)&brp[gnB];
            else {
                if (gnB + 0 < N) bv2.x = brp[gnB + 0];
                if (gnB + 1 < N) bv2.y = brp[gnB + 1];
                if (gnB + 2 < N) bv2.z = brp[gnB + 2];
            }
        }

#pragma unroll
        for (int kk = 0; kk < 8; kk++) {
            float a[8], b[8];
            *(float4*)&a[0] = *(const float4*)&As[cur][kk][ty * 8];
            *(float4*)&a[4] = *(const float4*)&As[cur][kk][ty * 8 + 4];
            *(float4*)&b[0] = *(const float4*)&Bs[cur][kk][tx * 8];
            *(float4*)&b[4] = *(const float4*)&Bs[cur][kk][tx * 8 + 4];
#pragma unroll
            for (int i = 0; i < 8; i++)
#pragma unroll
                for (int j = 0; j < 8; j++)
                    acc[i][j] = fmaf(a[i], b[j], acc[i][j]);
        }

        if (has) {
            As[nxt][akc + 0][arow] = av2.x;
            As[nxt][akc + 1][arow] = av2.y;
            As[nxt][akc + 2][arow] = av2.z;
            As[nxt][akc + 3][arow] = av2.w;
            *(float4*)&Bs[nxt][brow][bcol] = bv2;
        }
        __syncthreads();
    }

    // epilogue
#pragma unroll
    for (int i = 0; i < 8; i++) {
        int gm = bm + ty * 8 + i;
        if (gm >= M) continue;
        float* crow = &Cm[(size_t)gm * N];
#pragma unroll
        for (int j4 = 0; j4 < 2; j4++) {
            int gn = bn + tx * 8 + j4 * 4;
            float4 v;
            v.x = acc[i][j4 * 4 + 0];
            v.y = acc[i][j4 * 4 + 1];
            v.z = acc[i][j4 * 4 + 2];
            v.w = acc[i][j4 * 4 + 3];
            if (fuse) {
                v.x = fmaxf(v.x + bias[gn + 0], 0.f);
                v.y = fmaxf(v.y + bias[gn + 1], 0.f);
                v.z = fmaxf(v.z + bias[gn + 2], 0.f);
                v.w = fmaxf(v.w + bias[gn + 3], 0.f);
            }
            if (gn + 3 < N) {
                *(float4*)&crow[gn] = v;
            } else {
                if (gn + 0 < N) crow[gn + 0] = v.x;
                if (gn + 1 < N) crow[gn + 1] = v.y;
                if (gn + 2 < N) crow[gn + 2] = v.z;
            }
        }
    }
}

// ----------------------------------------------------------------------------
// Per-node attention scores from g_bufB: one warp per node
// ----------------------------------------------------------------------------
__global__ void attn_scores(const float* __restrict__ att_s,
                            const float* __restrict__ att_d,
                            int H, int C)
{
    int warp = (blockIdx.x * blockDim.x + threadIdx.x) >> 5;
    int lane = threadIdx.x & 31;
    if (warp >= NN) return;
    for (int h = 0; h < H; h++) {
        const float* hr = g_bufB + (size_t)warp * H * C + (size_t)h * C;
        float ss = 0.f, sd = 0.f;
        for (int c = lane; c < C; c += 32) {
            float hv = hr[c];
            ss = fmaf(hv, att_s[h * C + c], ss);
            sd = fmaf(hv, att_d[h * C + c], sd);
        }
#pragma unroll
        for (int o = 16; o; o >>= 1) {
            ss += __shfl_down_sync(0xFFFFFFFFu, ss, o);
            sd += __shfl_down_sync(0xFFFFFFFFu, sd, o);
        }
        if (lane == 0) {
            g_asrc[warp * H + h] = ss;
            g_adst[warp * H + h] = sd;
        }
    }
}

// ----------------------------------------------------------------------------
// GAT aggregation (softmax over incoming edges + self loop) -> g_bufA
// ----------------------------------------------------------------------------
template<int H, int C, int NCH>
__global__ void __launch_bounds__(128)
gat_agg(const float* __restrict__ bias)
{
    constexpr int HC = H * C;
    constexpr int CHUNK = 64;
    int i = blockIdx.x;
    int tid = threadIdx.x;

    __shared__ float s_alpha[CHUNK][H];
    __shared__ int   s_src[CHUNK];

    const float* hbuf = g_bufB;
    float* out = g_bufA;

    float adsti[H], m[H], den[H], eself[H], aself[H];
#pragma unroll
    for (int h = 0; h < H; h++) adsti[h] = g_adst[i * H + h];
#pragma unroll
    for (int h = 0; h < H; h++) {
        eself[h] = lrelu(g_asrc[i * H + h] + adsti[h]);
        m[h] = eself[h];
    }

    int beg = g_ptr[i];
    int deg = g_ptr[i + 1] - beg;

    for (int j = 0; j < deg; j++) {
        int s = g_csrsrc[beg + j];
#pragma unroll
        for (int h = 0; h < H; h++) {
            float e = lrelu(g_asrc[s * H + h] + adsti[h]);
            m[h] = fmaxf(m[h], e);
        }
    }
#pragma unroll
    for (int h = 0; h < H; h++) den[h] = __expf(eself[h] - m[h]);
    for (int j = 0; j < deg; j++) {
        int s = g_csrsrc[beg + j];
#pragma unroll
        for (int h = 0; h < H; h++) {
            float e = lrelu(g_asrc[s * H + h] + adsti[h]);
            den[h] += __expf(e - m[h]);
        }
    }
#pragma unroll
    for (int h = 0; h < H; h++)
        aself[h] = __expf(eself[h] - m[h]) / (den[h] + 1e-16f);

    float acc[NCH];
    int   hidx[NCH];
#pragma unroll
    for (int t = 0; t < NCH; t++) {
        int c = tid + t * 128;
        hidx[t] = c / C;
        acc[t] = (c < HC) ? aself[hidx[t]] * hbuf[(size_t)i * HC + c] : 0.f;
    }

    for (int cb = 0; cb < deg; cb += CHUNK) {
        int cn = min(CHUNK, deg - cb);
        __syncthreads();
        if (tid < cn) {
            int s = g_csrsrc[beg + cb + tid];
            s_src[tid] = s;
#pragma unroll
            for (int h = 0; h < H; h++) {
                float e = lrelu(g_asrc[s * H + h] + adsti[h]);
                s_alpha[tid][h] = __expf(e - m[h]) / (den[h] + 1e-16f);
            }
        }
        __syncthreads();
        for (int j = 0; j < cn; j++) {
            const float* hr = hbuf + (size_t)s_src[j] * HC;
            float al[H];
#pragma unroll
            for (int h = 0; h < H; h++) al[h] = s_alpha[j][h];
#pragma unroll
            for (int t = 0; t < NCH; t++) {
                int c = tid + t * 128;
                if (c < HC) acc[t] = fmaf(al[hidx[t]], hr[c], acc[t]);
            }
        }
    }

#pragma unroll
    for (int t = 0; t < NCH; t++) {
        int c = tid + t * 128;
        if (c < HC) {
            float v = acc[t] + bias[c];
            out[(size_t)i * HC + c] = fmaxf(v, 0.f);
        }
    }
}

// ----------------------------------------------------------------------------
// Global max pool over sorted batch (int32): g_bufA -> g_pool
// ----------------------------------------------------------------------------
__global__ void pool_max(const int* __restrict__ batch)
{
    int g = blockIdx.x;
    int c = blockIdx.y * 128 + threadIdx.x;

    int lo = 0, hi = NN;
    while (lo < hi) { int mid = (lo + hi) >> 1; if (batch[mid] < g) lo = mid + 1; else hi = mid; }
    int start = lo;
    lo = start; hi = NN;
    while (lo < hi) { int mid = (lo + hi) >> 1; if (batch[mid] < g + 1) lo = mid + 1; else hi = mid; }
    int end = lo;

    if (c < D3) {
        float mv = 0.f;
        for (int n = start; n < end; n++)
            mv = fmaxf(mv, g_bufA[(size_t)n * D3 + c]);
        g_pool[g * D3 + c] = mv;
    }
}

// ----------------------------------------------------------------------------
// launch
// ----------------------------------------------------------------------------
extern "C" void kernel_launch(void* const* d_in, const int* in_sizes, int n_in,
                              void* d_out, int out_size)
{
    const float* x     = (const float*)d_in[0];
    const int*   ei    = (const int*)d_in[1];
    const int*   batch = (const int*)d_in[2];
    const float* W1 = (const float*)d_in[3];
    const float* as1 = (const float*)d_in[4];
    const float* ad1 = (const float*)d_in[5];
    const float* b1 = (const float*)d_in[6];
    const float* W2 = (const float*)d_in[7];
    const float* as2 = (const float*)d_in[8];
    const float* ad2 = (const float*)d_in[9];
    const float* b2 = (const float*)d_in[10];
    const float* W3 = (const float*)d_in[11];
    const float* as3 = (const float*)d_in[12];
    const float* ad3 = (const float*)d_in[13];
    const float* b3 = (const float*)d_in[14];
    const float* fc1_w = (const float*)d_in[15];
    const float* fc1_b = (const float*)d_in[16];
    const float* fc2_w = (const float*)d_in[17];
    const float* fc2_b = (const float*)d_in[18];
    float* outp = (float*)d_out;

    // --- CSR build ---
    zero_counts_kernel<<<(NN + 255) / 256, 256>>>();
    hist_kernel<<<(EE + 255) / 256, 256>>>(ei);
    scan_kernel<<<1, 1024>>>();
    csr_fill_kernel<<<(EE + 255) / 256, 256>>>(ei);

    dim3 blk(256);
    // --- layer 1: g_bufB = x @ W1 [N,312]  (K=78 -> generic kernel) ---
    {
        dim3 grid((312 + 127) / 128, (NN + 127) / 128);
        sgemm128<<<grid, blk>>>(x, 0, W1, nullptr, 2, NN, 312, 78, nullptr, 0);
        attn_scores<<<(NN * 32 + 127) / 128, 128>>>(as1, ad1, HEADS, D1);
        gat_agg<HEADS, D1, 3><<<NN, 128>>>(b1);
    }
    // --- layer 2: g_bufB = g_bufA @ W2 [N,1248]  (K=312) ---
    {
        dim3 grid((1248 + 127) / 128, (NN + 127) / 128);
        sgemm_db<<<grid, blk>>>(nullptr, 1, W2, nullptr, 2, NN, 1248, 312, nullptr, 0);
        attn_scores<<<(NN * 32 + 127) / 128, 128>>>(as2, ad2, HEADS, D2);
        gat_agg<HEADS, D2, 10><<<NN, 128>>>(b2);
    }
    // --- layer 3: g_bufB = g_bufA @ W3 [N,1248]  (K=1248) ---
    {
        dim3 grid((1248 + 127) / 128, (NN + 127) / 128);
        sgemm_db<<<grid, blk>>>(nullptr, 1, W3, nullptr, 2, NN, 1248, 1248, nullptr, 0);
        attn_scores<<<(NN * 32 + 127) / 128, 128>>>(as3, ad3, 1, D3);
        gat_agg<1, D3, 10><<<NN, 128>>>(b3);
    }
    // --- pool + FC ---
    {
        dim3 pg(GG, (D3 + 127) / 128);
        pool_max<<<pg, 128>>>(batch);
        dim3 g1((HID + 127) / 128, (GG + 127) / 128);
        sgemm_db<<<g1, blk>>>(nullptr, 3, fc1_w, nullptr, 4, GG, HID, D3, fc1_b, 1);
        dim3 g2((OUTD + 127) / 128, (GG + 127) / 128);
        sgemm_db<<<g2, blk>>>(nullptr, 4, fc2_w, outp, 0, GG, OUTD, HID, fc2_b, 1);
    }
    (void)n_in; (void)in_sizes; (void)out_size;
}

// round 5
// speedup vs baseline: 2.1080x; 1.6459x over previous
#include <cuda_runtime.h>
#include <cuda_bf16.h>
#include <math.h>
#include <stdint.h>

// ----------------------------------------------------------------------------
// Problem constants
// ----------------------------------------------------------------------------
#define NN     50000
#define EE     200000
#define HEADS  4
#define GG     512
#define HID    1024
#define OUTD   128
#define D1     78
#define D2     312
#define D3     1248
#define NEG    0.2f

// ----------------------------------------------------------------------------
// Scratch (device globals)
// ----------------------------------------------------------------------------
__device__ float g_bufA[(size_t)NN * D3];
__device__ float g_bufB[(size_t)NN * D3];
__device__ float g_asrc[(size_t)NN * HEADS];
__device__ float g_adst[(size_t)NN * HEADS];
__device__ int   g_counts[NN];
__device__ int   g_cursor[NN];
__device__ int   g_ptr[NN + 1];
__device__ int   g_csrsrc[EE];
__device__ float g_pool[GG * D3];
__device__ float g_fc1[GG * HID];

__device__ __forceinline__ float lrelu(float x) { return x > 0.f ? x : NEG * x; }

__device__ __forceinline__ const float* sel_cf(int sel, const float* ext) {
    switch (sel) {
        case 1: return g_bufA;
        case 2: return g_bufB;
        case 3: return g_pool;
        case 4: return g_fc1;
        default: return ext;
    }
}
__device__ __forceinline__ float* sel_f(int sel, float* ext) {
    switch (sel) {
        case 1: return g_bufA;
        case 2: return g_bufB;
        case 3: return g_pool;
        case 4: return g_fc1;
        default: return ext;
    }
}

__device__ __forceinline__ uint32_t f2tf(float f) {
    uint32_t r;
    asm("cvt.rna.tf32.f32 %0, %1;" : "=r"(r) : "f"(f));
    return r;
}

// ----------------------------------------------------------------------------
// CSR construction (edge_index is int32)
// ----------------------------------------------------------------------------
__global__ void zero_counts_kernel() {
    int i = blockIdx.x * blockDim.x + threadIdx.x;
    if (i < NN) { g_counts[i] = 0; g_cursor[i] = 0; }
}

__global__ void hist_kernel(const int* __restrict__ ei) {
    int e = blockIdx.x * blockDim.x + threadIdx.x;
    if (e < EE) atomicAdd(&g_counts[ei[EE + e]], 1);
}

__global__ void scan_kernel() {
    __shared__ int sh[1024];
    __shared__ int s_off;
    int tid = threadIdx.x;
    if (tid == 0) { s_off = 0; g_ptr[0] = 0; }
    __syncthreads();
    for (int base = 0; base < NN; base += 1024) {
        int v = (base + tid < NN) ? g_counts[base + tid] : 0;
        sh[tid] = v;
        __syncthreads();
        for (int s = 1; s < 1024; s <<= 1) {
            int t = (tid >= s) ? sh[tid - s] : 0;
            __syncthreads();
            sh[tid] += t;
            __syncthreads();
        }
        int off = s_off;
        if (base + tid < NN) g_ptr[base + tid + 1] = off + sh[tid];
        __syncthreads();
        if (tid == 0) s_off = off + sh[1023];
        __syncthreads();
    }
}

__global__ void csr_fill_kernel(const int* __restrict__ ei) {
    int e = blockIdx.x * blockDim.x + threadIdx.x;
    if (e < EE) {
        int r = ei[e];
        int c = ei[EE + e];
        int pos = g_ptr[c] + atomicAdd(&g_cursor[c], 1);
        g_csrsrc[pos] = r;
    }
}

// ----------------------------------------------------------------------------
// Generic SGEMM (any K) — layer-1 only (K=78)
// ----------------------------------------------------------------------------
__global__ void __launch_bounds__(256)
sgemm128(const float* Aext, int Asel, const float* __restrict__ B,
         float* Cext, int Csel, int M, int N, int K,
         const float* __restrict__ bias, int fuse)
{
    const float* A = sel_cf(Asel, Aext);
    float* Cm = sel_f(Csel, Cext);

    __shared__ float As[8][128];
    __shared__ float Bs[8][132];

    int tid = threadIdx.x;
    int bm = blockIdx.y * 128, bn = blockIdx.x * 128;
    int tx = tid & 15, ty = tid >> 4;

    float acc[8][8];
#pragma unroll
    for (int i = 0; i < 8; i++)
#pragma unroll
        for (int j = 0; j < 8; j++) acc[i][j] = 0.f;

    for (int k0 = 0; k0 < K; k0 += 8) {
#pragma unroll
        for (int i = 0; i < 4; i++) {
            int flat = tid * 4 + i;
            int m = flat >> 3, kk = flat & 7;
            int gm = bm + m, gk = k0 + kk;
            float v = 0.f;
            if (gm < M && gk < K) v = A[(size_t)gm * K + gk];
            As[kk][m] = v;
        }
        {
            int kk = tid >> 5;
            int n4 = (tid & 31) * 4;
            int gk = k0 + kk, gn = bn + n4;
            float v0 = 0.f, v1 = 0.f, v2 = 0.f, v3 = 0.f;
            if (gk < K) {
                const float* brow = B + (size_t)gk * N;
                if (gn + 3 < N) {
                    v0 = brow[gn]; v1 = brow[gn + 1];
                    v2 = brow[gn + 2]; v3 = brow[gn + 3];
                } else {
                    if (gn + 0 < N) v0 = brow[gn + 0];
                    if (gn + 1 < N) v1 = brow[gn + 1];
                    if (gn + 2 < N) v2 = brow[gn + 2];
                    if (gn + 3 < N) v3 = brow[gn + 3];
                }
            }
            Bs[kk][n4 + 0] = v0; Bs[kk][n4 + 1] = v1;
            Bs[kk][n4 + 2] = v2; Bs[kk][n4 + 3] = v3;
        }
        __syncthreads();

#pragma unroll
        for (int kk = 0; kk < 8; kk++) {
            float a[8], b[8];
#pragma unroll
            for (int i = 0; i < 8; i++) a[i] = As[kk][ty * 8 + i];
#pragma unroll
            for (int j = 0; j < 8; j++) b[j] = Bs[kk][tx * 8 + j];
#pragma unroll
            for (int i = 0; i < 8; i++)
#pragma unroll
                for (int j = 0; j < 8; j++)
                    acc[i][j] = fmaf(a[i], b[j], acc[i][j]);
        }
        __syncthreads();
    }

#pragma unroll
    for (int i = 0; i < 8; i++) {
        int gm = bm + ty * 8 + i;
        if (gm >= M) continue;
#pragma unroll
        for (int j = 0; j < 8; j++) {
            int gn = bn + tx * 8 + j;
            if (gn >= N) continue;
            float v = acc[i][j];
            if (fuse) { v += bias[gn]; v = fmaxf(v, 0.f); }
            Cm[(size_t)gm * N + gn] = v;
        }
    }
}

// ----------------------------------------------------------------------------
// Fast fp32 SGEMM (double-buffered) — FC layers (K % 8 == 0)
// ----------------------------------------------------------------------------
__global__ void __launch_bounds__(256)
sgemm_db(const float* Aext, int Asel, const float* __restrict__ B,
         float* Cext, int Csel, int M, int N, int K,
         const float* __restrict__ bias, int fuse)
{
    const float* A = sel_cf(Asel, Aext);
    float* Cm = sel_f(Csel, Cext);

    __shared__ float As[2][8][128];
    __shared__ float Bs[2][8][132];

    int tid = threadIdx.x;
    int bm = blockIdx.y * 128, bn = blockIdx.x * 128;
    int tx = tid & 15, ty = tid >> 4;

    int arow = tid >> 1;
    int akc  = (tid & 1) * 4;
    int brow = tid >> 5;
    int bcol = (tid & 31) * 4;

    int gmA = bm + arow;
    int gnB = bn + bcol;
    bool aok = (gmA < M);
    bool b4  = (gnB + 3 < N);

    float acc[8][8];
#pragma unroll
    for (int i = 0; i < 8; i++)
#pragma unroll
        for (int j = 0; j < 8; j++) acc[i][j] = 0.f;

    int steps = K >> 3;

    {
        float4 av = make_float4(0.f, 0.f, 0.f, 0.f);
        if (aok) av = *(const float4*)&A[(size_t)gmA * K + akc];
        float4 bv = make_float4(0.f, 0.f, 0.f, 0.f);
        const float* brp = &B[(size_t)brow * N];
        if (b4) bv = *(const float4*)&brp[gnB];
        else {
            if (gnB + 0 < N) bv.x = brp[gnB + 0];
            if (gnB + 1 < N) bv.y = brp[gnB + 1];
            if (gnB + 2 < N) bv.z = brp[gnB + 2];
        }
        As[0][akc + 0][arow] = av.x;
        As[0][akc + 1][arow] = av.y;
        As[0][akc + 2][arow] = av.z;
        As[0][akc + 3][arow] = av.w;
        *(float4*)&Bs[0][brow][bcol] = bv;
    }
    __syncthreads();

    for (int s = 0; s < steps; s++) {
        int cur = s & 1, nxt = cur ^ 1;
        bool has = (s + 1 < steps);

        float4 av2 = make_float4(0.f, 0.f, 0.f, 0.f);
        float4 bv2 = make_float4(0.f, 0.f, 0.f, 0.f);
        if (has) {
            int k0 = (s + 1) << 3;
            if (aok) av2 = *(const float4*)&A[(size_t)gmA * K + k0 + akc];
            const float* brp = &B[(size_t)(k0 + brow) * N];
            if (b4) bv2 = *(const float4*)&brp[gnB];
            else {
                if (gnB + 0 < N) bv2.x = brp[gnB + 0];
                if (gnB + 1 < N) bv2.y = brp[gnB + 1];
                if (gnB + 2 < N) bv2.z = brp[gnB + 2];
            }
        }

#pragma unroll
        for (int kk = 0; kk < 8; kk++) {
            float a[8], b[8];
            *(float4*)&a[0] = *(const float4*)&As[cur][kk][ty * 8];
            *(float4*)&a[4] = *(const float4*)&As[cur][kk][ty * 8 + 4];
            *(float4*)&b[0] = *(const float4*)&Bs[cur][kk][tx * 8];
            *(float4*)&b[4] = *(const float4*)&Bs[cur][kk][tx * 8 + 4];
#pragma unroll
            for (int i = 0; i < 8; i++)
#pragma unroll
                for (int j = 0; j < 8; j++)
                    acc[i][j] = fmaf(a[i], b[j], acc[i][j]);
        }

        if (has) {
            As[nxt][akc + 0][arow] = av2.x;
            As[nxt][akc + 1][arow] = av2.y;
            As[nxt][akc + 2][arow] = av2.z;
            As[nxt][akc + 3][arow] = av2.w;
            *(float4*)&Bs[nxt][brow][bcol] = bv2;
        }
        __syncthreads();
    }

#pragma unroll
    for (int i = 0; i < 8; i++) {
        int gm = bm + ty * 8 + i;
        if (gm >= M) continue;
        float* crow = &Cm[(size_t)gm * N];
#pragma unroll
        for (int j4 = 0; j4 < 2; j4++) {
            int gn = bn + tx * 8 + j4 * 4;
            float4 v;
            v.x = acc[i][j4 * 4 + 0];
            v.y = acc[i][j4 * 4 + 1];
            v.z = acc[i][j4 * 4 + 2];
            v.w = acc[i][j4 * 4 + 3];
            if (fuse) {
                v.x = fmaxf(v.x + bias[gn + 0], 0.f);
                v.y = fmaxf(v.y + bias[gn + 1], 0.f);
                v.z = fmaxf(v.z + bias[gn + 2], 0.f);
                v.w = fmaxf(v.w + bias[gn + 3], 0.f);
            }
            if (gn + 3 < N) {
                *(float4*)&crow[gn] = v;
            } else {
                if (gn + 0 < N) crow[gn + 0] = v.x;
                if (gn + 1 < N) crow[gn + 1] = v.y;
                if (gn + 2 < N) crow[gn + 2] = v.z;
            }
        }
    }
}

// ----------------------------------------------------------------------------
// TF32 tensor-core GEMM: C = A @ B, fp32 accum.
// 128x128 block tile, BK=16, 256 threads (8 warps: 4m x 2n), warp tile 32x64.
// mma.sync.aligned.m16n8k8.row.col.f32.tf32.tf32.f32
// Requires K%4==0, N%4==0 (guards handle ragged M/N tiles, K tail zero-filled).
// ----------------------------------------------------------------------------
__device__ __forceinline__ void mma_tf32(float c[4], const uint32_t a[4],
                                         uint32_t b0, uint32_t b1)
{
    asm volatile(
        "mma.sync.aligned.m16n8k8.row.col.f32.tf32.tf32.f32 "
        "{%0,%1,%2,%3}, {%4,%5,%6,%7}, {%8,%9}, {%0,%1,%2,%3};"
        : "+f"(c[0]), "+f"(c[1]), "+f"(c[2]), "+f"(c[3])
        : "r"(a[0]), "r"(a[1]), "r"(a[2]), "r"(a[3]), "r"(b0), "r"(b1));
}

__global__ void __launch_bounds__(256)
tgemm_tf32(const float* Aext, int Asel, const float* __restrict__ B,
           float* Cext, int Csel, int M, int N, int K)
{
    const float* A = sel_cf(Asel, Aext);
    float* Cm = sel_f(Csel, Cext);

    __shared__ uint32_t As[2][16][136];   // [k][m], pad->conflict-free frags
    __shared__ uint32_t Bs[2][16][136];   // [k][n]

    int tid = threadIdx.x;
    int warpid = tid >> 5, lane = tid & 31;
    int bm = blockIdx.y * 128, bn = blockIdx.x * 128;
    int wm = (warpid >> 1) * 32;          // warp m offset (4 warps)
    int wn = (warpid & 1) * 64;           // warp n offset (2 warps)
    int grp = lane >> 2, tig = lane & 3;

    // loader mapping
    int arow = tid >> 1;                  // m 0..127
    int akc  = (tid & 1) * 8;             // k base {0,8}, covers 8 k each
    int brow = tid & 7;                   // k 0..7 (and +8)
    int bcol = (tid >> 3) * 4;            // n 0..124

    int gmA = bm + arow;
    int gnB = bn + bcol;
    bool aok = (gmA < M);
    bool bn4 = (gnB + 3 < N);

    float cacc[2][8][4];
#pragma unroll
    for (int mf = 0; mf < 2; mf++)
#pragma unroll
        for (int nf = 0; nf < 8; nf++)
#pragma unroll
            for (int q = 0; q < 4; q++) cacc[mf][nf][q] = 0.f;

    int steps = (K + 15) >> 4;

    // ---- stage loaders (global -> regs) ----
    float4 avr[2], bvr[2];
    auto ldA = [&](int k0) {
#pragma unroll
        for (int q = 0; q < 2; q++) {
            int gk = k0 + akc + q * 4;
            float4 v = make_float4(0.f, 0.f, 0.f, 0.f);
            if (aok && gk < K) {
                if (gk + 3 < K) v = *(const float4*)&A[(size_t)gmA * K + gk];
                else {
                    float* pv = (float*)&v;
                    for (int z = 0; z < 4; z++)
                        if (gk + z < K) pv[z] = A[(size_t)gmA * K + gk + z];
                }
            }
            avr[q] = v;
        }
    };
    auto ldB = [&](int k0) {
#pragma unroll
        for (int q = 0; q < 2; q++) {
            int gk = k0 + brow + q * 8;
            float4 v = make_float4(0.f, 0.f, 0.f, 0.f);
            if (gk < K) {
                const float* bp = &B[(size_t)gk * N];
                if (bn4) v = *(const float4*)&bp[gnB];
                else {
                    if (gnB + 0 < N) v.x = bp[gnB + 0];
                    if (gnB + 1 < N) v.y = bp[gnB + 1];
                    if (gnB + 2 < N) v.z = bp[gnB + 2];
                }
            }
            bvr[q] = v;
        }
    };
    auto stStage = [&](int st) {
#pragma unroll
        for (int q = 0; q < 2; q++) {
            int kk = akc + q * 4;
            As[st][kk + 0][arow] = f2tf(avr[q].x);
            As[st][kk + 1][arow] = f2tf(avr[q].y);
            As[st][kk + 2][arow] = f2tf(avr[q].z);
            As[st][kk + 3][arow] = f2tf(avr[q].w);
        }
#pragma unroll
        for (int q = 0; q < 2; q++) {
            int kk = brow + q * 8;
            uint4 u;
            u.x = f2tf(bvr[q].x); u.y = f2tf(bvr[q].y);
            u.z = f2tf(bvr[q].z); u.w = f2tf(bvr[q].w);
            *(uint4*)&Bs[st][kk][bcol] = u;
        }
    };

    // prologue
    ldA(0); ldB(0);
    stStage(0);
    __syncthreads();

    for (int s = 0; s < steps; s++) {
        int cur = s & 1;
        bool has = (s + 1 < steps);
        if (has) { int k0 = (s + 1) << 4; ldA(k0); ldB(k0); }

#pragma unroll
        for (int kf = 0; kf < 2; kf++) {
            int kb = kf * 8;
            uint32_t af[2][4];
#pragma unroll
            for (int mf = 0; mf < 2; mf++) {
                int m0 = wm + mf * 16;
                af[mf][0] = As[cur][kb + tig    ][m0 + grp    ];
                af[mf][1] = As[cur][kb + tig    ][m0 + grp + 8];
                af[mf][2] = As[cur][kb + tig + 4][m0 + grp    ];
                af[mf][3] = As[cur][kb + tig + 4][m0 + grp + 8];
            }
#pragma unroll
            for (int nf = 0; nf < 8; nf++) {
                int n0 = wn + nf * 8 + grp;
                uint32_t b0 = Bs[cur][kb + tig    ][n0];
                uint32_t b1 = Bs[cur][kb + tig + 4][n0];
                mma_tf32(cacc[0][nf], af[0], b0, b1);
                mma_tf32(cacc[1][nf], af[1], b0, b1);
            }
        }

        if (has) stStage(cur ^ 1);
        __syncthreads();
    }

    // epilogue
#pragma unroll
    for (int mf = 0; mf < 2; mf++) {
#pragma unroll
        for (int nf = 0; nf < 8; nf++) {
            int r0 = bm + wm + mf * 16 + grp;
            int c0 = bn + wn + nf * 8 + tig * 2;
            const float* c = cacc[mf][nf];
            if (r0 < M) {
                if (c0 + 1 < N) *(float2*)&Cm[(size_t)r0 * N + c0] = make_float2(c[0], c[1]);
                else if (c0 < N) Cm[(size_t)r0 * N + c0] = c[0];
            }
            if (r0 + 8 < M) {
                if (c0 + 1 < N) *(float2*)&Cm[(size_t)(r0 + 8) * N + c0] = make_float2(c[2], c[3]);
                else if (c0 < N) Cm[(size_t)(r0 + 8) * N + c0] = c[2];
            }
        }
    }
}

// ----------------------------------------------------------------------------
// Per-node attention scores from g_bufB: one warp per node
// ----------------------------------------------------------------------------
__global__ void attn_scores(const float* __restrict__ att_s,
                            const float* __restrict__ att_d,
                            int H, int C)
{
    int warp = (blockIdx.x * blockDim.x + threadIdx.x) >> 5;
    int lane = threadIdx.x & 31;
    if (warp >= NN) return;
    for (int h = 0; h < H; h++) {
        const float* hr = g_bufB + (size_t)warp * H * C + (size_t)h * C;
        float ss = 0.f, sd = 0.f;
        for (int c = lane; c < C; c += 32) {
            float hv = hr[c];
            ss = fmaf(hv, att_s[h * C + c], ss);
            sd = fmaf(hv, att_d[h * C + c], sd);
        }
#pragma unroll
        for (int o = 16; o; o >>= 1) {
            ss += __shfl_down_sync(0xFFFFFFFFu, ss, o);
            sd += __shfl_down_sync(0xFFFFFFFFu, sd, o);
        }
        if (lane == 0) {
            g_asrc[warp * H + h] = ss;
            g_adst[warp * H + h] = sd;
        }
    }
}

// ----------------------------------------------------------------------------
// GAT aggregation (softmax over incoming edges + self loop) -> g_bufA
// ----------------------------------------------------------------------------
template<int H, int C, int NCH>
__global__ void __launch_bounds__(128)
gat_agg(const float* __restrict__ bias)
{
    constexpr int HC = H * C;
    constexpr int CHUNK = 64;
    int i = blockIdx.x;
    int tid = threadIdx.x;

    __shared__ float s_alpha[CHUNK][H];
    __shared__ int   s_src[CHUNK];

    const float* hbuf = g_bufB;
    float* out = g_bufA;

    float adsti[H], m[H], den[H], eself[H], aself[H];
#pragma unroll
    for (int h = 0; h < H; h++) adsti[h] = g_adst[i * H + h];
#pragma unroll
    for (int h = 0; h < H; h++) {
        eself[h] = lrelu(g_asrc[i * H + h] + adsti[h]);
        m[h] = eself[h];
    }

    int beg = g_ptr[i];
    int deg = g_ptr[i + 1] - beg;

    for (int j = 0; j < deg; j++) {
        int s = g_csrsrc[beg + j];
#pragma unroll
        for (int h = 0; h < H; h++) {
            float e = lrelu(g_asrc[s * H + h] + adsti[h]);
            m[h] = fmaxf(m[h], e);
        }
    }
#pragma unroll
    for (int h = 0; h < H; h++) den[h] = __expf(eself[h] - m[h]);
    for (int j = 0; j < deg; j++) {
        int s = g_csrsrc[beg + j];
#pragma unroll
        for (int h = 0; h < H; h++) {
            float e = lrelu(g_asrc[s * H + h] + adsti[h]);
            den[h] += __expf(e - m[h]);
        }
    }
#pragma unroll
    for (int h = 0; h < H; h++)
        aself[h] = __expf(eself[h] - m[h]) / (den[h] + 1e-16f);

    float acc[NCH];
    int   hidx[NCH];
#pragma unroll
    for (int t = 0; t < NCH; t++) {
        int c = tid + t * 128;
        hidx[t] = c / C;
        acc[t] = (c < HC) ? aself[hidx[t]] * hbuf[(size_t)i * HC + c] : 0.f;
    }

    for (int cb = 0; cb < deg; cb += CHUNK) {
        int cn = min(CHUNK, deg - cb);
        __syncthreads();
        if (tid < cn) {
            int s = g_csrsrc[beg + cb + tid];
            s_src[tid] = s;
#pragma unroll
            for (int h = 0; h < H; h++) {
                float e = lrelu(g_asrc[s * H + h] + adsti[h]);
                s_alpha[tid][h] = __expf(e - m[h]) / (den[h] + 1e-16f);
            }
        }
        __syncthreads();
        for (int j = 0; j < cn; j++) {
            const float* hr = hbuf + (size_t)s_src[j] * HC;
            float al[H];
#pragma unroll
            for (int h = 0; h < H; h++) al[h] = s_alpha[j][h];
#pragma unroll
            for (int t = 0; t < NCH; t++) {
                int c = tid + t * 128;
                if (c < HC) acc[t] = fmaf(al[hidx[t]], hr[c], acc[t]);
            }
        }
    }

#pragma unroll
    for (int t = 0; t < NCH; t++) {
        int c = tid + t * 128;
        if (c < HC) {
            float v = acc[t] + bias[c];
            out[(size_t)i * HC + c] = fmaxf(v, 0.f);
        }
    }
}

// ----------------------------------------------------------------------------
// Global max pool over sorted batch (int32): g_bufA -> g_pool
// ----------------------------------------------------------------------------
__global__ void pool_max(const int* __restrict__ batch)
{
    int g = blockIdx.x;
    int c = blockIdx.y * 128 + threadIdx.x;

    int lo = 0, hi = NN;
    while (lo < hi) { int mid = (lo + hi) >> 1; if (batch[mid] < g) lo = mid + 1; else hi = mid; }
    int start = lo;
    lo = start; hi = NN;
    while (lo < hi) { int mid = (lo + hi) >> 1; if (batch[mid] < g + 1) lo = mid + 1; else hi = mid; }
    int end = lo;

    if (c < D3) {
        float mv = 0.f;
        for (int n = start; n < end; n++)
            mv = fmaxf(mv, g_bufA[(size_t)n * D3 + c]);
        g_pool[g * D3 + c] = mv;
    }
}

// ----------------------------------------------------------------------------
// launch
// ----------------------------------------------------------------------------
extern "C" void kernel_launch(void* const* d_in, const int* in_sizes, int n_in,
                              void* d_out, int out_size)
{
    const float* x     = (const float*)d_in[0];
    const int*   ei    = (const int*)d_in[1];
    const int*   batch = (const int*)d_in[2];
    const float* W1 = (const float*)d_in[3];
    const float* as1 = (const float*)d_in[4];
    const float* ad1 = (const float*)d_in[5];
    const float* b1 = (const float*)d_in[6];
    const float* W2 = (const float*)d_in[7];
    const float* as2 = (const float*)d_in[8];
    const float* ad2 = (const float*)d_in[9];
    const float* b2 = (const float*)d_in[10];
    const float* W3 = (const float*)d_in[11];
    const float* as3 = (const float*)d_in[12];
    const float* ad3 = (const float*)d_in[13];
    const float* b3 = (const float*)d_in[14];
    const float* fc1_w = (const float*)d_in[15];
    const float* fc1_b = (const float*)d_in[16];
    const float* fc2_w = (const float*)d_in[17];
    const float* fc2_b = (const float*)d_in[18];
    float* outp = (float*)d_out;

    // --- CSR build ---
    zero_counts_kernel<<<(NN + 255) / 256, 256>>>();
    hist_kernel<<<(EE + 255) / 256, 256>>>(ei);
    scan_kernel<<<1, 1024>>>();
    csr_fill_kernel<<<(EE + 255) / 256, 256>>>(ei);

    dim3 blk(256);
    // --- layer 1: g_bufB = x @ W1 [N,312]  (K=78, fp32) ---
    {
        dim3 grid((312 + 127) / 128, (NN + 127) / 128);
        sgemm128<<<grid, blk>>>(x, 0, W1, nullptr, 2, NN, 312, 78, nullptr, 0);
        attn_scores<<<(NN * 32 + 127) / 128, 128>>>(as1, ad1, HEADS, D1);
        gat_agg<HEADS, D1, 3><<<NN, 128>>>(b1);
    }
    // --- layer 2: g_bufB = g_bufA @ W2 [N,1248]  (K=312, tf32) ---
    {
        dim3 grid((1248 + 127) / 128, (NN + 127) / 128);
        tgemm_tf32<<<grid, blk>>>(nullptr, 1, W2, nullptr, 2, NN, 1248, 312);
        attn_scores<<<(NN * 32 + 127) / 128, 128>>>(as2, ad2, HEADS, D2);
        gat_agg<HEADS, D2, 10><<<NN, 128>>>(b2);
    }
    // --- layer 3: g_bufB = g_bufA @ W3 [N,1248]  (K=1248, tf32) ---
    {
        dim3 grid((1248 + 127) / 128, (NN + 127) / 128);
        tgemm_tf32<<<grid, blk>>>(nullptr, 1, W3, nullptr, 2, NN, 1248, 1248);
        attn_scores<<<(NN * 32 + 127) / 128, 128>>>(as3, ad3, 1, D3);
        gat_agg<1, D3, 10><<<NN, 128>>>(b3);
    }
    // --- pool + FC (fp32 for final accuracy) ---
    {
        dim3 pg(GG, (D3 + 127) / 128);
        pool_max<<<pg, 128>>>(batch);
        dim3 g1((HID + 127) / 128, (GG + 127) / 128);
        sgemm_db<<<g1, blk>>>(nullptr, 3, fc1_w, nullptr, 4, GG, HID, D3, fc1_b, 1);
        dim3 g2((OUTD + 127) / 128, (GG + 127) / 128);
        sgemm_db<<<g2, blk>>>(nullptr, 4, fc2_w, outp, 0, GG, OUTD, HID, fc2_b, 1);
    }
    (void)n_in; (void)in_sizes; (void)out_size;
}

// round 7
// speedup vs baseline: 2.3994x; 1.1383x over previous
#include <cuda_runtime.h>
#include <cuda_bf16.h>
#include <math.h>
#include <stdint.h>

// ----------------------------------------------------------------------------
// Problem constants
// ----------------------------------------------------------------------------
#define NN     50000
#define EE     200000
#define HEADS  4
#define GG     512
#define HID    1024
#define OUTD   128
#define D1     78
#define D2     312
#define D3     1248
#define NEG    0.2f

// ----------------------------------------------------------------------------
// Scratch (device globals)
// ----------------------------------------------------------------------------
__device__ float g_bufA[(size_t)NN * D3];
__device__ float g_bufB[(size_t)NN * D3];
__device__ float g_asrc[(size_t)NN * HEADS];
__device__ float g_adst[(size_t)NN * HEADS];
__device__ int   g_counts[NN];
__device__ int   g_cursor[NN];
__device__ int   g_ptr[NN + 1];
__device__ int   g_csrsrc[EE];
__device__ float g_pool[GG * D3];
__device__ float g_fc1[GG * HID];

__device__ __forceinline__ float lrelu(float x) { return x > 0.f ? x : NEG * x; }

__device__ __forceinline__ const float* sel_cf(int sel, const float* ext) {
    switch (sel) {
        case 1: return g_bufA;
        case 2: return g_bufB;
        case 3: return g_pool;
        case 4: return g_fc1;
        default: return ext;
    }
}
__device__ __forceinline__ float* sel_f(int sel, float* ext) {
    switch (sel) {
        case 1: return g_bufA;
        case 2: return g_bufB;
        case 3: return g_pool;
        case 4: return g_fc1;
        default: return ext;
    }
}

__device__ __forceinline__ uint32_t f2tf(float f) {
    uint32_t r;
    asm("cvt.rna.tf32.f32 %0, %1;" : "=r"(r) : "f"(f));
    return r;
}

// ----------------------------------------------------------------------------
// CSR construction (edge_index is int32)
// ----------------------------------------------------------------------------
__global__ void zero_counts_kernel() {
    int i = blockIdx.x * blockDim.x + threadIdx.x;
    if (i < NN) { g_counts[i] = 0; g_cursor[i] = 0; }
}

__global__ void hist_kernel(const int* __restrict__ ei) {
    int e = blockIdx.x * blockDim.x + threadIdx.x;
    if (e < EE) atomicAdd(&g_counts[ei[EE + e]], 1);
}

__global__ void scan_kernel() {
    __shared__ int sh[1024];
    __shared__ int s_off;
    int tid = threadIdx.x;
    if (tid == 0) { s_off = 0; g_ptr[0] = 0; }
    __syncthreads();
    for (int base = 0; base < NN; base += 1024) {
        int v = (base + tid < NN) ? g_counts[base + tid] : 0;
        sh[tid] = v;
        __syncthreads();
        for (int s = 1; s < 1024; s <<= 1) {
            int t = (tid >= s) ? sh[tid - s] : 0;
            __syncthreads();
            sh[tid] += t;
            __syncthreads();
        }
        int off = s_off;
        if (base + tid < NN) g_ptr[base + tid + 1] = off + sh[tid];
        __syncthreads();
        if (tid == 0) s_off = off + sh[1023];
        __syncthreads();
    }
}

__global__ void csr_fill_kernel(const int* __restrict__ ei) {
    int e = blockIdx.x * blockDim.x + threadIdx.x;
    if (e < EE) {
        int r = ei[e];
        int c = ei[EE + e];
        int pos = g_ptr[c] + atomicAdd(&g_cursor[c], 1);
        g_csrsrc[pos] = r;
    }
}

// ----------------------------------------------------------------------------
// Generic SGEMM (any K) — layer-1 only (K=78)
// ----------------------------------------------------------------------------
__global__ void __launch_bounds__(256)
sgemm128(const float* Aext, int Asel, const float* __restrict__ B,
         float* Cext, int Csel, int M, int N, int K,
         const float* __restrict__ bias, int fuse)
{
    const float* A = sel_cf(Asel, Aext);
    float* Cm = sel_f(Csel, Cext);

    __shared__ float As[8][128];
    __shared__ float Bs[8][132];

    int tid = threadIdx.x;
    int bm = blockIdx.y * 128, bn = blockIdx.x * 128;
    int tx = tid & 15, ty = tid >> 4;

    float acc[8][8];
#pragma unroll
    for (int i = 0; i < 8; i++)
#pragma unroll
        for (int j = 0; j < 8; j++) acc[i][j] = 0.f;

    for (int k0 = 0; k0 < K; k0 += 8) {
#pragma unroll
        for (int i = 0; i < 4; i++) {
            int flat = tid * 4 + i;
            int m = flat >> 3, kk = flat & 7;
            int gm = bm + m, gk = k0 + kk;
            float v = 0.f;
            if (gm < M && gk < K) v = A[(size_t)gm * K + gk];
            As[kk][m] = v;
        }
        {
            int kk = tid >> 5;
            int n4 = (tid & 31) * 4;
            int gk = k0 + kk, gn = bn + n4;
            float v0 = 0.f, v1 = 0.f, v2 = 0.f, v3 = 0.f;
            if (gk < K) {
                const float* brow = B + (size_t)gk * N;
                if (gn + 3 < N) {
                    v0 = brow[gn]; v1 = brow[gn + 1];
                    v2 = brow[gn + 2]; v3 = brow[gn + 3];
                } else {
                    if (gn + 0 < N) v0 = brow[gn + 0];
                    if (gn + 1 < N) v1 = brow[gn + 1];
                    if (gn + 2 < N) v2 = brow[gn + 2];
                    if (gn + 3 < N) v3 = brow[gn + 3];
                }
            }
            Bs[kk][n4 + 0] = v0; Bs[kk][n4 + 1] = v1;
            Bs[kk][n4 + 2] = v2; Bs[kk][n4 + 3] = v3;
        }
        __syncthreads();

#pragma unroll
        for (int kk = 0; kk < 8; kk++) {
            float a[8], b[8];
#pragma unroll
            for (int i = 0; i < 8; i++) a[i] = As[kk][ty * 8 + i];
#pragma unroll
            for (int j = 0; j < 8; j++) b[j] = Bs[kk][tx * 8 + j];
#pragma unroll
            for (int i = 0; i < 8; i++)
#pragma unroll
                for (int j = 0; j < 8; j++)
                    acc[i][j] = fmaf(a[i], b[j], acc[i][j]);
        }
        __syncthreads();
    }

#pragma unroll
    for (int i = 0; i < 8; i++) {
        int gm = bm + ty * 8 + i;
        if (gm >= M) continue;
#pragma unroll
        for (int j = 0; j < 8; j++) {
            int gn = bn + tx * 8 + j;
            if (gn >= N) continue;
            float v = acc[i][j];
            if (fuse) { v += bias[gn]; v = fmaxf(v, 0.f); }
            Cm[(size_t)gm * N + gn] = v;
        }
    }
}

// ----------------------------------------------------------------------------
// Fast fp32 SGEMM (double-buffered) — FC layers (K % 8 == 0)
// ----------------------------------------------------------------------------
__global__ void __launch_bounds__(256)
sgemm_db(const float* Aext, int Asel, const float* __restrict__ B,
         float* Cext, int Csel, int M, int N, int K,
         const float* __restrict__ bias, int fuse)
{
    const float* A = sel_cf(Asel, Aext);
    float* Cm = sel_f(Csel, Cext);

    __shared__ float As[2][8][128];
    __shared__ float Bs[2][8][132];

    int tid = threadIdx.x;
    int bm = blockIdx.y * 128, bn = blockIdx.x * 128;
    int tx = tid & 15, ty = tid >> 4;

    int arow = tid >> 1;
    int akc  = (tid & 1) * 4;
    int brow = tid >> 5;
    int bcol = (tid & 31) * 4;

    int gmA = bm + arow;
    int gnB = bn + bcol;
    bool aok = (gmA < M);
    bool b4  = (gnB + 3 < N);

    float acc[8][8];
#pragma unroll
    for (int i = 0; i < 8; i++)
#pragma unroll
        for (int j = 0; j < 8; j++) acc[i][j] = 0.f;

    int steps = K >> 3;

    {
        float4 av = make_float4(0.f, 0.f, 0.f, 0.f);
        if (aok) av = *(const float4*)&A[(size_t)gmA * K + akc];
        float4 bv = make_float4(0.f, 0.f, 0.f, 0.f);
        const float* brp = &B[(size_t)brow * N];
        if (b4) bv = *(const float4*)&brp[gnB];
        else {
            if (gnB + 0 < N) bv.x = brp[gnB + 0];
            if (gnB + 1 < N) bv.y = brp[gnB + 1];
            if (gnB + 2 < N) bv.z = brp[gnB + 2];
        }
        As[0][akc + 0][arow] = av.x;
        As[0][akc + 1][arow] = av.y;
        As[0][akc + 2][arow] = av.z;
        As[0][akc + 3][arow] = av.w;
        *(float4*)&Bs[0][brow][bcol] = bv;
    }
    __syncthreads();

    for (int s = 0; s < steps; s++) {
        int cur = s & 1, nxt = cur ^ 1;
        bool has = (s + 1 < steps);

        float4 av2 = make_float4(0.f, 0.f, 0.f, 0.f);
        float4 bv2 = make_float4(0.f, 0.f, 0.f, 0.f);
        if (has) {
            int k0 = (s + 1) << 3;
            if (aok) av2 = *(const float4*)&A[(size_t)gmA * K + k0 + akc];
            const float* brp = &B[(size_t)(k0 + brow) * N];
            if (b4) bv2 = *(const float4*)&brp[gnB];
            else {
                if (gnB + 0 < N) bv2.x = brp[gnB + 0];
                if (gnB + 1 < N) bv2.y = brp[gnB + 1];
                if (gnB + 2 < N) bv2.z = brp[gnB + 2];
            }
        }

#pragma unroll
        for (int kk = 0; kk < 8; kk++) {
            float a[8], b[8];
            *(float4*)&a[0] = *(const float4*)&As[cur][kk][ty * 8];
            *(float4*)&a[4] = *(const float4*)&As[cur][kk][ty * 8 + 4];
            *(float4*)&b[0] = *(const float4*)&Bs[cur][kk][tx * 8];
            *(float4*)&b[4] = *(const float4*)&Bs[cur][kk][tx * 8 + 4];
#pragma unroll
            for (int i = 0; i < 8; i++)
#pragma unroll
                for (int j = 0; j < 8; j++)
                    acc[i][j] = fmaf(a[i], b[j], acc[i][j]);
        }

        if (has) {
            As[nxt][akc + 0][arow] = av2.x;
            As[nxt][akc + 1][arow] = av2.y;
            As[nxt][akc + 2][arow] = av2.z;
            As[nxt][akc + 3][arow] = av2.w;
            *(float4*)&Bs[nxt][brow][bcol] = bv2;
        }
        __syncthreads();
    }

#pragma unroll
    for (int i = 0; i < 8; i++) {
        int gm = bm + ty * 8 + i;
        if (gm >= M) continue;
        float* crow = &Cm[(size_t)gm * N];
#pragma unroll
        for (int j4 = 0; j4 < 2; j4++) {
            int gn = bn + tx * 8 + j4 * 4;
            float4 v;
            v.x = acc[i][j4 * 4 + 0];
            v.y = acc[i][j4 * 4 + 1];
            v.z = acc[i][j4 * 4 + 2];
            v.w = acc[i][j4 * 4 + 3];
            if (fuse) {
                v.x = fmaxf(v.x + bias[gn + 0], 0.f);
                v.y = fmaxf(v.y + bias[gn + 1], 0.f);
                v.z = fmaxf(v.z + bias[gn + 2], 0.f);
                v.w = fmaxf(v.w + bias[gn + 3], 0.f);
            }
            if (gn + 3 < N) {
                *(float4*)&crow[gn] = v;
            } else {
                if (gn + 0 < N) crow[gn + 0] = v.x;
                if (gn + 1 < N) crow[gn + 1] = v.y;
                if (gn + 2 < N) crow[gn + 2] = v.z;
            }
        }
    }
}

// ----------------------------------------------------------------------------
// TF32 tensor-core GEMM via legacy mma.sync (the only tensor path ptxas
// accepts on this toolchain). 128x128 block tile, BK=32, double-buffered
// dynamic smem, 256 threads (8 warps: 4m x 2n), warp tile 32x64.
// ----------------------------------------------------------------------------
__device__ __forceinline__ void mma_tf32(float c[4], const uint32_t a[4],
                                         uint32_t b0, uint32_t b1)
{
    asm volatile(
        "mma.sync.aligned.m16n8k8.row.col.f32.tf32.tf32.f32 "
        "{%0,%1,%2,%3}, {%4,%5,%6,%7}, {%8,%9}, {%0,%1,%2,%3};"
        : "+f"(c[0]), "+f"(c[1]), "+f"(c[2]), "+f"(c[3])
        : "r"(a[0]), "r"(a[1]), "r"(a[2]), "r"(a[3]), "r"(b0), "r"(b1));
}

#define TG_LDK   136
#define TG_STAGE (32 * TG_LDK)              // uint32 per operand per stage
#define TG_SMEM_BYTES (4 * TG_STAGE * 4)    // 2 stages x 2 operands

__global__ void __launch_bounds__(256)
tgemm_tf32(const float* Aext, int Asel, const float* __restrict__ B,
           float* Cext, int Csel, int M, int N, int K)
{
    extern __shared__ uint32_t sm[];
    uint32_t* Asm = sm;                     // [2][32][136]
    uint32_t* Bsm = sm + 2 * TG_STAGE;      // [2][32][136]

    const float* A = sel_cf(Asel, Aext);
    float* Cm = sel_f(Csel, Cext);

    int tid = threadIdx.x;
    int warpid = tid >> 5, lane = tid & 31;
    int bm = blockIdx.y * 128, bn = blockIdx.x * 128;
    int wm = (warpid >> 1) * 32;
    int wn = (warpid & 1) * 64;
    int grp = lane >> 2, tig = lane & 3;

    float cacc[2][8][4];
#pragma unroll
    for (int mf = 0; mf < 2; mf++)
#pragma unroll
        for (int nf = 0; nf < 8; nf++)
#pragma unroll
            for (int q = 0; q < 4; q++) cacc[mf][nf][q] = 0.f;

    int steps = (K + 31) >> 5;

    // staging registers
    float4 avr[4], bvr[4];

    // ---- global load of one K32 stage into regs ----
    auto ldStage = [&](int k0) {
#pragma unroll
        for (int q = 0; q < 4; q++) {
            int flat = q * 256 + tid;
            int am  = flat >> 3;            // 0..127
            int akq = (flat & 7) * 4;       // 0..28
            int gm = bm + am, gk = k0 + akq;
            float4 v = make_float4(0.f, 0.f, 0.f, 0.f);
            if (gm < M && gk < K) v = *(const float4*)&A[(size_t)gm * K + gk];
            avr[q] = v;
        }
#pragma unroll
        for (int q = 0; q < 4; q++) {
            int flat = q * 256 + tid;
            int bk  = flat >> 5;            // 0..31
            int bn4 = (flat & 31) * 4;      // 0..124
            int gk = k0 + bk, gn = bn + bn4;
            float4 v = make_float4(0.f, 0.f, 0.f, 0.f);
            if (gk < K) {
                const float* bp = &B[(size_t)gk * N];
                if (gn + 3 < N) v = *(const float4*)&bp[gn];
                else {
                    if (gn + 0 < N) v.x = bp[gn + 0];
                    if (gn + 1 < N) v.y = bp[gn + 1];
                    if (gn + 2 < N) v.z = bp[gn + 2];
                }
            }
            bvr[q] = v;
        }
    };
    // ---- store staged regs into smem stage st (with tf32 convert) ----
    auto stStage = [&](int st) {
        uint32_t* as = Asm + st * TG_STAGE;
        uint32_t* bs = Bsm + st * TG_STAGE;
#pragma unroll
        for (int q = 0; q < 4; q++) {
            int flat = q * 256 + tid;
            int am  = flat >> 3;
            int akq = (flat & 7) * 4;
            as[(akq + 0) * TG_LDK + am] = f2tf(avr[q].x);
            as[(akq + 1) * TG_LDK + am] = f2tf(avr[q].y);
            as[(akq + 2) * TG_LDK + am] = f2tf(avr[q].z);
            as[(akq + 3) * TG_LDK + am] = f2tf(avr[q].w);
        }
#pragma unroll
        for (int q = 0; q < 4; q++) {
            int flat = q * 256 + tid;
            int bk  = flat >> 5;
            int bn4 = (flat & 31) * 4;
            uint4 u;
            u.x = f2tf(bvr[q].x); u.y = f2tf(bvr[q].y);
            u.z = f2tf(bvr[q].z); u.w = f2tf(bvr[q].w);
            *(uint4*)&bs[bk * TG_LDK + bn4] = u;
        }
    };

    ldStage(0);
    stStage(0);
    __syncthreads();

    for (int s = 0; s < steps; s++) {
        int cur = s & 1;
        bool has = (s + 1 < steps);
        if (has) ldStage((s + 1) << 5);

        const uint32_t* as = Asm + cur * TG_STAGE;
        const uint32_t* bs = Bsm + cur * TG_STAGE;
#pragma unroll
        for (int kf = 0; kf < 4; kf++) {
            int kb = kf * 8;
            uint32_t af[2][4];
#pragma unroll
            for (int mf = 0; mf < 2; mf++) {
                int m0 = wm + mf * 16;
                af[mf][0] = as[(kb + tig    ) * TG_LDK + m0 + grp    ];
                af[mf][1] = as[(kb + tig    ) * TG_LDK + m0 + grp + 8];
                af[mf][2] = as[(kb + tig + 4) * TG_LDK + m0 + grp    ];
                af[mf][3] = as[(kb + tig + 4) * TG_LDK + m0 + grp + 8];
            }
#pragma unroll
            for (int nf = 0; nf < 8; nf++) {
                int n0 = wn + nf * 8 + grp;
                uint32_t b0 = bs[(kb + tig    ) * TG_LDK + n0];
                uint32_t b1 = bs[(kb + tig + 4) * TG_LDK + n0];
                mma_tf32(cacc[0][nf], af[0], b0, b1);
                mma_tf32(cacc[1][nf], af[1], b0, b1);
            }
        }

        if (has) stStage(cur ^ 1);
        __syncthreads();
    }

    // epilogue
#pragma unroll
    for (int mf = 0; mf < 2; mf++) {
#pragma unroll
        for (int nf = 0; nf < 8; nf++) {
            int r0 = bm + wm + mf * 16 + grp;
            int c0 = bn + wn + nf * 8 + tig * 2;
            const float* c = cacc[mf][nf];
            if (r0 < M) {
                if (c0 + 1 < N) *(float2*)&Cm[(size_t)r0 * N + c0] = make_float2(c[0], c[1]);
                else if (c0 < N) Cm[(size_t)r0 * N + c0] = c[0];
            }
            if (r0 + 8 < M) {
                if (c0 + 1 < N) *(float2*)&Cm[(size_t)(r0 + 8) * N + c0] = make_float2(c[2], c[3]);
                else if (c0 < N) Cm[(size_t)(r0 + 8) * N + c0] = c[2];
            }
        }
    }
}

// ----------------------------------------------------------------------------
// Per-node attention scores from g_bufB: one warp per node
// ----------------------------------------------------------------------------
__global__ void attn_scores(const float* __restrict__ att_s,
                            const float* __restrict__ att_d,
                            int H, int C)
{
    int warp = (blockIdx.x * blockDim.x + threadIdx.x) >> 5;
    int lane = threadIdx.x & 31;
    if (warp >= NN) return;
    for (int h = 0; h < H; h++) {
        const float* hr = g_bufB + (size_t)warp * H * C + (size_t)h * C;
        float ss = 0.f, sd = 0.f;
        for (int c = lane; c < C; c += 32) {
            float hv = hr[c];
            ss = fmaf(hv, att_s[h * C + c], ss);
            sd = fmaf(hv, att_d[h * C + c], sd);
        }
#pragma unroll
        for (int o = 16; o; o >>= 1) {
            ss += __shfl_down_sync(0xFFFFFFFFu, ss, o);
            sd += __shfl_down_sync(0xFFFFFFFFu, sd, o);
        }
        if (lane == 0) {
            g_asrc[warp * H + h] = ss;
            g_adst[warp * H + h] = sd;
        }
    }
}

// ----------------------------------------------------------------------------
// GAT aggregation (softmax over incoming edges + self loop) -> g_bufA
// ----------------------------------------------------------------------------
template<int H, int C, int NCH>
__global__ void __launch_bounds__(128)
gat_agg(const float* __restrict__ bias)
{
    constexpr int HC = H * C;
    constexpr int CHUNK = 64;
    int i = blockIdx.x;
    int tid = threadIdx.x;

    __shared__ float s_alpha[CHUNK][H];
    __shared__ int   s_src[CHUNK];

    const float* hbuf = g_bufB;
    float* out = g_bufA;

    float adsti[H], m[H], den[H], eself[H], aself[H];
#pragma unroll
    for (int h = 0; h < H; h++) adsti[h] = g_adst[i * H + h];
#pragma unroll
    for (int h = 0; h < H; h++) {
        eself[h] = lrelu(g_asrc[i * H + h] + adsti[h]);
        m[h] = eself[h];
    }

    int beg = g_ptr[i];
    int deg = g_ptr[i + 1] - beg;

    for (int j = 0; j < deg; j++) {
        int s = g_csrsrc[beg + j];
#pragma unroll
        for (int h = 0; h < H; h++) {
            float e = lrelu(g_asrc[s * H + h] + adsti[h]);
            m[h] = fmaxf(m[h], e);
        }
    }
#pragma unroll
    for (int h = 0; h < H; h++) den[h] = __expf(eself[h] - m[h]);
    for (int j = 0; j < deg; j++) {
        int s = g_csrsrc[beg + j];
#pragma unroll
        for (int h = 0; h < H; h++) {
            float e = lrelu(g_asrc[s * H + h] + adsti[h]);
            den[h] += __expf(e - m[h]);
        }
    }
#pragma unroll
    for (int h = 0; h < H; h++)
        aself[h] = __expf(eself[h] - m[h]) / (den[h] + 1e-16f);

    float acc[NCH];
    int   hidx[NCH];
#pragma unroll
    for (int t = 0; t < NCH; t++) {
        int c = tid + t * 128;
        hidx[t] = c / C;
        acc[t] = (c < HC) ? aself[hidx[t]] * hbuf[(size_t)i * HC + c] : 0.f;
    }

    for (int cb = 0; cb < deg; cb += CHUNK) {
        int cn = min(CHUNK, deg - cb);
        __syncthreads();
        if (tid < cn) {
            int s = g_csrsrc[beg + cb + tid];
            s_src[tid] = s;
#pragma unroll
            for (int h = 0; h < H; h++) {
                float e = lrelu(g_asrc[s * H + h] + adsti[h]);
                s_alpha[tid][h] = __expf(e - m[h]) / (den[h] + 1e-16f);
            }
        }
        __syncthreads();
        for (int j = 0; j < cn; j++) {
            const float* hr = hbuf + (size_t)s_src[j] * HC;
            float al[H];
#pragma unroll
            for (int h = 0; h < H; h++) al[h] = s_alpha[j][h];
#pragma unroll
            for (int t = 0; t < NCH; t++) {
                int c = tid + t * 128;
                if (c < HC) acc[t] = fmaf(al[hidx[t]], hr[c], acc[t]);
            }
        }
    }

#pragma unroll
    for (int t = 0; t < NCH; t++) {
        int c = tid + t * 128;
        if (c < HC) {
            float v = acc[t] + bias[c];
            out[(size_t)i * HC + c] = fmaxf(v, 0.f);
        }
    }
}

// ----------------------------------------------------------------------------
// Global max pool over sorted batch (int32): g_bufA -> g_pool
// ----------------------------------------------------------------------------
__global__ void pool_max(const int* __restrict__ batch)
{
    int g = blockIdx.x;
    int c = blockIdx.y * 128 + threadIdx.x;

    int lo = 0, hi = NN;
    while (lo < hi) { int mid = (lo + hi) >> 1; if (batch[mid] < g) lo = mid + 1; else hi = mid; }
    int start = lo;
    lo = start; hi = NN;
    while (lo < hi) { int mid = (lo + hi) >> 1; if (batch[mid] < g + 1) lo = mid + 1; else hi = mid; }
    int end = lo;

    if (c < D3) {
        float mv = 0.f;
        for (int n = start; n < end; n++)
            mv = fmaxf(mv, g_bufA[(size_t)n * D3 + c]);
        g_pool[g * D3 + c] = mv;
    }
}

// ----------------------------------------------------------------------------
// launch
// ----------------------------------------------------------------------------
extern "C" void kernel_launch(void* const* d_in, const int* in_sizes, int n_in,
                              void* d_out, int out_size)
{
    const float* x     = (const float*)d_in[0];
    const int*   ei    = (const int*)d_in[1];
    const int*   batch = (const int*)d_in[2];
    const float* W1 = (const float*)d_in[3];
    const float* as1 = (const float*)d_in[4];
    const float* ad1 = (const float*)d_in[5];
    const float* b1 = (const float*)d_in[6];
    const float* W2 = (const float*)d_in[7];
    const float* as2 = (const float*)d_in[8];
    const float* ad2 = (const float*)d_in[9];
    const float* b2 = (const float*)d_in[10];
    const float* W3 = (const float*)d_in[11];
    const float* as3 = (const float*)d_in[12];
    const float* ad3 = (const float*)d_in[13];
    const float* b3 = (const float*)d_in[14];
    const float* fc1_w = (const float*)d_in[15];
    const float* fc1_b = (const float*)d_in[16];
    const float* fc2_w = (const float*)d_in[17];
    const float* fc2_b = (const float*)d_in[18];
    float* outp = (float*)d_out;

    cudaFuncSetAttribute(tgemm_tf32,
                         cudaFuncAttributeMaxDynamicSharedMemorySize, TG_SMEM_BYTES);

    // --- CSR build ---
    zero_counts_kernel<<<(NN + 255) / 256, 256>>>();
    hist_kernel<<<(EE + 255) / 256, 256>>>(ei);
    scan_kernel<<<1, 1024>>>();
    csr_fill_kernel<<<(EE + 255) / 256, 256>>>(ei);

    dim3 blk(256);
    // --- layer 1: g_bufB = x @ W1 [N,312]  (K=78, fp32) ---
    {
        dim3 grid((312 + 127) / 128, (NN + 127) / 128);
        sgemm128<<<grid, blk>>>(x, 0, W1, nullptr, 2, NN, 312, 78, nullptr, 0);
        attn_scores<<<(NN * 32 + 127) / 128, 128>>>(as1, ad1, HEADS, D1);
        gat_agg<HEADS, D1, 3><<<NN, 128>>>(b1);
    }
    // --- layer 2: g_bufB = g_bufA @ W2 [N,1248]  (K=312, tf32) ---
    {
        dim3 grid((1248 + 127) / 128, (NN + 127) / 128);
        tgemm_tf32<<<grid, blk, TG_SMEM_BYTES>>>(nullptr, 1, W2, nullptr, 2, NN, 1248, 312);
        attn_scores<<<(NN * 32 + 127) / 128, 128>>>(as2, ad2, HEADS, D2);
        gat_agg<HEADS, D2, 10><<<NN, 128>>>(b2);
    }
    // --- layer 3: g_bufB = g_bufA @ W3 [N,1248]  (K=1248, tf32) ---
    {
        dim3 grid((1248 + 127) / 128, (NN + 127) / 128);
        tgemm_tf32<<<grid, blk, TG_SMEM_BYTES>>>(nullptr, 1, W3, nullptr, 2, NN, 1248, 1248);
        attn_scores<<<(NN * 32 + 127) / 128, 128>>>(as3, ad3, 1, D3);
        gat_agg<1, D3, 10><<<NN, 128>>>(b3);
    }
    // --- pool + FC (fp32) ---
    {
        dim3 pg(GG, (D3 + 127) / 128);
        pool_max<<<pg, 128>>>(batch);
        dim3 g1((HID + 127) / 128, (GG + 127) / 128);
        sgemm_db<<<g1, blk>>>(nullptr, 3, fc1_w, nullptr, 4, GG, HID, D3, fc1_b, 1);
        dim3 g2((OUTD + 127) / 128, (GG + 127) / 128);
        sgemm_db<<<g2, blk>>>(nullptr, 4, fc2_w, outp, 0, GG, OUTD, HID, fc2_b, 1);
    }
    (void)n_in; (void)in_sizes; (void)out_size;
}

// round 8
// speedup vs baseline: 2.4972x; 1.0407x over previous
#include <cuda_runtime.h>
#include <cuda_bf16.h>
#include <math.h>
#include <stdint.h>

// ----------------------------------------------------------------------------
// Problem constants
// ----------------------------------------------------------------------------
#define NN     50000
#define EE     200000
#define HEADS  4
#define GG     512
#define HID    1024
#define OUTD   128
#define D1     78
#define D2     312
#define D3     1248
#define NEG    0.2f
#define K1PAD  80

// ----------------------------------------------------------------------------
// Scratch (device globals)
// ----------------------------------------------------------------------------
__device__ float g_bufA[(size_t)NN * D3];
__device__ float g_bufB[(size_t)NN * D3];
__device__ float g_xpad[(size_t)NN * K1PAD];
__device__ float g_w1pad[K1PAD * 312];
__device__ float g_asrc[(size_t)NN * HEADS];
__device__ float g_adst[(size_t)NN * HEADS];
__device__ int   g_counts[NN];
__device__ int   g_cursor[NN];
__device__ int   g_ptr[NN + 1];
__device__ int   g_csrsrc[EE];
__device__ float g_pool[GG * D3];
__device__ float g_fc1[GG * HID];

__device__ __forceinline__ float lrelu(float x) { return x > 0.f ? x : NEG * x; }

__device__ __forceinline__ const float* sel_cf(int sel, const float* ext) {
    switch (sel) {
        case 1: return g_bufA;
        case 2: return g_bufB;
        case 3: return g_pool;
        case 4: return g_fc1;
        case 5: return g_xpad;
        case 6: return g_w1pad;
        default: return ext;
    }
}
__device__ __forceinline__ float* sel_f(int sel, float* ext) {
    switch (sel) {
        case 1: return g_bufA;
        case 2: return g_bufB;
        case 3: return g_pool;
        case 4: return g_fc1;
        default: return ext;
    }
}

__device__ __forceinline__ uint32_t f2tf(float f) {
    uint32_t r;
    asm("cvt.rna.tf32.f32 %0, %1;" : "=r"(r) : "f"(f));
    return r;
}

// ----------------------------------------------------------------------------
// CSR construction (edge_index is int32)
// ----------------------------------------------------------------------------
__global__ void zero_counts_kernel() {
    int i = blockIdx.x * blockDim.x + threadIdx.x;
    if (i < NN) { g_counts[i] = 0; g_cursor[i] = 0; }
}

__global__ void hist_kernel(const int* __restrict__ ei) {
    int e = blockIdx.x * blockDim.x + threadIdx.x;
    if (e < EE) atomicAdd(&g_counts[ei[EE + e]], 1);
}

__global__ void scan_kernel() {
    __shared__ int sh[1024];
    __shared__ int s_off;
    int tid = threadIdx.x;
    if (tid == 0) { s_off = 0; g_ptr[0] = 0; }
    __syncthreads();
    for (int base = 0; base < NN; base += 1024) {
        int v = (base + tid < NN) ? g_counts[base + tid] : 0;
        sh[tid] = v;
        __syncthreads();
        for (int s = 1; s < 1024; s <<= 1) {
            int t = (tid >= s) ? sh[tid - s] : 0;
            __syncthreads();
            sh[tid] += t;
            __syncthreads();
        }
        int off = s_off;
        if (base + tid < NN) g_ptr[base + tid + 1] = off + sh[tid];
        __syncthreads();
        if (tid == 0) s_off = off + sh[1023];
        __syncthreads();
    }
}

__global__ void csr_fill_kernel(const int* __restrict__ ei) {
    int e = blockIdx.x * blockDim.x + threadIdx.x;
    if (e < EE) {
        int r = ei[e];
        int c = ei[EE + e];
        int pos = g_ptr[c] + atomicAdd(&g_cursor[c], 1);
        g_csrsrc[pos] = r;
    }
}

// ----------------------------------------------------------------------------
// Pad kernels for layer-1 tensor GEMM
// ----------------------------------------------------------------------------
__global__ void pad_x_kernel(const float* __restrict__ x) {
    int idx = blockIdx.x * blockDim.x + threadIdx.x;
    if (idx < NN * K1PAD) {
        int n = idx / K1PAD, k = idx - n * K1PAD;
        g_xpad[idx] = (k < D1) ? x[(size_t)n * D1 + k] : 0.f;
    }
}
__global__ void pad_w1_kernel(const float* __restrict__ W1) {
    int idx = blockIdx.x * blockDim.x + threadIdx.x;
    if (idx < K1PAD * 312) {
        int k = idx / 312, n = idx - k * 312;
        g_w1pad[idx] = (k < D1) ? W1[(size_t)k * 312 + n] : 0.f;
    }
}

// ----------------------------------------------------------------------------
// Fast fp32 SGEMM (double-buffered) — FC layers (K % 8 == 0)
// ----------------------------------------------------------------------------
__global__ void __launch_bounds__(256)
sgemm_db(const float* Aext, int Asel, const float* __restrict__ B,
         float* Cext, int Csel, int M, int N, int K,
         const float* __restrict__ bias, int fuse)
{
    const float* A = sel_cf(Asel, Aext);
    float* Cm = sel_f(Csel, Cext);

    __shared__ float As[2][8][128];
    __shared__ float Bs[2][8][132];

    int tid = threadIdx.x;
    int bm = blockIdx.y * 128, bn = blockIdx.x * 128;
    int tx = tid & 15, ty = tid >> 4;

    int arow = tid >> 1;
    int akc  = (tid & 1) * 4;
    int brow = tid >> 5;
    int bcol = (tid & 31) * 4;

    int gmA = bm + arow;
    int gnB = bn + bcol;
    bool aok = (gmA < M);
    bool b4  = (gnB + 3 < N);

    float acc[8][8];
#pragma unroll
    for (int i = 0; i < 8; i++)
#pragma unroll
        for (int j = 0; j < 8; j++) acc[i][j] = 0.f;

    int steps = K >> 3;

    {
        float4 av = make_float4(0.f, 0.f, 0.f, 0.f);
        if (aok) av = *(const float4*)&A[(size_t)gmA * K + akc];
        float4 bv = make_float4(0.f, 0.f, 0.f, 0.f);
        const float* brp = &B[(size_t)brow * N];
        if (b4) bv = *(const float4*)&brp[gnB];
        else {
            if (gnB + 0 < N) bv.x = brp[gnB + 0];
            if (gnB + 1 < N) bv.y = brp[gnB + 1];
            if (gnB + 2 < N) bv.z = brp[gnB + 2];
        }
        As[0][akc + 0][arow] = av.x;
        As[0][akc + 1][arow] = av.y;
        As[0][akc + 2][arow] = av.z;
        As[0][akc + 3][arow] = av.w;
        *(float4*)&Bs[0][brow][bcol] = bv;
    }
    __syncthreads();

    for (int s = 0; s < steps; s++) {
        int cur = s & 1, nxt = cur ^ 1;
        bool has = (s + 1 < steps);

        float4 av2 = make_float4(0.f, 0.f, 0.f, 0.f);
        float4 bv2 = make_float4(0.f, 0.f, 0.f, 0.f);
        if (has) {
            int k0 = (s + 1) << 3;
            if (aok) av2 = *(const float4*)&A[(size_t)gmA * K + k0 + akc];
            const float* brp = &B[(size_t)(k0 + brow) * N];
            if (b4) bv2 = *(const float4*)&brp[gnB];
            else {
                if (gnB + 0 < N) bv2.x = brp[gnB + 0];
                if (gnB + 1 < N) bv2.y = brp[gnB + 1];
                if (gnB + 2 < N) bv2.z = brp[gnB + 2];
            }
        }

#pragma unroll
        for (int kk = 0; kk < 8; kk++) {
            float a[8], b[8];
            *(float4*)&a[0] = *(const float4*)&As[cur][kk][ty * 8];
            *(float4*)&a[4] = *(const float4*)&As[cur][kk][ty * 8 + 4];
            *(float4*)&b[0] = *(const float4*)&Bs[cur][kk][tx * 8];
            *(float4*)&b[4] = *(const float4*)&Bs[cur][kk][tx * 8 + 4];
#pragma unroll
            for (int i = 0; i < 8; i++)
#pragma unroll
                for (int j = 0; j < 8; j++)
                    acc[i][j] = fmaf(a[i], b[j], acc[i][j]);
        }

        if (has) {
            As[nxt][akc + 0][arow] = av2.x;
            As[nxt][akc + 1][arow] = av2.y;
            As[nxt][akc + 2][arow] = av2.z;
            As[nxt][akc + 3][arow] = av2.w;
            *(float4*)&Bs[nxt][brow][bcol] = bv2;
        }
        __syncthreads();
    }

#pragma unroll
    for (int i = 0; i < 8; i++) {
        int gm = bm + ty * 8 + i;
        if (gm >= M) continue;
        float* crow = &Cm[(size_t)gm * N];
#pragma unroll
        for (int j4 = 0; j4 < 2; j4++) {
            int gn = bn + tx * 8 + j4 * 4;
            float4 v;
            v.x = acc[i][j4 * 4 + 0];
            v.y = acc[i][j4 * 4 + 1];
            v.z = acc[i][j4 * 4 + 2];
            v.w = acc[i][j4 * 4 + 3];
            if (fuse) {
                v.x = fmaxf(v.x + bias[gn + 0], 0.f);
                v.y = fmaxf(v.y + bias[gn + 1], 0.f);
                v.z = fmaxf(v.z + bias[gn + 2], 0.f);
                v.w = fmaxf(v.w + bias[gn + 3], 0.f);
            }
            if (gn + 3 < N) {
                *(float4*)&crow[gn] = v;
            } else {
                if (gn + 0 < N) crow[gn + 0] = v.x;
                if (gn + 1 < N) crow[gn + 1] = v.y;
                if (gn + 2 < N) crow[gn + 2] = v.z;
            }
        }
    }
}

// ----------------------------------------------------------------------------
// TF32 tensor-core GEMM (legacy mma.sync). 128x128 tile, BK=32, 2-stage smem.
// Requires K % 4 == 0 (A row float4 loads stay within the row).
// ----------------------------------------------------------------------------
__device__ __forceinline__ void mma_tf32(float c[4], const uint32_t a[4],
                                         uint32_t b0, uint32_t b1)
{
    asm volatile(
        "mma.sync.aligned.m16n8k8.row.col.f32.tf32.tf32.f32 "
        "{%0,%1,%2,%3}, {%4,%5,%6,%7}, {%8,%9}, {%0,%1,%2,%3};"
        : "+f"(c[0]), "+f"(c[1]), "+f"(c[2]), "+f"(c[3])
        : "r"(a[0]), "r"(a[1]), "r"(a[2]), "r"(a[3]), "r"(b0), "r"(b1));
}

#define TG_LDK   136
#define TG_STAGE (32 * TG_LDK)
#define TG_SMEM_BYTES (4 * TG_STAGE * 4)

__global__ void __launch_bounds__(256)
tgemm_tf32(const float* Aext, int Asel, const float* Bext, int Bsel,
           float* Cext, int Csel, int M, int N, int K)
{
    extern __shared__ uint32_t sm[];
    uint32_t* Asm = sm;
    uint32_t* Bsm = sm + 2 * TG_STAGE;

    const float* A = sel_cf(Asel, Aext);
    const float* B = sel_cf(Bsel, Bext);
    float* Cm = sel_f(Csel, Cext);

    int tid = threadIdx.x;
    int warpid = tid >> 5, lane = tid & 31;
    int bm = blockIdx.y * 128, bn = blockIdx.x * 128;
    int wm = (warpid >> 1) * 32;
    int wn = (warpid & 1) * 64;
    int grp = lane >> 2, tig = lane & 3;

    float cacc[2][8][4];
#pragma unroll
    for (int mf = 0; mf < 2; mf++)
#pragma unroll
        for (int nf = 0; nf < 8; nf++)
#pragma unroll
            for (int q = 0; q < 4; q++) cacc[mf][nf][q] = 0.f;

    int steps = (K + 31) >> 5;

    float4 avr[4], bvr[4];

    auto ldStage = [&](int k0) {
#pragma unroll
        for (int q = 0; q < 4; q++) {
            int flat = q * 256 + tid;
            int am  = flat >> 3;
            int akq = (flat & 7) * 4;
            int gm = bm + am, gk = k0 + akq;
            float4 v = make_float4(0.f, 0.f, 0.f, 0.f);
            if (gm < M && gk < K) v = *(const float4*)&A[(size_t)gm * K + gk];
            avr[q] = v;
        }
#pragma unroll
        for (int q = 0; q < 4; q++) {
            int flat = q * 256 + tid;
            int bk  = flat >> 5;
            int bn4 = (flat & 31) * 4;
            int gk = k0 + bk, gn = bn + bn4;
            float4 v = make_float4(0.f, 0.f, 0.f, 0.f);
            if (gk < K) {
                const float* bp = &B[(size_t)gk * N];
                if (gn + 3 < N) v = *(const float4*)&bp[gn];
                else {
                    if (gn + 0 < N) v.x = bp[gn + 0];
                    if (gn + 1 < N) v.y = bp[gn + 1];
                    if (gn + 2 < N) v.z = bp[gn + 2];
                }
            }
            bvr[q] = v;
        }
    };
    auto stStage = [&](int st) {
        uint32_t* as = Asm + st * TG_STAGE;
        uint32_t* bs = Bsm + st * TG_STAGE;
#pragma unroll
        for (int q = 0; q < 4; q++) {
            int flat = q * 256 + tid;
            int am  = flat >> 3;
            int akq = (flat & 7) * 4;
            as[(akq + 0) * TG_LDK + am] = f2tf(avr[q].x);
            as[(akq + 1) * TG_LDK + am] = f2tf(avr[q].y);
            as[(akq + 2) * TG_LDK + am] = f2tf(avr[q].z);
            as[(akq + 3) * TG_LDK + am] = f2tf(avr[q].w);
        }
#pragma unroll
        for (int q = 0; q < 4; q++) {
            int flat = q * 256 + tid;
            int bk  = flat >> 5;
            int bn4 = (flat & 31) * 4;
            uint4 u;
            u.x = f2tf(bvr[q].x); u.y = f2tf(bvr[q].y);
            u.z = f2tf(bvr[q].z); u.w = f2tf(bvr[q].w);
            *(uint4*)&bs[bk * TG_LDK + bn4] = u;
        }
    };

    ldStage(0);
    stStage(0);
    __syncthreads();

    for (int s = 0; s < steps; s++) {
        int cur = s & 1;
        bool has = (s + 1 < steps);
        if (has) ldStage((s + 1) << 5);

        const uint32_t* as = Asm + cur * TG_STAGE;
        const uint32_t* bs = Bsm + cur * TG_STAGE;
#pragma unroll
        for (int kf = 0; kf < 4; kf++) {
            int kb = kf * 8;
            uint32_t af[2][4];
#pragma unroll
            for (int mf = 0; mf < 2; mf++) {
                int m0 = wm + mf * 16;
                af[mf][0] = as[(kb + tig    ) * TG_LDK + m0 + grp    ];
                af[mf][1] = as[(kb + tig    ) * TG_LDK + m0 + grp + 8];
                af[mf][2] = as[(kb + tig + 4) * TG_LDK + m0 + grp    ];
                af[mf][3] = as[(kb + tig + 4) * TG_LDK + m0 + grp + 8];
            }
#pragma unroll
            for (int nf = 0; nf < 8; nf++) {
                int n0 = wn + nf * 8 + grp;
                uint32_t b0 = bs[(kb + tig    ) * TG_LDK + n0];
                uint32_t b1 = bs[(kb + tig + 4) * TG_LDK + n0];
                mma_tf32(cacc[0][nf], af[0], b0, b1);
                mma_tf32(cacc[1][nf], af[1], b0, b1);
            }
        }

        if (has) stStage(cur ^ 1);
        __syncthreads();
    }

#pragma unroll
    for (int mf = 0; mf < 2; mf++) {
#pragma unroll
        for (int nf = 0; nf < 8; nf++) {
            int r0 = bm + wm + mf * 16 + grp;
            int c0 = bn + wn + nf * 8 + tig * 2;
            const float* c = cacc[mf][nf];
            if (r0 < M) {
                if (c0 + 1 < N) *(float2*)&Cm[(size_t)r0 * N + c0] = make_float2(c[0], c[1]);
                else if (c0 < N) Cm[(size_t)r0 * N + c0] = c[0];
            }
            if (r0 + 8 < M) {
                if (c0 + 1 < N) *(float2*)&Cm[(size_t)(r0 + 8) * N + c0] = make_float2(c[2], c[3]);
                else if (c0 < N) Cm[(size_t)(r0 + 8) * N + c0] = c[2];
            }
        }
    }
}

// ----------------------------------------------------------------------------
// attn scores, scalar (layer 1: C=78 not /4). One warp per node.
// ----------------------------------------------------------------------------
__global__ void attn_scores(const float* __restrict__ att_s,
                            const float* __restrict__ att_d,
                            int H, int C)
{
    int warp = (blockIdx.x * blockDim.x + threadIdx.x) >> 5;
    int lane = threadIdx.x & 31;
    if (warp >= NN) return;
    for (int h = 0; h < H; h++) {
        const float* hr = g_bufB + (size_t)warp * H * C + (size_t)h * C;
        float ss = 0.f, sd = 0.f;
        for (int c = lane; c < C; c += 32) {
            float hv = hr[c];
            ss = fmaf(hv, att_s[h * C + c], ss);
            sd = fmaf(hv, att_d[h * C + c], sd);
        }
#pragma unroll
        for (int o = 16; o; o >>= 1) {
            ss += __shfl_down_sync(0xFFFFFFFFu, ss, o);
            sd += __shfl_down_sync(0xFFFFFFFFu, sd, o);
        }
        if (lane == 0) {
            g_asrc[warp * H + h] = ss;
            g_adst[warp * H + h] = sd;
        }
    }
}

// float4 variant, requires C % 4 == 0 (layers 2,3)
__global__ void attn_scores4(const float* __restrict__ att_s,
                             const float* __restrict__ att_d,
                             int H, int C)
{
    int warp = (blockIdx.x * blockDim.x + threadIdx.x) >> 5;
    int lane = threadIdx.x & 31;
    if (warp >= NN) return;
    int C4 = C >> 2;
    const float4* row4 = (const float4*)(g_bufB + (size_t)warp * H * C);
    const float4* as4  = (const float4*)att_s;
    const float4* ad4  = (const float4*)att_d;
    for (int h = 0; h < H; h++) {
        int base = h * C4;
        float ss = 0.f, sd = 0.f;
        for (int c = lane; c < C4; c += 32) {
            float4 v = row4[base + c];
            float4 s = as4[base + c];
            float4 d = ad4[base + c];
            ss = fmaf(v.x, s.x, fmaf(v.y, s.y, fmaf(v.z, s.z, fmaf(v.w, s.w, ss))));
            sd = fmaf(v.x, d.x, fmaf(v.y, d.y, fmaf(v.z, d.z, fmaf(v.w, d.w, sd))));
        }
#pragma unroll
        for (int o = 16; o; o >>= 1) {
            ss += __shfl_down_sync(0xFFFFFFFFu, ss, o);
            sd += __shfl_down_sync(0xFFFFFFFFu, sd, o);
        }
        if (lane == 0) {
            g_asrc[warp * H + h] = ss;
            g_adst[warp * H + h] = sd;
        }
    }
}

// ----------------------------------------------------------------------------
// GAT aggregation, float4 gather. NV float4-chunks per thread (128 threads).
// ----------------------------------------------------------------------------
template<int H, int C, int NV>
__global__ void __launch_bounds__(128)
gat_agg4(const float* __restrict__ bias)
{
    constexpr int HC  = H * C;
    constexpr int HC4 = HC / 4;
    constexpr int CHUNK = 64;
    int i = blockIdx.x;
    int tid = threadIdx.x;

    __shared__ float s_alpha[CHUNK][4];
    __shared__ int   s_src[CHUNK];

    const float* hbuf = g_bufB;
    float* out = g_bufA;

    float adsti[H], m[H], den[H], eself[H], aself[H];
#pragma unroll
    for (int h = 0; h < H; h++) adsti[h] = g_adst[i * H + h];
#pragma unroll
    for (int h = 0; h < H; h++) {
        eself[h] = lrelu(g_asrc[i * H + h] + adsti[h]);
        m[h] = eself[h];
    }

    int beg = g_ptr[i];
    int deg = g_ptr[i + 1] - beg;

    for (int j = 0; j < deg; j++) {
        int s = g_csrsrc[beg + j];
#pragma unroll
        for (int h = 0; h < H; h++) {
            float e = lrelu(g_asrc[s * H + h] + adsti[h]);
            m[h] = fmaxf(m[h], e);
        }
    }
#pragma unroll
    for (int h = 0; h < H; h++) den[h] = __expf(eself[h] - m[h]);
    for (int j = 0; j < deg; j++) {
        int s = g_csrsrc[beg + j];
#pragma unroll
        for (int h = 0; h < H; h++) {
            float e = lrelu(g_asrc[s * H + h] + adsti[h]);
            den[h] += __expf(e - m[h]);
        }
    }
#pragma unroll
    for (int h = 0; h < H; h++)
        aself[h] = __expf(eself[h] - m[h]) / (den[h] + 1e-16f);

    // per-chunk head indices (compile-time pattern per thread)
    int c4i[NV];
    bool val[NV];
    int h0[NV], h1[NV], h2[NV], h3[NV];
#pragma unroll
    for (int t = 0; t < NV; t++) {
        int c4 = tid + t * 128;
        c4i[t] = c4;
        val[t] = (c4 < HC4);
        int c = c4 * 4;
        h0[t] = min(c     / C, H - 1);
        h1[t] = min((c+1) / C, H - 1);
        h2[t] = min((c+2) / C, H - 1);
        h3[t] = min((c+3) / C, H - 1);
    }

    const float4* self4 = (const float4*)(hbuf + (size_t)i * HC);
    float4 acc[NV];
#pragma unroll
    for (int t = 0; t < NV; t++) {
        if (val[t]) {
            float4 v = self4[c4i[t]];
            acc[t].x = aself[h0[t]] * v.x;
            acc[t].y = aself[h1[t]] * v.y;
            acc[t].z = aself[h2[t]] * v.z;
            acc[t].w = aself[h3[t]] * v.w;
        } else {
            acc[t] = make_float4(0.f, 0.f, 0.f, 0.f);
        }
    }

    for (int cb = 0; cb < deg; cb += CHUNK) {
        int cn = min(CHUNK, deg - cb);
        __syncthreads();
        if (tid < cn) {
            int s = g_csrsrc[beg + cb + tid];
            s_src[tid] = s;
#pragma unroll
            for (int h = 0; h < H; h++) {
                float e = lrelu(g_asrc[s * H + h] + adsti[h]);
                s_alpha[tid][h] = __expf(e - m[h]) / (den[h] + 1e-16f);
            }
        }
        __syncthreads();
        for (int j = 0; j < cn; j++) {
            const float4* hr4 = (const float4*)(hbuf + (size_t)s_src[j] * HC);
#pragma unroll
            for (int t = 0; t < NV; t++) {
                if (!val[t]) continue;
                float4 v = hr4[c4i[t]];
                acc[t].x = fmaf(s_alpha[j][h0[t]], v.x, acc[t].x);
                acc[t].y = fmaf(s_alpha[j][h1[t]], v.y, acc[t].y);
                acc[t].z = fmaf(s_alpha[j][h2[t]], v.z, acc[t].z);
                acc[t].w = fmaf(s_alpha[j][h3[t]], v.w, acc[t].w);
            }
        }
    }

    const float4* bias4 = (const float4*)bias;
    float4* out4 = (float4*)(out + (size_t)i * HC);
#pragma unroll
    for (int t = 0; t < NV; t++) {
        if (!val[t]) continue;
        float4 b = bias4[c4i[t]];
        float4 v;
        v.x = fmaxf(acc[t].x + b.x, 0.f);
        v.y = fmaxf(acc[t].y + b.y, 0.f);
        v.z = fmaxf(acc[t].z + b.z, 0.f);
        v.w = fmaxf(acc[t].w + b.w, 0.f);
        out4[c4i[t]] = v;
    }
}

// ----------------------------------------------------------------------------
// Global max pool over sorted batch (int32), float4: g_bufA -> g_pool
// ----------------------------------------------------------------------------
__global__ void pool_max(const int* __restrict__ batch)
{
    int g = blockIdx.x;
    int c4 = blockIdx.y * 128 + threadIdx.x;   // D3/4 = 312 float4

    int lo = 0, hi = NN;
    while (lo < hi) { int mid = (lo + hi) >> 1; if (batch[mid] < g) lo = mid + 1; else hi = mid; }
    int start = lo;
    lo = start; hi = NN;
    while (lo < hi) { int mid = (lo + hi) >> 1; if (batch[mid] < g + 1) lo = mid + 1; else hi = mid; }
    int end = lo;

    if (c4 < D3 / 4) {
        float4 mv = make_float4(0.f, 0.f, 0.f, 0.f);
        for (int n = start; n < end; n++) {
            float4 v = *(const float4*)&g_bufA[(size_t)n * D3 + c4 * 4];
            mv.x = fmaxf(mv.x, v.x); mv.y = fmaxf(mv.y, v.y);
            mv.z = fmaxf(mv.z, v.z); mv.w = fmaxf(mv.w, v.w);
        }
        *(float4*)&g_pool[g * D3 + c4 * 4] = mv;
    }
}

// ----------------------------------------------------------------------------
// launch
// ----------------------------------------------------------------------------
extern "C" void kernel_launch(void* const* d_in, const int* in_sizes, int n_in,
                              void* d_out, int out_size)
{
    const float* x     = (const float*)d_in[0];
    const int*   ei    = (const int*)d_in[1];
    const int*   batch = (const int*)d_in[2];
    const float* W1 = (const float*)d_in[3];
    const float* as1 = (const float*)d_in[4];
    const float* ad1 = (const float*)d_in[5];
    const float* b1 = (const float*)d_in[6];
    const float* W2 = (const float*)d_in[7];
    const float* as2 = (const float*)d_in[8];
    const float* ad2 = (const float*)d_in[9];
    const float* b2 = (const float*)d_in[10];
    const float* W3 = (const float*)d_in[11];
    const float* as3 = (const float*)d_in[12];
    const float* ad3 = (const float*)d_in[13];
    const float* b3 = (const float*)d_in[14];
    const float* fc1_w = (const float*)d_in[15];
    const float* fc1_b = (const float*)d_in[16];
    const float* fc2_w = (const float*)d_in[17];
    const float* fc2_b = (const float*)d_in[18];
    float* outp = (float*)d_out;

    cudaFuncSetAttribute(tgemm_tf32,
                         cudaFuncAttributeMaxDynamicSharedMemorySize, TG_SMEM_BYTES);

    // --- CSR build + input padding (parallel streams of small work) ---
    zero_counts_kernel<<<(NN + 255) / 256, 256>>>();
    hist_kernel<<<(EE + 255) / 256, 256>>>(ei);
    scan_kernel<<<1, 1024>>>();
    csr_fill_kernel<<<(EE + 255) / 256, 256>>>(ei);
    pad_x_kernel<<<(NN * K1PAD + 255) / 256, 256>>>(x);
    pad_w1_kernel<<<(K1PAD * 312 + 255) / 256, 256>>>(W1);

    dim3 blk(256);
    // --- layer 1: g_bufB = xpad @ w1pad [N,312]  (K=80, tf32) ---
    {
        dim3 grid((312 + 127) / 128, (NN + 127) / 128);
        tgemm_tf32<<<grid, blk, TG_SMEM_BYTES>>>(nullptr, 5, nullptr, 6, nullptr, 2,
                                                 NN, 312, K1PAD);
        attn_scores<<<(NN * 32 + 127) / 128, 128>>>(as1, ad1, HEADS, D1);
        gat_agg4<HEADS, D1, 1><<<NN, 128>>>(b1);   // HC4 = 78
    }
    // --- layer 2: g_bufB = g_bufA @ W2 [N,1248]  (K=312, tf32) ---
    {
        dim3 grid((1248 + 127) / 128, (NN + 127) / 128);
        tgemm_tf32<<<grid, blk, TG_SMEM_BYTES>>>(nullptr, 1, W2, 0, nullptr, 2,
                                                 NN, 1248, 312);
        attn_scores4<<<(NN * 32 + 127) / 128, 128>>>(as2, ad2, HEADS, D2);
        gat_agg4<HEADS, D2, 3><<<NN, 128>>>(b2);   // HC4 = 312
    }
    // --- layer 3: g_bufB = g_bufA @ W3 [N,1248]  (K=1248, tf32) ---
    {
        dim3 grid((1248 + 127) / 128, (NN + 127) / 128);
        tgemm_tf32<<<grid, blk, TG_SMEM_BYTES>>>(nullptr, 1, W3, 0, nullptr, 2,
                                                 NN, 1248, 1248);
        attn_scores4<<<(NN * 32 + 127) / 128, 128>>>(as3, ad3, 1, D3);
        gat_agg4<1, D3, 3><<<NN, 128>>>(b3);       // HC4 = 312
    }
    // --- pool + FC (fp32) ---
    {
        dim3 pg(GG, (D3 / 4 + 127) / 128);
        pool_max<<<pg, 128>>>(batch);
        dim3 g1((HID + 127) / 128, (GG + 127) / 128);
        sgemm_db<<<g1, blk>>>(nullptr, 3, fc1_w, nullptr, 4, GG, HID, D3, fc1_b, 1);
        dim3 g2((OUTD + 127) / 128, (GG + 127) / 128);
        sgemm_db<<<g2, blk>>>(nullptr, 4, fc2_w, outp, 0, GG, OUTD, HID, fc2_b, 1);
    }
    (void)n_in; (void)in_sizes; (void)out_size;
}

// round 9
// speedup vs baseline: 2.5717x; 1.0298x over previous
#include <cuda_runtime.h>
#include <cuda_bf16.h>
#include <math.h>
#include <stdint.h>

// ----------------------------------------------------------------------------
// Problem constants
// ----------------------------------------------------------------------------
#define NN     50000
#define EE     200000
#define HEADS  4
#define GG     512
#define HID    1024
#define OUTD   128
#define D1     78
#define D2     312
#define D3     1248
#define NEG    0.2f
#define K1PAD  80

// ----------------------------------------------------------------------------
// Scratch (device globals)
// ----------------------------------------------------------------------------
__device__ float g_bufA[(size_t)NN * D3];
__device__ float g_bufB[(size_t)NN * D3];
__device__ float g_xpad[(size_t)NN * K1PAD];
__device__ float g_w1pad[K1PAD * 312];
__device__ float g_asrc[(size_t)NN * HEADS];
__device__ float g_adst[(size_t)NN * HEADS];
__device__ int   g_counts[NN];
__device__ int   g_cursor[NN];
__device__ int   g_ptr[NN + 1];
__device__ int   g_csrsrc[EE];
__device__ float g_pool[GG * D3];
__device__ float g_fc1[GG * HID];

__device__ __forceinline__ float lrelu(float x) { return x > 0.f ? x : NEG * x; }

__device__ __forceinline__ const float* sel_cf(int sel, const float* ext) {
    switch (sel) {
        case 1: return g_bufA;
        case 2: return g_bufB;
        case 3: return g_pool;
        case 4: return g_fc1;
        case 5: return g_xpad;
        case 6: return g_w1pad;
        default: return ext;
    }
}
__device__ __forceinline__ float* sel_f(int sel, float* ext) {
    switch (sel) {
        case 1: return g_bufA;
        case 2: return g_bufB;
        case 3: return g_pool;
        case 4: return g_fc1;
        default: return ext;
    }
}

__device__ __forceinline__ uint32_t f2tf(float f) {
    uint32_t r;
    asm("cvt.rna.tf32.f32 %0, %1;" : "=r"(r) : "f"(f));
    return r;
}

// ----------------------------------------------------------------------------
// CSR construction (edge_index is int32)
// ----------------------------------------------------------------------------
__global__ void zero_counts_kernel() {
    int i = blockIdx.x * blockDim.x + threadIdx.x;
    if (i < NN) { g_counts[i] = 0; g_cursor[i] = 0; }
}

__global__ void zero_att_kernel() {
    int i = blockIdx.x * blockDim.x + threadIdx.x;
    if (i < NN * HEADS) { g_asrc[i] = 0.f; g_adst[i] = 0.f; }
}

__global__ void hist_kernel(const int* __restrict__ ei) {
    int e = blockIdx.x * blockDim.x + threadIdx.x;
    if (e < EE) atomicAdd(&g_counts[ei[EE + e]], 1);
}

__global__ void scan_kernel() {
    __shared__ int sh[1024];
    __shared__ int s_off;
    int tid = threadIdx.x;
    if (tid == 0) { s_off = 0; g_ptr[0] = 0; }
    __syncthreads();
    for (int base = 0; base < NN; base += 1024) {
        int v = (base + tid < NN) ? g_counts[base + tid] : 0;
        sh[tid] = v;
        __syncthreads();
        for (int s = 1; s < 1024; s <<= 1) {
            int t = (tid >= s) ? sh[tid - s] : 0;
            __syncthreads();
            sh[tid] += t;
            __syncthreads();
        }
        int off = s_off;
        if (base + tid < NN) g_ptr[base + tid + 1] = off + sh[tid];
        __syncthreads();
        if (tid == 0) s_off = off + sh[1023];
        __syncthreads();
    }
}

__global__ void csr_fill_kernel(const int* __restrict__ ei) {
    int e = blockIdx.x * blockDim.x + threadIdx.x;
    if (e < EE) {
        int r = ei[e];
        int c = ei[EE + e];
        int pos = g_ptr[c] + atomicAdd(&g_cursor[c], 1);
        g_csrsrc[pos] = r;
    }
}

// ----------------------------------------------------------------------------
// Pad kernels for layer-1 tensor GEMM
// ----------------------------------------------------------------------------
__global__ void pad_x_kernel(const float* __restrict__ x) {
    int idx = blockIdx.x * blockDim.x + threadIdx.x;
    if (idx < NN * K1PAD) {
        int n = idx / K1PAD, k = idx - n * K1PAD;
        g_xpad[idx] = (k < D1) ? x[(size_t)n * D1 + k] : 0.f;
    }
}
__global__ void pad_w1_kernel(const float* __restrict__ W1) {
    int idx = blockIdx.x * blockDim.x + threadIdx.x;
    if (idx < K1PAD * 312) {
        int k = idx / 312, n = idx - k * 312;
        g_w1pad[idx] = (k < D1) ? W1[(size_t)k * 312 + n] : 0.f;
    }
}

// ----------------------------------------------------------------------------
// Fast fp32 SGEMM (double-buffered) — FC layers (K % 8 == 0)
// ----------------------------------------------------------------------------
__global__ void __launch_bounds__(256)
sgemm_db(const float* Aext, int Asel, const float* __restrict__ B,
         float* Cext, int Csel, int M, int N, int K,
         const float* __restrict__ bias, int fuse)
{
    const float* A = sel_cf(Asel, Aext);
    float* Cm = sel_f(Csel, Cext);

    __shared__ float As[2][8][128];
    __shared__ float Bs[2][8][132];

    int tid = threadIdx.x;
    int bm = blockIdx.y * 128, bn = blockIdx.x * 128;
    int tx = tid & 15, ty = tid >> 4;

    int arow = tid >> 1;
    int akc  = (tid & 1) * 4;
    int brow = tid >> 5;
    int bcol = (tid & 31) * 4;

    int gmA = bm + arow;
    int gnB = bn + bcol;
    bool aok = (gmA < M);
    bool b4  = (gnB + 3 < N);

    float acc[8][8];
#pragma unroll
    for (int i = 0; i < 8; i++)
#pragma unroll
        for (int j = 0; j < 8; j++) acc[i][j] = 0.f;

    int steps = K >> 3;

    {
        float4 av = make_float4(0.f, 0.f, 0.f, 0.f);
        if (aok) av = *(const float4*)&A[(size_t)gmA * K + akc];
        float4 bv = make_float4(0.f, 0.f, 0.f, 0.f);
        const float* brp = &B[(size_t)brow * N];
        if (b4) bv = *(const float4*)&brp[gnB];
        else {
            if (gnB + 0 < N) bv.x = brp[gnB + 0];
            if (gnB + 1 < N) bv.y = brp[gnB + 1];
            if (gnB + 2 < N) bv.z = brp[gnB + 2];
        }
        As[0][akc + 0][arow] = av.x;
        As[0][akc + 1][arow] = av.y;
        As[0][akc + 2][arow] = av.z;
        As[0][akc + 3][arow] = av.w;
        *(float4*)&Bs[0][brow][bcol] = bv;
    }
    __syncthreads();

    for (int s = 0; s < steps; s++) {
        int cur = s & 1, nxt = cur ^ 1;
        bool has = (s + 1 < steps);

        float4 av2 = make_float4(0.f, 0.f, 0.f, 0.f);
        float4 bv2 = make_float4(0.f, 0.f, 0.f, 0.f);
        if (has) {
            int k0 = (s + 1) << 3;
            if (aok) av2 = *(const float4*)&A[(size_t)gmA * K + k0 + akc];
            const float* brp = &B[(size_t)(k0 + brow) * N];
            if (b4) bv2 = *(const float4*)&brp[gnB];
            else {
                if (gnB + 0 < N) bv2.x = brp[gnB + 0];
                if (gnB + 1 < N) bv2.y = brp[gnB + 1];
                if (gnB + 2 < N) bv2.z = brp[gnB + 2];
            }
        }

#pragma unroll
        for (int kk = 0; kk < 8; kk++) {
            float a[8], b[8];
            *(float4*)&a[0] = *(const float4*)&As[cur][kk][ty * 8];
            *(float4*)&a[4] = *(const float4*)&As[cur][kk][ty * 8 + 4];
            *(float4*)&b[0] = *(const float4*)&Bs[cur][kk][tx * 8];
            *(float4*)&b[4] = *(const float4*)&Bs[cur][kk][tx * 8 + 4];
#pragma unroll
            for (int i = 0; i < 8; i++)
#pragma unroll
                for (int j = 0; j < 8; j++)
                    acc[i][j] = fmaf(a[i], b[j], acc[i][j]);
        }

        if (has) {
            As[nxt][akc + 0][arow] = av2.x;
            As[nxt][akc + 1][arow] = av2.y;
            As[nxt][akc + 2][arow] = av2.z;
            As[nxt][akc + 3][arow] = av2.w;
            *(float4*)&Bs[nxt][brow][bcol] = bv2;
        }
        __syncthreads();
    }

#pragma unroll
    for (int i = 0; i < 8; i++) {
        int gm = bm + ty * 8 + i;
        if (gm >= M) continue;
        float* crow = &Cm[(size_t)gm * N];
#pragma unroll
        for (int j4 = 0; j4 < 2; j4++) {
            int gn = bn + tx * 8 + j4 * 4;
            float4 v;
            v.x = acc[i][j4 * 4 + 0];
            v.y = acc[i][j4 * 4 + 1];
            v.z = acc[i][j4 * 4 + 2];
            v.w = acc[i][j4 * 4 + 3];
            if (fuse) {
                v.x = fmaxf(v.x + bias[gn + 0], 0.f);
                v.y = fmaxf(v.y + bias[gn + 1], 0.f);
                v.z = fmaxf(v.z + bias[gn + 2], 0.f);
                v.w = fmaxf(v.w + bias[gn + 3], 0.f);
            }
            if (gn + 3 < N) {
                *(float4*)&crow[gn] = v;
            } else {
                if (gn + 0 < N) crow[gn + 0] = v.x;
                if (gn + 1 < N) crow[gn + 1] = v.y;
                if (gn + 2 < N) crow[gn + 2] = v.z;
            }
        }
    }
}

// ----------------------------------------------------------------------------
// TF32 tensor-core GEMM (legacy mma.sync) with fused attention-score epilogue.
// 128x128 tile, BK=32, 2-stage smem, 256 threads (8 warps: 4m x 2n).
// ATT_H > 0: accumulate a_src[r,h] = <C[r, hC:(h+1)C], att_s[h]> via atomics.
// ----------------------------------------------------------------------------
__device__ __forceinline__ void mma_tf32(float c[4], const uint32_t a[4],
                                         uint32_t b0, uint32_t b1)
{
    asm volatile(
        "mma.sync.aligned.m16n8k8.row.col.f32.tf32.tf32.f32 "
        "{%0,%1,%2,%3}, {%4,%5,%6,%7}, {%8,%9}, {%0,%1,%2,%3};"
        : "+f"(c[0]), "+f"(c[1]), "+f"(c[2]), "+f"(c[3])
        : "r"(a[0]), "r"(a[1]), "r"(a[2]), "r"(a[3]), "r"(b0), "r"(b1));
}

#define TG_LDK   136
#define TG_STAGE (32 * TG_LDK)
#define TG_SMEM_BYTES (4 * TG_STAGE * 4)

template<int ATT_H, int ATT_C>
__global__ void __launch_bounds__(256)
tgemm_tf32(const float* Aext, int Asel, const float* Bext, int Bsel,
           float* Cext, int Csel, int M, int N, int K,
           const float* __restrict__ att_s, const float* __restrict__ att_d)
{
    extern __shared__ uint32_t sm[];
    uint32_t* Asm = sm;
    uint32_t* Bsm = sm + 2 * TG_STAGE;

    const float* A = sel_cf(Asel, Aext);
    const float* B = sel_cf(Bsel, Bext);
    float* Cm = sel_f(Csel, Cext);

    int tid = threadIdx.x;
    int warpid = tid >> 5, lane = tid & 31;
    int bm = blockIdx.y * 128, bn = blockIdx.x * 128;
    int wm = (warpid >> 1) * 32;
    int wn = (warpid & 1) * 64;
    int grp = lane >> 2, tig = lane & 3;

    float cacc[2][8][4];
#pragma unroll
    for (int mf = 0; mf < 2; mf++)
#pragma unroll
        for (int nf = 0; nf < 8; nf++)
#pragma unroll
            for (int q = 0; q < 4; q++) cacc[mf][nf][q] = 0.f;

    int steps = (K + 31) >> 5;

    float4 avr[4], bvr[4];

    auto ldStage = [&](int k0) {
#pragma unroll
        for (int q = 0; q < 4; q++) {
            int flat = q * 256 + tid;
            int am  = flat >> 3;
            int akq = (flat & 7) * 4;
            int gm = bm + am, gk = k0 + akq;
            float4 v = make_float4(0.f, 0.f, 0.f, 0.f);
            if (gm < M && gk < K) v = *(const float4*)&A[(size_t)gm * K + gk];
            avr[q] = v;
        }
#pragma unroll
        for (int q = 0; q < 4; q++) {
            int flat = q * 256 + tid;
            int bk  = flat >> 5;
            int bn4 = (flat & 31) * 4;
            int gk = k0 + bk, gn = bn + bn4;
            float4 v = make_float4(0.f, 0.f, 0.f, 0.f);
            if (gk < K) {
                const float* bp = &B[(size_t)gk * N];
                if (gn + 3 < N) v = *(const float4*)&bp[gn];
                else {
                    if (gn + 0 < N) v.x = bp[gn + 0];
                    if (gn + 1 < N) v.y = bp[gn + 1];
                    if (gn + 2 < N) v.z = bp[gn + 2];
                }
            }
            bvr[q] = v;
        }
    };
    auto stStage = [&](int st) {
        uint32_t* as = Asm + st * TG_STAGE;
        uint32_t* bs = Bsm + st * TG_STAGE;
#pragma unroll
        for (int q = 0; q < 4; q++) {
            int flat = q * 256 + tid;
            int am  = flat >> 3;
            int akq = (flat & 7) * 4;
            as[(akq + 0) * TG_LDK + am] = f2tf(avr[q].x);
            as[(akq + 1) * TG_LDK + am] = f2tf(avr[q].y);
            as[(akq + 2) * TG_LDK + am] = f2tf(avr[q].z);
            as[(akq + 3) * TG_LDK + am] = f2tf(avr[q].w);
        }
#pragma unroll
        for (int q = 0; q < 4; q++) {
            int flat = q * 256 + tid;
            int bk  = flat >> 5;
            int bn4 = (flat & 31) * 4;
            uint4 u;
            u.x = f2tf(bvr[q].x); u.y = f2tf(bvr[q].y);
            u.z = f2tf(bvr[q].z); u.w = f2tf(bvr[q].w);
            *(uint4*)&bs[bk * TG_LDK + bn4] = u;
        }
    };

    ldStage(0);
    stStage(0);
    __syncthreads();

    for (int s = 0; s < steps; s++) {
        int cur = s & 1;
        bool has = (s + 1 < steps);
        if (has) ldStage((s + 1) << 5);

        const uint32_t* as = Asm + cur * TG_STAGE;
        const uint32_t* bs = Bsm + cur * TG_STAGE;
#pragma unroll
        for (int kf = 0; kf < 4; kf++) {
            int kb = kf * 8;
            uint32_t af[2][4];
#pragma unroll
            for (int mf = 0; mf < 2; mf++) {
                int m0 = wm + mf * 16;
                af[mf][0] = as[(kb + tig    ) * TG_LDK + m0 + grp    ];
                af[mf][1] = as[(kb + tig    ) * TG_LDK + m0 + grp + 8];
                af[mf][2] = as[(kb + tig + 4) * TG_LDK + m0 + grp    ];
                af[mf][3] = as[(kb + tig + 4) * TG_LDK + m0 + grp + 8];
            }
#pragma unroll
            for (int nf = 0; nf < 8; nf++) {
                int n0 = wn + nf * 8 + grp;
                uint32_t b0 = bs[(kb + tig    ) * TG_LDK + n0];
                uint32_t b1 = bs[(kb + tig + 4) * TG_LDK + n0];
                mma_tf32(cacc[0][nf], af[0], b0, b1);
                mma_tf32(cacc[1][nf], af[1], b0, b1);
            }
        }

        if (has) stStage(cur ^ 1);
        __syncthreads();
    }

    // ---- write C ----
#pragma unroll
    for (int mf = 0; mf < 2; mf++) {
#pragma unroll
        for (int nf = 0; nf < 8; nf++) {
            int r0 = bm + wm + mf * 16 + grp;
            int c0 = bn + wn + nf * 8 + tig * 2;
            const float* c = cacc[mf][nf];
            if (r0 < M) {
                if (c0 + 1 < N) *(float2*)&Cm[(size_t)r0 * N + c0] = make_float2(c[0], c[1]);
                else if (c0 < N) Cm[(size_t)r0 * N + c0] = c[0];
            }
            if (r0 + 8 < M) {
                if (c0 + 1 < N) *(float2*)&Cm[(size_t)(r0 + 8) * N + c0] = make_float2(c[2], c[3]);
                else if (c0 < N) Cm[(size_t)(r0 + 8) * N + c0] = c[2];
            }
        }
    }

    // ---- fused attention scores ----
    if (ATT_H > 0) {
        // a 64-col warp strip spans at most 2 heads (ATT_C >= 64)
        int hbase = (bn + wn) / ATT_C;
        float accs[2][2][2];   // [mf][rowhalf][slot]
        float accd[2][2][2];
#pragma unroll
        for (int mf = 0; mf < 2; mf++)
#pragma unroll
            for (int rh = 0; rh < 2; rh++)
#pragma unroll
                for (int sl = 0; sl < 2; sl++) {
                    accs[mf][rh][sl] = 0.f;
                    accd[mf][rh][sl] = 0.f;
                }
#pragma unroll
        for (int nf = 0; nf < 8; nf++) {
#pragma unroll
            for (int q = 0; q < 2; q++) {
                int col = bn + wn + nf * 8 + tig * 2 + q;
                if (col < N) {
                    float vs = att_s[col];
                    float vd = att_d[col];
                    bool s1 = (col / ATT_C) != hbase;
#pragma unroll
                    for (int mf = 0; mf < 2; mf++) {
                        float cA = cacc[mf][nf][q];
                        float cB = cacc[mf][nf][2 + q];
                        if (!s1) {
                            accs[mf][0][0] = fmaf(cA, vs, accs[mf][0][0]);
                            accs[mf][1][0] = fmaf(cB, vs, accs[mf][1][0]);
                            accd[mf][0][0] = fmaf(cA, vd, accd[mf][0][0]);
                            accd[mf][1][0] = fmaf(cB, vd, accd[mf][1][0]);
                        } else {
                            accs[mf][0][1] = fmaf(cA, vs, accs[mf][0][1]);
                            accs[mf][1][1] = fmaf(cB, vs, accs[mf][1][1]);
                            accd[mf][0][1] = fmaf(cA, vd, accd[mf][0][1]);
                            accd[mf][1][1] = fmaf(cB, vd, accd[mf][1][1]);
                        }
                    }
                }
            }
        }
        // reduce across the 4 lanes (tig) sharing each row
#pragma unroll
        for (int off = 1; off <= 2; off <<= 1) {
#pragma unroll
            for (int mf = 0; mf < 2; mf++)
#pragma unroll
                for (int rh = 0; rh < 2; rh++)
#pragma unroll
                    for (int sl = 0; sl < 2; sl++) {
                        accs[mf][rh][sl] += __shfl_xor_sync(0xFFFFFFFFu, accs[mf][rh][sl], off);
                        accd[mf][rh][sl] += __shfl_xor_sync(0xFFFFFFFFu, accd[mf][rh][sl], off);
                    }
        }
        if (tig == 0) {
#pragma unroll
            for (int mf = 0; mf < 2; mf++)
#pragma unroll
                for (int rh = 0; rh < 2; rh++) {
                    int r = bm + wm + mf * 16 + grp + rh * 8;
                    if (r < M) {
#pragma unroll
                        for (int sl = 0; sl < 2; sl++) {
                            int h = hbase + sl;
                            if (h < ATT_H) {
                                float vs = accs[mf][rh][sl];
                                float vd = accd[mf][rh][sl];
                                if (vs != 0.f) atomicAdd(&g_asrc[r * ATT_H + h], vs);
                                if (vd != 0.f) atomicAdd(&g_adst[r * ATT_H + h], vd);
                            }
                        }
                    }
                }
        }
    }
}

// ----------------------------------------------------------------------------
// GAT aggregation, float4 gather + online softmax. One 128-thread block/node.
// ----------------------------------------------------------------------------
template<int H, int C, int NV>
__global__ void __launch_bounds__(128)
gat_agg4(const float* __restrict__ bias)
{
    constexpr int HC  = H * C;
    constexpr int HC4 = HC / 4;
    constexpr int CHUNK = 64;
    int i = blockIdx.x;
    int tid = threadIdx.x;

    __shared__ float s_alpha[CHUNK][4];
    __shared__ int   s_src[CHUNK];

    const float* hbuf = g_bufB;
    float* out = g_bufA;

    float adsti[H], m[H], den[H], eself[H], aself[H];
#pragma unroll
    for (int h = 0; h < H; h++) adsti[h] = g_adst[i * H + h];
#pragma unroll
    for (int h = 0; h < H; h++) {
        eself[h] = lrelu(g_asrc[i * H + h] + adsti[h]);
        m[h] = eself[h];
        den[h] = 1.f;   // self term: exp(eself - m) = 1
    }

    int beg = g_ptr[i];
    int deg = g_ptr[i + 1] - beg;

    // single online-softmax pass (max + denom)
    for (int j = 0; j < deg; j++) {
        int s = g_csrsrc[beg + j];
#pragma unroll
        for (int h = 0; h < H; h++) {
            float e = lrelu(g_asrc[s * H + h] + adsti[h]);
            float mo = m[h];
            float mn = fmaxf(mo, e);
            den[h] = den[h] * __expf(mo - mn) + __expf(e - mn);
            m[h] = mn;
        }
    }
#pragma unroll
    for (int h = 0; h < H; h++)
        aself[h] = __expf(eself[h] - m[h]) / (den[h] + 1e-16f);

    // per-chunk head indices (compile-time pattern per thread)
    int c4i[NV];
    bool val[NV];
    int h0[NV], h1[NV], h2[NV], h3[NV];
#pragma unroll
    for (int t = 0; t < NV; t++) {
        int c4 = tid + t * 128;
        c4i[t] = c4;
        val[t] = (c4 < HC4);
        int c = c4 * 4;
        h0[t] = min(c     / C, H - 1);
        h1[t] = min((c+1) / C, H - 1);
        h2[t] = min((c+2) / C, H - 1);
        h3[t] = min((c+3) / C, H - 1);
    }

    const float4* self4 = (const float4*)(hbuf + (size_t)i * HC);
    float4 acc[NV];
#pragma unroll
    for (int t = 0; t < NV; t++) {
        if (val[t]) {
            float4 v = self4[c4i[t]];
            acc[t].x = aself[h0[t]] * v.x;
            acc[t].y = aself[h1[t]] * v.y;
            acc[t].z = aself[h2[t]] * v.z;
            acc[t].w = aself[h3[t]] * v.w;
        } else {
            acc[t] = make_float4(0.f, 0.f, 0.f, 0.f);
        }
    }

    for (int cb = 0; cb < deg; cb += CHUNK) {
        int cn = min(CHUNK, deg - cb);
        __syncthreads();
        if (tid < cn) {
            int s = g_csrsrc[beg + cb + tid];
            s_src[tid] = s;
#pragma unroll
            for (int h = 0; h < H; h++) {
                float e = lrelu(g_asrc[s * H + h] + adsti[h]);
                s_alpha[tid][h] = __expf(e - m[h]) / (den[h] + 1e-16f);
            }
        }
        __syncthreads();
        for (int j = 0; j < cn; j++) {
            const float4* hr4 = (const float4*)(hbuf + (size_t)s_src[j] * HC);
#pragma unroll
            for (int t = 0; t < NV; t++) {
                if (!val[t]) continue;
                float4 v = hr4[c4i[t]];
                acc[t].x = fmaf(s_alpha[j][h0[t]], v.x, acc[t].x);
                acc[t].y = fmaf(s_alpha[j][h1[t]], v.y, acc[t].y);
                acc[t].z = fmaf(s_alpha[j][h2[t]], v.z, acc[t].z);
                acc[t].w = fmaf(s_alpha[j][h3[t]], v.w, acc[t].w);
            }
        }
    }

    const float4* bias4 = (const float4*)bias;
    float4* out4 = (float4*)(out + (size_t)i * HC);
#pragma unroll
    for (int t = 0; t < NV; t++) {
        if (!val[t]) continue;
        float4 b = bias4[c4i[t]];
        float4 v;
        v.x = fmaxf(acc[t].x + b.x, 0.f);
        v.y = fmaxf(acc[t].y + b.y, 0.f);
        v.z = fmaxf(acc[t].z + b.z, 0.f);
        v.w = fmaxf(acc[t].w + b.w, 0.f);
        out4[c4i[t]] = v;
    }
}

// ----------------------------------------------------------------------------
// Global max pool over sorted batch (int32), float4: g_bufA -> g_pool
// ----------------------------------------------------------------------------
__global__ void pool_max(const int* __restrict__ batch)
{
    int g = blockIdx.x;
    int c4 = blockIdx.y * 128 + threadIdx.x;

    int lo = 0, hi = NN;
    while (lo < hi) { int mid = (lo + hi) >> 1; if (batch[mid] < g) lo = mid + 1; else hi = mid; }
    int start = lo;
    lo = start; hi = NN;
    while (lo < hi) { int mid = (lo + hi) >> 1; if (batch[mid] < g + 1) lo = mid + 1; else hi = mid; }
    int end = lo;

    if (c4 < D3 / 4) {
        float4 mv = make_float4(0.f, 0.f, 0.f, 0.f);
        for (int n = start; n < end; n++) {
            float4 v = *(const float4*)&g_bufA[(size_t)n * D3 + c4 * 4];
            mv.x = fmaxf(mv.x, v.x); mv.y = fmaxf(mv.y, v.y);
            mv.z = fmaxf(mv.z, v.z); mv.w = fmaxf(mv.w, v.w);
        }
        *(float4*)&g_pool[g * D3 + c4 * 4] = mv;
    }
}

// ----------------------------------------------------------------------------
// launch
// ----------------------------------------------------------------------------
extern "C" void kernel_launch(void* const* d_in, const int* in_sizes, int n_in,
                              void* d_out, int out_size)
{
    const float* x     = (const float*)d_in[0];
    const int*   ei    = (const int*)d_in[1];
    const int*   batch = (const int*)d_in[2];
    const float* W1 = (const float*)d_in[3];
    const float* as1 = (const float*)d_in[4];
    const float* ad1 = (const float*)d_in[5];
    const float* b1 = (const float*)d_in[6];
    const float* W2 = (const float*)d_in[7];
    const float* as2 = (const float*)d_in[8];
    const float* ad2 = (const float*)d_in[9];
    const float* b2 = (const float*)d_in[10];
    const float* W3 = (const float*)d_in[11];
    const float* as3 = (const float*)d_in[12];
    const float* ad3 = (const float*)d_in[13];
    const float* b3 = (const float*)d_in[14];
    const float* fc1_w = (const float*)d_in[15];
    const float* fc1_b = (const float*)d_in[16];
    const float* fc2_w = (const float*)d_in[17];
    const float* fc2_b = (const float*)d_in[18];
    float* outp = (float*)d_out;

    cudaFuncSetAttribute(tgemm_tf32<HEADS, D1>,
                         cudaFuncAttributeMaxDynamicSharedMemorySize, TG_SMEM_BYTES);
    cudaFuncSetAttribute(tgemm_tf32<HEADS, D2>,
                         cudaFuncAttributeMaxDynamicSharedMemorySize, TG_SMEM_BYTES);
    cudaFuncSetAttribute(tgemm_tf32<1, D3>,
                         cudaFuncAttributeMaxDynamicSharedMemorySize, TG_SMEM_BYTES);

    // --- CSR build + input padding + score zeroing ---
    zero_counts_kernel<<<(NN + 255) / 256, 256>>>();
    hist_kernel<<<(EE + 255) / 256, 256>>>(ei);
    scan_kernel<<<1, 1024>>>();
    csr_fill_kernel<<<(EE + 255) / 256, 256>>>(ei);
    pad_x_kernel<<<(NN * K1PAD + 255) / 256, 256>>>(x);
    pad_w1_kernel<<<(K1PAD * 312 + 255) / 256, 256>>>(W1);
    zero_att_kernel<<<(NN * HEADS + 255) / 256, 256>>>();

    dim3 blk(256);
    // --- layer 1: g_bufB = xpad @ w1pad [N,312] (K=80, tf32 + fused attn) ---
    {
        dim3 grid((312 + 127) / 128, (NN + 127) / 128);
        tgemm_tf32<HEADS, D1><<<grid, blk, TG_SMEM_BYTES>>>(
            nullptr, 5, nullptr, 6, nullptr, 2, NN, 312, K1PAD, as1, ad1);
        gat_agg4<HEADS, D1, 1><<<NN, 128>>>(b1);
    }
    // --- layer 2: g_bufB = g_bufA @ W2 [N,1248] (K=312, tf32 + fused attn) ---
    {
        zero_att_kernel<<<(NN * HEADS + 255) / 256, 256>>>();
        dim3 grid((1248 + 127) / 128, (NN + 127) / 128);
        tgemm_tf32<HEADS, D2><<<grid, blk, TG_SMEM_BYTES>>>(
            nullptr, 1, W2, 0, nullptr, 2, NN, 1248, 312, as2, ad2);
        gat_agg4<HEADS, D2, 3><<<NN, 128>>>(b2);
    }
    // --- layer 3: g_bufB = g_bufA @ W3 [N,1248] (K=1248, tf32 + fused attn) ---
    {
        zero_att_kernel<<<(NN * HEADS + 255) / 256, 256>>>();
        dim3 grid((1248 + 127) / 128, (NN + 127) / 128);
        tgemm_tf32<1, D3><<<grid, blk, TG_SMEM_BYTES>>>(
            nullptr, 1, W3, 0, nullptr, 2, NN, 1248, 1248, as3, ad3);
        gat_agg4<1, D3, 3><<<NN, 128>>>(b3);
    }
    // --- pool + FC (fp32) ---
    {
        dim3 pg(GG, (D3 / 4 + 127) / 128);
        pool_max<<<pg, 128>>>(batch);
        dim3 g1((HID + 127) / 128, (GG + 127) / 128);
        sgemm_db<<<g1, blk>>>(nullptr, 3, fc1_w, nullptr, 4, GG, HID, D3, fc1_b, 1);
        dim3 g2((OUTD + 127) / 128, (GG + 127) / 128);
        sgemm_db<<<g2, blk>>>(nullptr, 4, fc2_w, outp, 0, GG, OUTD, HID, fc2_b, 1);
    }
    (void)n_in; (void)in_sizes; (void)out_size;
}

// round 10
// speedup vs baseline: 2.7420x; 1.0662x over previous
#include <cuda_runtime.h>
#include <cuda_bf16.h>
#include <math.h>
#include <stdint.h>

// ----------------------------------------------------------------------------
// Problem constants
// ----------------------------------------------------------------------------
#define NN     50000
#define EE     200000
#define HEADS  4
#define GG     512
#define HID    1024
#define OUTD   128
#define D1     78
#define D2     312
#define D3     1248
#define NEG    0.2f
#define K1PAD  80

// ----------------------------------------------------------------------------
// Scratch (device globals)
// ----------------------------------------------------------------------------
__device__ float g_bufA[(size_t)NN * D3];
__device__ float g_bufB[(size_t)NN * D3];
__device__ float g_xpad[(size_t)NN * K1PAD];
__device__ float g_w1pad[K1PAD * 312];
__device__ float g_asrc[(size_t)NN * HEADS];
__device__ float g_adst[(size_t)NN * HEADS];
__device__ int   g_counts[NN];
__device__ int   g_cursor[NN];
__device__ int   g_ptr[NN + 1];
__device__ int   g_csrsrc[EE];
__device__ float g_pool[GG * D3];
__device__ float g_fc1[GG * HID];

__device__ __forceinline__ float lrelu(float x) { return x > 0.f ? x : NEG * x; }

__device__ __forceinline__ const float* sel_cf(int sel, const float* ext) {
    switch (sel) {
        case 1: return g_bufA;
        case 2: return g_bufB;
        case 3: return g_pool;
        case 4: return g_fc1;
        case 5: return g_xpad;
        case 6: return g_w1pad;
        default: return ext;
    }
}
__device__ __forceinline__ float* sel_f(int sel, float* ext) {
    switch (sel) {
        case 1: return g_bufA;
        case 2: return g_bufB;
        case 3: return g_pool;
        case 4: return g_fc1;
        default: return ext;
    }
}

__device__ __forceinline__ uint32_t f2tf(float f) {
    uint32_t r;
    asm("cvt.rna.tf32.f32 %0, %1;" : "=r"(r) : "f"(f));
    return r;
}

// ----------------------------------------------------------------------------
// CSR construction (edge_index is int32)
// ----------------------------------------------------------------------------
__global__ void zero_counts_kernel() {
    int i = blockIdx.x * blockDim.x + threadIdx.x;
    if (i < NN) { g_counts[i] = 0; g_cursor[i] = 0; }
}

__global__ void zero_att_kernel() {
    int i = blockIdx.x * blockDim.x + threadIdx.x;
    if (i < NN * HEADS) { g_asrc[i] = 0.f; g_adst[i] = 0.f; }
}

__global__ void hist_kernel(const int* __restrict__ ei) {
    int e = blockIdx.x * blockDim.x + threadIdx.x;
    if (e < EE) atomicAdd(&g_counts[ei[EE + e]], 1);
}

__global__ void scan_kernel() {
    __shared__ int sh[1024];
    __shared__ int s_off;
    int tid = threadIdx.x;
    if (tid == 0) { s_off = 0; g_ptr[0] = 0; }
    __syncthreads();
    for (int base = 0; base < NN; base += 1024) {
        int v = (base + tid < NN) ? g_counts[base + tid] : 0;
        sh[tid] = v;
        __syncthreads();
        for (int s = 1; s < 1024; s <<= 1) {
            int t = (tid >= s) ? sh[tid - s] : 0;
            __syncthreads();
            sh[tid] += t;
            __syncthreads();
        }
        int off = s_off;
        if (base + tid < NN) g_ptr[base + tid + 1] = off + sh[tid];
        __syncthreads();
        if (tid == 0) s_off = off + sh[1023];
        __syncthreads();
    }
}

__global__ void csr_fill_kernel(const int* __restrict__ ei) {
    int e = blockIdx.x * blockDim.x + threadIdx.x;
    if (e < EE) {
        int r = ei[e];
        int c = ei[EE + e];
        int pos = g_ptr[c] + atomicAdd(&g_cursor[c], 1);
        g_csrsrc[pos] = r;
    }
}

// ----------------------------------------------------------------------------
// Pad kernels for layer-1 tensor GEMM
// ----------------------------------------------------------------------------
__global__ void pad_x_kernel(const float* __restrict__ x) {
    int idx = blockIdx.x * blockDim.x + threadIdx.x;
    if (idx < NN * K1PAD) {
        int n = idx / K1PAD, k = idx - n * K1PAD;
        g_xpad[idx] = (k < D1) ? x[(size_t)n * D1 + k] : 0.f;
    }
}
__global__ void pad_w1_kernel(const float* __restrict__ W1) {
    int idx = blockIdx.x * blockDim.x + threadIdx.x;
    if (idx < K1PAD * 312) {
        int k = idx / 312, n = idx - k * 312;
        g_w1pad[idx] = (k < D1) ? W1[(size_t)k * 312 + n] : 0.f;
    }
}

// ----------------------------------------------------------------------------
// TF32 tensor-core GEMM (legacy mma.sync).
// 128x128 tile, BK=32, 2-stage smem, 256 threads (8 warps: 4m x 2n).
// ATT_H > 0: fused attention-score epilogue (atomicAdd into g_asrc/g_adst).
// FUSE: bias + ReLU epilogue.
// ----------------------------------------------------------------------------
__device__ __forceinline__ void mma_tf32(float c[4], const uint32_t a[4],
                                         uint32_t b0, uint32_t b1)
{
    asm volatile(
        "mma.sync.aligned.m16n8k8.row.col.f32.tf32.tf32.f32 "
        "{%0,%1,%2,%3}, {%4,%5,%6,%7}, {%8,%9}, {%0,%1,%2,%3};"
        : "+f"(c[0]), "+f"(c[1]), "+f"(c[2]), "+f"(c[3])
        : "r"(a[0]), "r"(a[1]), "r"(a[2]), "r"(a[3]), "r"(b0), "r"(b1));
}

#define TG_LDK   136
#define TG_STAGE (32 * TG_LDK)
#define TG_SMEM_BYTES (4 * TG_STAGE * 4)

template<int ATT_H, int ATT_C, int FUSE>
__global__ void __launch_bounds__(256)
tgemm_tf32(const float* Aext, int Asel, const float* Bext, int Bsel,
           float* Cext, int Csel, int M, int N, int K,
           const float* __restrict__ att_s, const float* __restrict__ att_d,
           const float* __restrict__ bias)
{
    extern __shared__ uint32_t sm[];
    uint32_t* Asm = sm;
    uint32_t* Bsm = sm + 2 * TG_STAGE;

    const float* A = sel_cf(Asel, Aext);
    const float* B = sel_cf(Bsel, Bext);
    float* Cm = sel_f(Csel, Cext);

    int tid = threadIdx.x;
    int warpid = tid >> 5, lane = tid & 31;
    int bm = blockIdx.y * 128, bn = blockIdx.x * 128;
    int wm = (warpid >> 1) * 32;
    int wn = (warpid & 1) * 64;
    int grp = lane >> 2, tig = lane & 3;

    float cacc[2][8][4];
#pragma unroll
    for (int mf = 0; mf < 2; mf++)
#pragma unroll
        for (int nf = 0; nf < 8; nf++)
#pragma unroll
            for (int q = 0; q < 4; q++) cacc[mf][nf][q] = 0.f;

    int steps = (K + 31) >> 5;

    float4 avr[4], bvr[4];

    auto ldStage = [&](int k0) {
#pragma unroll
        for (int q = 0; q < 4; q++) {
            int flat = q * 256 + tid;
            int am  = flat >> 3;
            int akq = (flat & 7) * 4;
            int gm = bm + am, gk = k0 + akq;
            float4 v = make_float4(0.f, 0.f, 0.f, 0.f);
            if (gm < M && gk < K) v = *(const float4*)&A[(size_t)gm * K + gk];
            avr[q] = v;
        }
#pragma unroll
        for (int q = 0; q < 4; q++) {
            int flat = q * 256 + tid;
            int bk  = flat >> 5;
            int bn4 = (flat & 31) * 4;
            int gk = k0 + bk, gn = bn + bn4;
            float4 v = make_float4(0.f, 0.f, 0.f, 0.f);
            if (gk < K) {
                const float* bp = &B[(size_t)gk * N];
                if (gn + 3 < N) v = *(const float4*)&bp[gn];
                else {
                    if (gn + 0 < N) v.x = bp[gn + 0];
                    if (gn + 1 < N) v.y = bp[gn + 1];
                    if (gn + 2 < N) v.z = bp[gn + 2];
                }
            }
            bvr[q] = v;
        }
    };
    auto stStage = [&](int st) {
        uint32_t* as = Asm + st * TG_STAGE;
        uint32_t* bs = Bsm + st * TG_STAGE;
#pragma unroll
        for (int q = 0; q < 4; q++) {
            int flat = q * 256 + tid;
            int am  = flat >> 3;
            int akq = (flat & 7) * 4;
            as[(akq + 0) * TG_LDK + am] = f2tf(avr[q].x);
            as[(akq + 1) * TG_LDK + am] = f2tf(avr[q].y);
            as[(akq + 2) * TG_LDK + am] = f2tf(avr[q].z);
            as[(akq + 3) * TG_LDK + am] = f2tf(avr[q].w);
        }
#pragma unroll
        for (int q = 0; q < 4; q++) {
            int flat = q * 256 + tid;
            int bk  = flat >> 5;
            int bn4 = (flat & 31) * 4;
            uint4 u;
            u.x = f2tf(bvr[q].x); u.y = f2tf(bvr[q].y);
            u.z = f2tf(bvr[q].z); u.w = f2tf(bvr[q].w);
            *(uint4*)&bs[bk * TG_LDK + bn4] = u;
        }
    };

    ldStage(0);
    stStage(0);
    __syncthreads();

    for (int s = 0; s < steps; s++) {
        int cur = s & 1;
        bool has = (s + 1 < steps);
        if (has) ldStage((s + 1) << 5);

        const uint32_t* as = Asm + cur * TG_STAGE;
        const uint32_t* bs = Bsm + cur * TG_STAGE;
#pragma unroll
        for (int kf = 0; kf < 4; kf++) {
            int kb = kf * 8;
            uint32_t af[2][4];
#pragma unroll
            for (int mf = 0; mf < 2; mf++) {
                int m0 = wm + mf * 16;
                af[mf][0] = as[(kb + tig    ) * TG_LDK + m0 + grp    ];
                af[mf][1] = as[(kb + tig    ) * TG_LDK + m0 + grp + 8];
                af[mf][2] = as[(kb + tig + 4) * TG_LDK + m0 + grp    ];
                af[mf][3] = as[(kb + tig + 4) * TG_LDK + m0 + grp + 8];
            }
#pragma unroll
            for (int nf = 0; nf < 8; nf++) {
                int n0 = wn + nf * 8 + grp;
                uint32_t b0 = bs[(kb + tig    ) * TG_LDK + n0];
                uint32_t b1 = bs[(kb + tig + 4) * TG_LDK + n0];
                mma_tf32(cacc[0][nf], af[0], b0, b1);
                mma_tf32(cacc[1][nf], af[1], b0, b1);
            }
        }

        if (has) stStage(cur ^ 1);
        __syncthreads();
    }

    // ---- write C (optional bias+relu) ----
#pragma unroll
    for (int mf = 0; mf < 2; mf++) {
#pragma unroll
        for (int nf = 0; nf < 8; nf++) {
            int r0 = bm + wm + mf * 16 + grp;
            int c0 = bn + wn + nf * 8 + tig * 2;
            float c[4] = { cacc[mf][nf][0], cacc[mf][nf][1],
                           cacc[mf][nf][2], cacc[mf][nf][3] };
            if (FUSE) {
                float b0 = (c0     < N) ? bias[c0]     : 0.f;
                float b1 = (c0 + 1 < N) ? bias[c0 + 1] : 0.f;
                c[0] = fmaxf(c[0] + b0, 0.f);
                c[1] = fmaxf(c[1] + b1, 0.f);
                c[2] = fmaxf(c[2] + b0, 0.f);
                c[3] = fmaxf(c[3] + b1, 0.f);
            }
            if (r0 < M) {
                if (c0 + 1 < N) *(float2*)&Cm[(size_t)r0 * N + c0] = make_float2(c[0], c[1]);
                else if (c0 < N) Cm[(size_t)r0 * N + c0] = c[0];
            }
            if (r0 + 8 < M) {
                if (c0 + 1 < N) *(float2*)&Cm[(size_t)(r0 + 8) * N + c0] = make_float2(c[2], c[3]);
                else if (c0 < N) Cm[(size_t)(r0 + 8) * N + c0] = c[2];
            }
        }
    }

    // ---- fused attention scores ----
    if (ATT_H > 0) {
        int hbase = (bn + wn) / ATT_C;
        float accs[2][2][2];
        float accd[2][2][2];
#pragma unroll
        for (int mf = 0; mf < 2; mf++)
#pragma unroll
            for (int rh = 0; rh < 2; rh++)
#pragma unroll
                for (int sl = 0; sl < 2; sl++) {
                    accs[mf][rh][sl] = 0.f;
                    accd[mf][rh][sl] = 0.f;
                }
#pragma unroll
        for (int nf = 0; nf < 8; nf++) {
#pragma unroll
            for (int q = 0; q < 2; q++) {
                int col = bn + wn + nf * 8 + tig * 2 + q;
                if (col < N) {
                    float vs = att_s[col];
                    float vd = att_d[col];
                    bool s1 = (col / ATT_C) != hbase;
#pragma unroll
                    for (int mf = 0; mf < 2; mf++) {
                        float cA = cacc[mf][nf][q];
                        float cB = cacc[mf][nf][2 + q];
                        if (!s1) {
                            accs[mf][0][0] = fmaf(cA, vs, accs[mf][0][0]);
                            accs[mf][1][0] = fmaf(cB, vs, accs[mf][1][0]);
                            accd[mf][0][0] = fmaf(cA, vd, accd[mf][0][0]);
                            accd[mf][1][0] = fmaf(cB, vd, accd[mf][1][0]);
                        } else {
                            accs[mf][0][1] = fmaf(cA, vs, accs[mf][0][1]);
                            accs[mf][1][1] = fmaf(cB, vs, accs[mf][1][1]);
                            accd[mf][0][1] = fmaf(cA, vd, accd[mf][0][1]);
                            accd[mf][1][1] = fmaf(cB, vd, accd[mf][1][1]);
                        }
                    }
                }
            }
        }
#pragma unroll
        for (int off = 1; off <= 2; off <<= 1) {
#pragma unroll
            for (int mf = 0; mf < 2; mf++)
#pragma unroll
                for (int rh = 0; rh < 2; rh++)
#pragma unroll
                    for (int sl = 0; sl < 2; sl++) {
                        accs[mf][rh][sl] += __shfl_xor_sync(0xFFFFFFFFu, accs[mf][rh][sl], off);
                        accd[mf][rh][sl] += __shfl_xor_sync(0xFFFFFFFFu, accd[mf][rh][sl], off);
                    }
        }
        if (tig == 0) {
#pragma unroll
            for (int mf = 0; mf < 2; mf++)
#pragma unroll
                for (int rh = 0; rh < 2; rh++) {
                    int r = bm + wm + mf * 16 + grp + rh * 8;
                    if (r < M) {
#pragma unroll
                        for (int sl = 0; sl < 2; sl++) {
                            int h = hbase + sl;
                            if (h < ATT_H) {
                                float vs = accs[mf][rh][sl];
                                float vd = accd[mf][rh][sl];
                                if (vs != 0.f) atomicAdd(&g_asrc[r * ATT_H + h], vs);
                                if (vd != 0.f) atomicAdd(&g_adst[r * ATT_H + h], vd);
                            }
                        }
                    }
                }
        }
    }
}

// ----------------------------------------------------------------------------
// GAT aggregation: float4 gather + online softmax + edge-row prefetch.
// ----------------------------------------------------------------------------
template<int H, int C, int NV>
__global__ void __launch_bounds__(128)
gat_agg4(const float* __restrict__ bias)
{
    constexpr int HC  = H * C;
    constexpr int HC4 = HC / 4;
    constexpr int CHUNK = 64;
    int i = blockIdx.x;
    int tid = threadIdx.x;

    __shared__ float s_alpha[CHUNK][4];
    __shared__ int   s_src[CHUNK];

    const float* hbuf = g_bufB;
    float* out = g_bufA;

    float adsti[H], m[H], den[H], eself[H], aself[H];
#pragma unroll
    for (int h = 0; h < H; h++) adsti[h] = g_adst[i * H + h];
#pragma unroll
    for (int h = 0; h < H; h++) {
        eself[h] = lrelu(g_asrc[i * H + h] + adsti[h]);
        m[h] = eself[h];
        den[h] = 1.f;
    }

    int beg = g_ptr[i];
    int deg = g_ptr[i + 1] - beg;

    // single online-softmax pass (max + denom)
    for (int j = 0; j < deg; j++) {
        int s = g_csrsrc[beg + j];
#pragma unroll
        for (int h = 0; h < H; h++) {
            float e = lrelu(g_asrc[s * H + h] + adsti[h]);
            float mo = m[h];
            float mn = fmaxf(mo, e);
            den[h] = den[h] * __expf(mo - mn) + __expf(e - mn);
            m[h] = mn;
        }
    }
#pragma unroll
    for (int h = 0; h < H; h++)
        aself[h] = __expf(eself[h] - m[h]) / (den[h] + 1e-16f);

    int c4i[NV];
    bool val[NV];
    int h0[NV], h1[NV], h2[NV], h3[NV];
#pragma unroll
    for (int t = 0; t < NV; t++) {
        int c4 = tid + t * 128;
        c4i[t] = c4;
        val[t] = (c4 < HC4);
        int c = c4 * 4;
        h0[t] = min(c     / C, H - 1);
        h1[t] = min((c+1) / C, H - 1);
        h2[t] = min((c+2) / C, H - 1);
        h3[t] = min((c+3) / C, H - 1);
    }

    const float4* self4 = (const float4*)(hbuf + (size_t)i * HC);
    float4 acc[NV];
#pragma unroll
    for (int t = 0; t < NV; t++) {
        if (val[t]) {
            float4 v = self4[c4i[t]];
            acc[t].x = aself[h0[t]] * v.x;
            acc[t].y = aself[h1[t]] * v.y;
            acc[t].z = aself[h2[t]] * v.z;
            acc[t].w = aself[h3[t]] * v.w;
        } else {
            acc[t] = make_float4(0.f, 0.f, 0.f, 0.f);
        }
    }

    for (int cb = 0; cb < deg; cb += CHUNK) {
        int cn = min(CHUNK, deg - cb);
        __syncthreads();
        if (tid < cn) {
            int s = g_csrsrc[beg + cb + tid];
            s_src[tid] = s;
#pragma unroll
            for (int h = 0; h < H; h++) {
                float e = lrelu(g_asrc[s * H + h] + adsti[h]);
                s_alpha[tid][h] = __expf(e - m[h]) / (den[h] + 1e-16f);
            }
        }
        __syncthreads();

        // prefetch-pipelined edge accumulation
        float4 nxt[NV];
        {
            const float4* hr4 = (const float4*)(hbuf + (size_t)s_src[0] * HC);
#pragma unroll
            for (int t = 0; t < NV; t++)
                if (val[t]) nxt[t] = hr4[c4i[t]];
        }
        for (int j = 0; j < cn; j++) {
            float4 cur[NV];
#pragma unroll
            for (int t = 0; t < NV; t++) cur[t] = nxt[t];
            if (j + 1 < cn) {
                const float4* hn = (const float4*)(hbuf + (size_t)s_src[j + 1] * HC);
#pragma unroll
                for (int t = 0; t < NV; t++)
                    if (val[t]) nxt[t] = hn[c4i[t]];
            }
            float a0 = s_alpha[j][0];
            float a1 = (H > 1) ? s_alpha[j][1] : a0;
            float a2 = (H > 2) ? s_alpha[j][2] : a0;
            float a3 = (H > 3) ? s_alpha[j][3] : a0;
            float al[4] = { a0, a1, a2, a3 };
#pragma unroll
            for (int t = 0; t < NV; t++) {
                if (!val[t]) continue;
                acc[t].x = fmaf(al[h0[t]], cur[t].x, acc[t].x);
                acc[t].y = fmaf(al[h1[t]], cur[t].y, acc[t].y);
                acc[t].z = fmaf(al[h2[t]], cur[t].z, acc[t].z);
                acc[t].w = fmaf(al[h3[t]], cur[t].w, acc[t].w);
            }
        }
    }

    const float4* bias4 = (const float4*)bias;
    float4* out4 = (float4*)(out + (size_t)i * HC);
#pragma unroll
    for (int t = 0; t < NV; t++) {
        if (!val[t]) continue;
        float4 b = bias4[c4i[t]];
        float4 v;
        v.x = fmaxf(acc[t].x + b.x, 0.f);
        v.y = fmaxf(acc[t].y + b.y, 0.f);
        v.z = fmaxf(acc[t].z + b.z, 0.f);
        v.w = fmaxf(acc[t].w + b.w, 0.f);
        out4[c4i[t]] = v;
    }
}

// ----------------------------------------------------------------------------
// Global max pool over sorted batch (int32), float4: g_bufA -> g_pool
// ----------------------------------------------------------------------------
__global__ void pool_max(const int* __restrict__ batch)
{
    int g = blockIdx.x;
    int c4 = blockIdx.y * 128 + threadIdx.x;

    int lo = 0, hi = NN;
    while (lo < hi) { int mid = (lo + hi) >> 1; if (batch[mid] < g) lo = mid + 1; else hi = mid; }
    int start = lo;
    lo = start; hi = NN;
    while (lo < hi) { int mid = (lo + hi) >> 1; if (batch[mid] < g + 1) lo = mid + 1; else hi = mid; }
    int end = lo;

    if (c4 < D3 / 4) {
        float4 mv = make_float4(0.f, 0.f, 0.f, 0.f);
        for (int n = start; n < end; n++) {
            float4 v = *(const float4*)&g_bufA[(size_t)n * D3 + c4 * 4];
            mv.x = fmaxf(mv.x, v.x); mv.y = fmaxf(mv.y, v.y);
            mv.z = fmaxf(mv.z, v.z); mv.w = fmaxf(mv.w, v.w);
        }
        *(float4*)&g_pool[g * D3 + c4 * 4] = mv;
    }
}

// ----------------------------------------------------------------------------
// launch
// ----------------------------------------------------------------------------
extern "C" void kernel_launch(void* const* d_in, const int* in_sizes, int n_in,
                              void* d_out, int out_size)
{
    const float* x     = (const float*)d_in[0];
    const int*   ei    = (const int*)d_in[1];
    const int*   batch = (const int*)d_in[2];
    const float* W1 = (const float*)d_in[3];
    const float* as1 = (const float*)d_in[4];
    const float* ad1 = (const float*)d_in[5];
    const float* b1 = (const float*)d_in[6];
    const float* W2 = (const float*)d_in[7];
    const float* as2 = (const float*)d_in[8];
    const float* ad2 = (const float*)d_in[9];
    const float* b2 = (const float*)d_in[10];
    const float* W3 = (const float*)d_in[11];
    const float* as3 = (const float*)d_in[12];
    const float* ad3 = (const float*)d_in[13];
    const float* b3 = (const float*)d_in[14];
    const float* fc1_w = (const float*)d_in[15];
    const float* fc1_b = (const float*)d_in[16];
    const float* fc2_w = (const float*)d_in[17];
    const float* fc2_b = (const float*)d_in[18];
    float* outp = (float*)d_out;

    cudaFuncSetAttribute(tgemm_tf32<HEADS, D1, 0>,
                         cudaFuncAttributeMaxDynamicSharedMemorySize, TG_SMEM_BYTES);
    cudaFuncSetAttribute(tgemm_tf32<HEADS, D2, 0>,
                         cudaFuncAttributeMaxDynamicSharedMemorySize, TG_SMEM_BYTES);
    cudaFuncSetAttribute(tgemm_tf32<1, D3, 0>,
                         cudaFuncAttributeMaxDynamicSharedMemorySize, TG_SMEM_BYTES);
    cudaFuncSetAttribute(tgemm_tf32<0, 1, 1>,
                         cudaFuncAttributeMaxDynamicSharedMemorySize, TG_SMEM_BYTES);

    // --- CSR build + input padding + score zeroing ---
    zero_counts_kernel<<<(NN + 255) / 256, 256>>>();
    hist_kernel<<<(EE + 255) / 256, 256>>>(ei);
    scan_kernel<<<1, 1024>>>();
    csr_fill_kernel<<<(EE + 255) / 256, 256>>>(ei);
    pad_x_kernel<<<(NN * K1PAD + 255) / 256, 256>>>(x);
    pad_w1_kernel<<<(K1PAD * 312 + 255) / 256, 256>>>(W1);
    zero_att_kernel<<<(NN * HEADS + 255) / 256, 256>>>();

    dim3 blk(256);
    // --- layer 1: g_bufB = xpad @ w1pad [N,312] (K=80, tf32 + fused attn) ---
    {
        dim3 grid((312 + 127) / 128, (NN + 127) / 128);
        tgemm_tf32<HEADS, D1, 0><<<grid, blk, TG_SMEM_BYTES>>>(
            nullptr, 5, nullptr, 6, nullptr, 2, NN, 312, K1PAD, as1, ad1, nullptr);
        gat_agg4<HEADS, D1, 1><<<NN, 128>>>(b1);
    }
    // --- layer 2: g_bufB = g_bufA @ W2 [N,1248] (K=312, tf32 + fused attn) ---
    {
        zero_att_kernel<<<(NN * HEADS + 255) / 256, 256>>>();
        dim3 grid((1248 + 127) / 128, (NN + 127) / 128);
        tgemm_tf32<HEADS, D2, 0><<<grid, blk, TG_SMEM_BYTES>>>(
            nullptr, 1, W2, 0, nullptr, 2, NN, 1248, 312, as2, ad2, nullptr);
        gat_agg4<HEADS, D2, 3><<<NN, 128>>>(b2);
    }
    // --- layer 3: g_bufB = g_bufA @ W3 [N,1248] (K=1248, tf32 + fused attn) ---
    {
        zero_att_kernel<<<(NN * HEADS + 255) / 256, 256>>>();
        dim3 grid((1248 + 127) / 128, (NN + 127) / 128);
        tgemm_tf32<1, D3, 0><<<grid, blk, TG_SMEM_BYTES>>>(
            nullptr, 1, W3, 0, nullptr, 2, NN, 1248, 1248, as3, ad3, nullptr);
        gat_agg4<1, D3, 3><<<NN, 128>>>(b3);
    }
    // --- pool + FC (tf32 tensor path, fused bias+relu) ---
    {
        dim3 pg(GG, (D3 / 4 + 127) / 128);
        pool_max<<<pg, 128>>>(batch);
        dim3 g1((HID + 127) / 128, (GG + 127) / 128);
        tgemm_tf32<0, 1, 1><<<g1, blk, TG_SMEM_BYTES>>>(
            nullptr, 3, fc1_w, 0, nullptr, 4, GG, HID, D3, nullptr, nullptr, fc1_b);
        dim3 g2((OUTD + 127) / 128, (GG + 127) / 128);
        tgemm_tf32<0, 1, 1><<<g2, blk, TG_SMEM_BYTES>>>(
            nullptr, 4, fc2_w, 0, outp, 0, GG, OUTD, HID, nullptr, nullptr, fc2_b);
    }
    (void)n_in; (void)in_sizes; (void)out_size;
}

// round 11
// speedup vs baseline: 3.6804x; 1.3422x over previous
#include <cuda_runtime.h>
#include <cuda_bf16.h>
#include <math.h>
#include <stdint.h>

// ----------------------------------------------------------------------------
// Problem constants
// ----------------------------------------------------------------------------
#define NN     50000
#define EE     200000
#define HEADS  4
#define GG     512
#define HID    1024
#define OUTD   128
#define D1     78
#define D2     312
#define D3     1248
#define NEG    0.2f
#define K1PAD  80
#define NP1    320      // layer-1 GEMM N (312 feat + 8 score cols)
#define NP23   1256     // layer-2/3 GEMM N (1248 feat + 8 score cols)

// ----------------------------------------------------------------------------
// Scratch (device globals; zero-initialized once at module load)
// ----------------------------------------------------------------------------
__device__ float g_bufA[(size_t)NN * D3];        // gat_agg output (tf32-rounded)
__device__ float g_bufB[(size_t)NN * NP23];      // GEMM output (feat + scores)
__device__ float g_xpad[(size_t)NN * K1PAD];     // padded x (tf32-rounded)
__device__ float g_w1r[K1PAD * NP1];             // rounded W1 + score cols
__device__ float g_w2r[D2 * NP23];
__device__ float g_w3r[(size_t)D3 * NP23];
__device__ float g_fc1r[(size_t)D3 * HID];
__device__ float g_fc2r[HID * OUTD];
__device__ int   g_counts[NN];
__device__ int   g_cursor[NN];
__device__ int   g_ptr[NN + 1];
__device__ int   g_csrsrc[EE];
__device__ float g_pool[GG * D3];
__device__ float g_fc1[GG * HID];

__device__ __forceinline__ float lrelu(float x) { return x > 0.f ? x : NEG * x; }

__device__ __forceinline__ uint32_t f2tf(float f) {
    uint32_t r;
    asm("cvt.rna.tf32.f32 %0, %1;" : "=r"(r) : "f"(f));
    return r;
}
__device__ __forceinline__ float tf32r(float f) { return __uint_as_float(f2tf(f)); }

__device__ __forceinline__ const float* sel_cf(int sel, const float* ext) {
    switch (sel) {
        case 1:  return g_bufA;
        case 2:  return g_bufB;
        case 3:  return g_pool;
        case 4:  return g_fc1;
        case 5:  return g_xpad;
        case 7:  return g_w1r;
        case 8:  return g_w2r;
        case 9:  return g_w3r;
        case 10: return g_fc1r;
        case 11: return g_fc2r;
        default: return ext;
    }
}
__device__ __forceinline__ float* sel_f(int sel, float* ext) {
    switch (sel) {
        case 1:  return g_bufA;
        case 2:  return g_bufB;
        case 3:  return g_pool;
        case 4:  return g_fc1;
        case 7:  return g_w1r;
        case 8:  return g_w2r;
        case 9:  return g_w3r;
        case 10: return g_fc1r;
        case 11: return g_fc2r;
        default: return ext;
    }
}

// ----------------------------------------------------------------------------
// CSR construction (edge_index is int32)
// ----------------------------------------------------------------------------
__global__ void zero_counts_kernel() {
    int i = blockIdx.x * blockDim.x + threadIdx.x;
    if (i < NN) { g_counts[i] = 0; g_cursor[i] = 0; }
}

__global__ void hist_kernel(const int* __restrict__ ei) {
    int e = blockIdx.x * blockDim.x + threadIdx.x;
    if (e < EE) atomicAdd(&g_counts[ei[EE + e]], 1);
}

__global__ void scan_kernel() {
    __shared__ int sh[1024];
    __shared__ int s_off;
    int tid = threadIdx.x;
    if (tid == 0) { s_off = 0; g_ptr[0] = 0; }
    __syncthreads();
    for (int base = 0; base < NN; base += 1024) {
        int v = (base + tid < NN) ? g_counts[base + tid] : 0;
        sh[tid] = v;
        __syncthreads();
        for (int s = 1; s < 1024; s <<= 1) {
            int t = (tid >= s) ? sh[tid - s] : 0;
            __syncthreads();
            sh[tid] += t;
            __syncthreads();
        }
        int off = s_off;
        if (base + tid < NN) g_ptr[base + tid + 1] = off + sh[tid];
        __syncthreads();
        if (tid == 0) s_off = off + sh[1023];
        __syncthreads();
    }
}

__global__ void csr_fill_kernel(const int* __restrict__ ei) {
    int e = blockIdx.x * blockDim.x + threadIdx.x;
    if (e < EE) {
        int r = ei[e];
        int c = ei[EE + e];
        int pos = g_ptr[c] + atomicAdd(&g_cursor[c], 1);
        g_csrsrc[pos] = r;
    }
}

// ----------------------------------------------------------------------------
// Operand preparation: pad x, round-copy weights, pre-contracted score cols
// ----------------------------------------------------------------------------
__global__ void pad_x_kernel(const float* __restrict__ x) {
    int idx = blockIdx.x * blockDim.x + threadIdx.x;
    if (idx < NN * K1PAD) {
        int n = idx / K1PAD, k = idx - n * K1PAD;
        g_xpad[idx] = (k < D1) ? tf32r(x[(size_t)n * D1 + k]) : 0.f;
    }
}

// dst[k*NP + n] = round(W[k*N + n])
__global__ void round_copy_kernel(const float* __restrict__ W,
                                  int K, int N, int NP, int dsel) {
    float* dst = sel_f(dsel, nullptr);
    int idx = blockIdx.x * blockDim.x + threadIdx.x;
    if (idx < K * N) {
        int k = idx / N, n = idx - k * N;
        dst[(size_t)k * NP + n] = tf32r(W[idx]);
    }
}

// score cols: dst[k*NP + N + slot], slot 0..3 = src heads, 4..7 = dst heads
__global__ void ws_fill_kernel(const float* __restrict__ W,
                               const float* __restrict__ att_s,
                               const float* __restrict__ att_d,
                               int K, int C, int H, int N, int NP, int dsel) {
    float* dst = sel_f(dsel, nullptr);
    int t = blockIdx.x * blockDim.x + threadIdx.x;
    if (t >= K * 8) return;
    int k = t >> 3, slot = t & 7;
    int h = slot & 3;
    const float* att = (slot >= 4) ? att_d : att_s;
    float v = 0.f;
    if (h < H) {
        const float* wr = W + (size_t)k * N + h * C;
        const float* ar = att + h * C;
        for (int c = 0; c < C; c++) v = fmaf(wr[c], ar[c], v);
    }
    dst[(size_t)k * NP + N + slot] = tf32r(v);
}

// ----------------------------------------------------------------------------
// TF32 tensor-core GEMM with cp.async 3-stage pipeline.
// All operands pre-rounded to tf32 in gmem. 128x128 tile, BK=32, 256 threads
// (8 warps: 4m x 2n, warp tile 32x64). A smem [m][36], B smem [k][136].
// FUSE: bias+ReLU epilogue. ROUND: round outputs to tf32.
// ----------------------------------------------------------------------------
__device__ __forceinline__ void mma_tf32(float c[4], const uint32_t a[4],
                                         uint32_t b0, uint32_t b1)
{
    asm volatile(
        "mma.sync.aligned.m16n8k8.row.col.f32.tf32.tf32.f32 "
        "{%0,%1,%2,%3}, {%4,%5,%6,%7}, {%8,%9}, {%0,%1,%2,%3};"
        : "+f"(c[0]), "+f"(c[1]), "+f"(c[2]), "+f"(c[3])
        : "r"(a[0]), "r"(a[1]), "r"(a[2]), "r"(a[3]), "r"(b0), "r"(b1));
}

#define CA_AP    36
#define CA_ASZ   (128 * CA_AP)          // 4608 words
#define CA_BP    136
#define CA_BSZ   (32 * CA_BP)           // 4352 words
#define CA_STW   (CA_ASZ + CA_BSZ)      // 8960 words per stage
#define CA_SMEM_BYTES (3 * CA_STW * 4)  // 107520 bytes

template<int FUSE, int ROUND>
__global__ void __launch_bounds__(256)
tgemm_ca(const float* Aext, int Asel, int Bsel,
         float* Cext, int Csel, int M, int N, int K,
         const float* __restrict__ bias)
{
    extern __shared__ float smf[];
    uint32_t sb = (uint32_t)__cvta_generic_to_shared(smf);

    const float* A = sel_cf(Asel, Aext);
    const float* B = sel_cf(Bsel, nullptr);
    float* Cm = sel_f(Csel, Cext);

    int tid = threadIdx.x;
    int warpid = tid >> 5, lane = tid & 31;
    int bm = blockIdx.y * 128, bn = blockIdx.x * 128;
    int wm = (warpid >> 1) * 32;
    int wn = (warpid & 1) * 64;
    int grp = lane >> 2, tig = lane & 3;

    float cacc[2][8][4];
#pragma unroll
    for (int mf = 0; mf < 2; mf++)
#pragma unroll
        for (int nf = 0; nf < 8; nf++)
#pragma unroll
            for (int q = 0; q < 4; q++) cacc[mf][nf][q] = 0.f;

    int steps = (K + 31) >> 5;

    auto issue = [&](int st, int k0) {
        uint32_t abase = sb + (uint32_t)(st * CA_STW) * 4;
        uint32_t bbase = abase + CA_ASZ * 4;
#pragma unroll
        for (int q = 0; q < 4; q++) {
            int flat = q * 256 + tid;
            int am = flat >> 3, ak4 = (flat & 7) * 4;
            int gm = bm + am, gk = k0 + ak4;
            bool p = (gm < M) && (gk < K);
            const float* src = p ? (A + (size_t)gm * K + gk) : A;
            uint32_t dst = abase + (uint32_t)(am * CA_AP + ak4) * 4;
            uint32_t sz = p ? 16u : 0u;
            asm volatile("cp.async.cg.shared.global [%0], [%1], 16, %2;"
                         :: "r"(dst), "l"(src), "r"(sz));
        }
#pragma unroll
        for (int q = 0; q < 4; q++) {
            int flat = q * 256 + tid;
            int bk = flat >> 5, n4 = (flat & 31) * 4;
            int gk = k0 + bk, gn = bn + n4;
            bool p = (gk < K) && (gn < N);
            const float* src = p ? (B + (size_t)gk * N + gn) : B;
            uint32_t dst = bbase + (uint32_t)(bk * CA_BP + n4) * 4;
            uint32_t sz = p ? 16u : 0u;
            asm volatile("cp.async.cg.shared.global [%0], [%1], 16, %2;"
                         :: "r"(dst), "l"(src), "r"(sz));
        }
        asm volatile("cp.async.commit_group;");
    };

    issue(0, 0);
    if (steps > 1) issue(1, 32);

    for (int s = 0; s < steps; s++) {
        int buf = s % 3;
        if (s + 1 < steps) asm volatile("cp.async.wait_group 1;");
        else               asm volatile("cp.async.wait_group 0;");
        __syncthreads();
        if (s + 2 < steps) issue((s + 2) % 3, (s + 2) << 5);

        const uint32_t* as = (const uint32_t*)(smf + buf * CA_STW);
        const uint32_t* bs = as + CA_ASZ;
#pragma unroll
        for (int kf = 0; kf < 4; kf++) {
            int kb = kf * 8;
            uint32_t af[2][4];
#pragma unroll
            for (int mf = 0; mf < 2; mf++) {
                int m0 = wm + mf * 16;
                af[mf][0] = as[(m0 + grp    ) * CA_AP + kb + tig    ];
                af[mf][1] = as[(m0 + grp + 8) * CA_AP + kb + tig    ];
                af[mf][2] = as[(m0 + grp    ) * CA_AP + kb + tig + 4];
                af[mf][3] = as[(m0 + grp + 8) * CA_AP + kb + tig + 4];
            }
#pragma unroll
            for (int nf = 0; nf < 8; nf++) {
                int n0 = wn + nf * 8 + grp;
                uint32_t b0 = bs[(kb + tig    ) * CA_BP + n0];
                uint32_t b1 = bs[(kb + tig + 4) * CA_BP + n0];
                mma_tf32(cacc[0][nf], af[0], b0, b1);
                mma_tf32(cacc[1][nf], af[1], b0, b1);
            }
        }
    }

    // epilogue
#pragma unroll
    for (int mf = 0; mf < 2; mf++) {
#pragma unroll
        for (int nf = 0; nf < 8; nf++) {
            int r0 = bm + wm + mf * 16 + grp;
            int c0 = bn + wn + nf * 8 + tig * 2;
            float c[4] = { cacc[mf][nf][0], cacc[mf][nf][1],
                           cacc[mf][nf][2], cacc[mf][nf][3] };
            if (FUSE) {
                float b0 = (c0     < N) ? bias[c0]     : 0.f;
                float b1 = (c0 + 1 < N) ? bias[c0 + 1] : 0.f;
                c[0] = fmaxf(c[0] + b0, 0.f);
                c[1] = fmaxf(c[1] + b1, 0.f);
                c[2] = fmaxf(c[2] + b0, 0.f);
                c[3] = fmaxf(c[3] + b1, 0.f);
            }
            if (ROUND) {
                c[0] = tf32r(c[0]); c[1] = tf32r(c[1]);
                c[2] = tf32r(c[2]); c[3] = tf32r(c[3]);
            }
            if (r0 < M) {
                if (c0 + 1 < N) *(float2*)&Cm[(size_t)r0 * N + c0] = make_float2(c[0], c[1]);
                else if (c0 < N) Cm[(size_t)r0 * N + c0] = c[0];
            }
            if (r0 + 8 < M) {
                if (c0 + 1 < N) *(float2*)&Cm[(size_t)(r0 + 8) * N + c0] = make_float2(c[2], c[3]);
                else if (c0 < N) Cm[(size_t)(r0 + 8) * N + c0] = c[2];
            }
        }
    }
}

// ----------------------------------------------------------------------------
// GAT aggregation: scores read from GEMM output columns [HC..HC+8).
// float4 gather + online softmax + edge-row prefetch. Output tf32-rounded.
// ----------------------------------------------------------------------------
template<int H, int C, int NP, int NV>
__global__ void __launch_bounds__(128)
gat_agg4(const float* __restrict__ bias)
{
    constexpr int HC  = H * C;
    constexpr int HC4 = HC / 4;
    constexpr int CHUNK = 64;
    int i = blockIdx.x;
    int tid = threadIdx.x;

    __shared__ float s_alpha[CHUNK][4];
    __shared__ int   s_src[CHUNK];

    const float* hbuf = g_bufB;
    float* out = g_bufA;
    const float* row = hbuf + (size_t)i * NP;

    float scS[4], scD[4];
    *(float4*)scS = *(const float4*)&row[HC];
    *(float4*)scD = *(const float4*)&row[HC + 4];

    float adsti[H], m[H], den[H], eself[H], aself[H];
#pragma unroll
    for (int h = 0; h < H; h++) {
        adsti[h] = scD[h];
        eself[h] = lrelu(scS[h] + adsti[h]);
        m[h] = eself[h];
        den[h] = 1.f;
    }

    int beg = g_ptr[i];
    int deg = g_ptr[i + 1] - beg;

    // online softmax over incoming edges
    for (int j = 0; j < deg; j++) {
        int s = g_csrsrc[beg + j];
        float es[4];
        *(float4*)es = *(const float4*)&hbuf[(size_t)s * NP + HC];
#pragma unroll
        for (int h = 0; h < H; h++) {
            float e = lrelu(es[h] + adsti[h]);
            float mo = m[h];
            float mn = fmaxf(mo, e);
            den[h] = den[h] * __expf(mo - mn) + __expf(e - mn);
            m[h] = mn;
        }
    }
#pragma unroll
    for (int h = 0; h < H; h++)
        aself[h] = __expf(eself[h] - m[h]) / (den[h] + 1e-16f);

    int c4i[NV];
    bool val[NV];
    int h0[NV], h1[NV], h2[NV], h3[NV];
#pragma unroll
    for (int t = 0; t < NV; t++) {
        int c4 = tid + t * 128;
        c4i[t] = c4;
        val[t] = (c4 < HC4);
        int c = c4 * 4;
        h0[t] = min(c     / C, H - 1);
        h1[t] = min((c+1) / C, H - 1);
        h2[t] = min((c+2) / C, H - 1);
        h3[t] = min((c+3) / C, H - 1);
    }

    const float4* self4 = (const float4*)row;
    float4 acc[NV];
#pragma unroll
    for (int t = 0; t < NV; t++) {
        if (val[t]) {
            float4 v = self4[c4i[t]];
            acc[t].x = aself[h0[t]] * v.x;
            acc[t].y = aself[h1[t]] * v.y;
            acc[t].z = aself[h2[t]] * v.z;
            acc[t].w = aself[h3[t]] * v.w;
        } else {
            acc[t] = make_float4(0.f, 0.f, 0.f, 0.f);
        }
    }

    for (int cb = 0; cb < deg; cb += CHUNK) {
        int cn = min(CHUNK, deg - cb);
        __syncthreads();
        if (tid < cn) {
            int s = g_csrsrc[beg + cb + tid];
            s_src[tid] = s;
            float es[4];
            *(float4*)es = *(const float4*)&hbuf[(size_t)s * NP + HC];
#pragma unroll
            for (int h = 0; h < H; h++) {
                float e = lrelu(es[h] + adsti[h]);
                s_alpha[tid][h] = __expf(e - m[h]) / (den[h] + 1e-16f);
            }
        }
        __syncthreads();

        float4 nxt[NV];
        {
            const float4* hr4 = (const float4*)(hbuf + (size_t)s_src[0] * NP);
#pragma unroll
            for (int t = 0; t < NV; t++)
                if (val[t]) nxt[t] = hr4[c4i[t]];
        }
        for (int j = 0; j < cn; j++) {
            float4 cur[NV];
#pragma unroll
            for (int t = 0; t < NV; t++) cur[t] = nxt[t];
            if (j + 1 < cn) {
                const float4* hn = (const float4*)(hbuf + (size_t)s_src[j + 1] * NP);
#pragma unroll
                for (int t = 0; t < NV; t++)
                    if (val[t]) nxt[t] = hn[c4i[t]];
            }
            float a0 = s_alpha[j][0];
            float a1 = (H > 1) ? s_alpha[j][1] : a0;
            float a2 = (H > 2) ? s_alpha[j][2] : a0;
            float a3 = (H > 3) ? s_alpha[j][3] : a0;
            float al[4] = { a0, a1, a2, a3 };
#pragma unroll
            for (int t = 0; t < NV; t++) {
                if (!val[t]) continue;
                acc[t].x = fmaf(al[h0[t]], cur[t].x, acc[t].x);
                acc[t].y = fmaf(al[h1[t]], cur[t].y, acc[t].y);
                acc[t].z = fmaf(al[h2[t]], cur[t].z, acc[t].z);
                acc[t].w = fmaf(al[h3[t]], cur[t].w, acc[t].w);
            }
        }
    }

    const float4* bias4 = (const float4*)bias;
    float4* out4 = (float4*)(out + (size_t)i * HC);
#pragma unroll
    for (int t = 0; t < NV; t++) {
        if (!val[t]) continue;
        float4 b = bias4[c4i[t]];
        float4 v;
        v.x = tf32r(fmaxf(acc[t].x + b.x, 0.f));
        v.y = tf32r(fmaxf(acc[t].y + b.y, 0.f));
        v.z = tf32r(fmaxf(acc[t].z + b.z, 0.f));
        v.w = tf32r(fmaxf(acc[t].w + b.w, 0.f));
        out4[c4i[t]] = v;
    }
}

// ----------------------------------------------------------------------------
// Global max pool over sorted batch (int32), float4, tf32-rounded output
// ----------------------------------------------------------------------------
__global__ void pool_max(const int* __restrict__ batch)
{
    int g = blockIdx.x;
    int c4 = blockIdx.y * 128 + threadIdx.x;

    int lo = 0, hi = NN;
    while (lo < hi) { int mid = (lo + hi) >> 1; if (batch[mid] < g) lo = mid + 1; else hi = mid; }
    int start = lo;
    lo = start; hi = NN;
    while (lo < hi) { int mid = (lo + hi) >> 1; if (batch[mid] < g + 1) lo = mid + 1; else hi = mid; }
    int end = lo;

    if (c4 < D3 / 4) {
        float4 mv = make_float4(0.f, 0.f, 0.f, 0.f);
        for (int n = start; n < end; n++) {
            float4 v = *(const float4*)&g_bufA[(size_t)n * D3 + c4 * 4];
            mv.x = fmaxf(mv.x, v.x); mv.y = fmaxf(mv.y, v.y);
            mv.z = fmaxf(mv.z, v.z); mv.w = fmaxf(mv.w, v.w);
        }
        mv.x = tf32r(mv.x); mv.y = tf32r(mv.y);
        mv.z = tf32r(mv.z); mv.w = tf32r(mv.w);
        *(float4*)&g_pool[g * D3 + c4 * 4] = mv;
    }
}

// ----------------------------------------------------------------------------
// launch
// ----------------------------------------------------------------------------
extern "C" void kernel_launch(void* const* d_in, const int* in_sizes, int n_in,
                              void* d_out, int out_size)
{
    const float* x     = (const float*)d_in[0];
    const int*   ei    = (const int*)d_in[1];
    const int*   batch = (const int*)d_in[2];
    const float* W1 = (const float*)d_in[3];
    const float* as1 = (const float*)d_in[4];
    const float* ad1 = (const float*)d_in[5];
    const float* b1 = (const float*)d_in[6];
    const float* W2 = (const float*)d_in[7];
    const float* as2 = (const float*)d_in[8];
    const float* ad2 = (const float*)d_in[9];
    const float* b2 = (const float*)d_in[10];
    const float* W3 = (const float*)d_in[11];
    const float* as3 = (const float*)d_in[12];
    const float* ad3 = (const float*)d_in[13];
    const float* b3 = (const float*)d_in[14];
    const float* fc1_w = (const float*)d_in[15];
    const float* fc1_b = (const float*)d_in[16];
    const float* fc2_w = (const float*)d_in[17];
    const float* fc2_b = (const float*)d_in[18];
    float* outp = (float*)d_out;

    cudaFuncSetAttribute(tgemm_ca<0, 0>,
                         cudaFuncAttributeMaxDynamicSharedMemorySize, CA_SMEM_BYTES);
    cudaFuncSetAttribute(tgemm_ca<1, 1>,
                         cudaFuncAttributeMaxDynamicSharedMemorySize, CA_SMEM_BYTES);
    cudaFuncSetAttribute(tgemm_ca<1, 0>,
                         cudaFuncAttributeMaxDynamicSharedMemorySize, CA_SMEM_BYTES);

    // --- CSR build + operand prep ---
    zero_counts_kernel<<<(NN + 255) / 256, 256>>>();
    hist_kernel<<<(EE + 255) / 256, 256>>>(ei);
    scan_kernel<<<1, 1024>>>();
    csr_fill_kernel<<<(EE + 255) / 256, 256>>>(ei);
    pad_x_kernel<<<(NN * K1PAD + 255) / 256, 256>>>(x);
    round_copy_kernel<<<(D1 * 312 + 255) / 256, 256>>>(W1, D1, 312, NP1, 7);
    ws_fill_kernel<<<(D1 * 8 + 255) / 256, 256>>>(W1, as1, ad1, D1, D1, HEADS, 312, NP1, 7);
    round_copy_kernel<<<(D2 * D3 + 255) / 256, 256>>>(W2, D2, D3, NP23, 8);
    ws_fill_kernel<<<(D2 * 8 + 255) / 256, 256>>>(W2, as2, ad2, D2, D2, HEADS, D3, NP23, 8);
    round_copy_kernel<<<(D3 * D3 + 255) / 256, 256>>>(W3, D3, D3, NP23, 9);
    ws_fill_kernel<<<(D3 * 8 + 255) / 256, 256>>>(W3, as3, ad3, D3, D3, 1, D3, NP23, 9);
    round_copy_kernel<<<(D3 * HID + 255) / 256, 256>>>(fc1_w, D3, HID, HID, 10);
    round_copy_kernel<<<(HID * OUTD + 255) / 256, 256>>>(fc2_w, HID, OUTD, OUTD, 11);

    dim3 blk(256);
    // --- layer 1: bufB[N,320] = xpad @ w1r  (K=80) ---
    {
        dim3 grid((NP1 + 127) / 128, (NN + 127) / 128);
        tgemm_ca<0, 0><<<grid, blk, CA_SMEM_BYTES>>>(
            nullptr, 5, 7, nullptr, 2, NN, NP1, K1PAD, nullptr);
        gat_agg4<HEADS, D1, NP1, 1><<<NN, 128>>>(b1);
    }
    // --- layer 2: bufB[N,1256] = bufA @ w2r  (K=312) ---
    {
        dim3 grid((NP23 + 127) / 128, (NN + 127) / 128);
        tgemm_ca<0, 0><<<grid, blk, CA_SMEM_BYTES>>>(
            nullptr, 1, 8, nullptr, 2, NN, NP23, D2, nullptr);
        gat_agg4<HEADS, D2, NP23, 3><<<NN, 128>>>(b2);
    }
    // --- layer 3: bufB[N,1256] = bufA @ w3r  (K=1248) ---
    {
        dim3 grid((NP23 + 127) / 128, (NN + 127) / 128);
        tgemm_ca<0, 0><<<grid, blk, CA_SMEM_BYTES>>>(
            nullptr, 1, 9, nullptr, 2, NN, NP23, D3, nullptr);
        gat_agg4<1, D3, NP23, 3><<<NN, 128>>>(b3);
    }
    // --- pool + FC (tensor path, fused bias+relu) ---
    {
        dim3 pg(GG, (D3 / 4 + 127) / 128);
        pool_max<<<pg, 128>>>(batch);
        dim3 g1((HID + 127) / 128, (GG + 127) / 128);
        tgemm_ca<1, 1><<<g1, blk, CA_SMEM_BYTES>>>(
            nullptr, 3, 10, nullptr, 4, GG, HID, D3, fc1_b);
        dim3 g2((OUTD + 127) / 128, (GG + 127) / 128);
        tgemm_ca<1, 0><<<g2, blk, CA_SMEM_BYTES>>>(
            nullptr, 4, 11, outp, 0, GG, OUTD, HID, fc2_b);
    }
    (void)n_in; (void)in_sizes; (void)out_size;
}

// round 12
// speedup vs baseline: 3.6902x; 1.0027x over previous
#include <cuda_runtime.h>
#include <cuda_bf16.h>
#include <math.h>
#include <stdint.h>

// ----------------------------------------------------------------------------
// Problem constants
// ----------------------------------------------------------------------------
#define NN     50000
#define EE     200000
#define HEADS  4
#define GG     512
#define HID    1024
#define OUTD   128
#define D1     78
#define D2     312
#define D3     1248
#define NEG    0.2f
#define K1PAD  80
#define NP1    320      // layer-1 GEMM N (312 feat + 8 score cols)
#define NP23   1256     // layer-2/3 GEMM N (1248 feat + 8 score cols)

// ----------------------------------------------------------------------------
// Scratch (device globals)
// ----------------------------------------------------------------------------
__device__ float g_bufA[(size_t)NN * D3];
__device__ float g_bufB[(size_t)NN * NP23];
__device__ float g_xpad[(size_t)NN * K1PAD];
__device__ float g_w1r[K1PAD * NP1];
__device__ float g_w2r[D2 * NP23];
__device__ float g_w3r[(size_t)D3 * NP23];
__device__ float g_fc1r[(size_t)D3 * HID];
__device__ float g_fc2r[HID * OUTD];
__device__ int   g_counts[NN];
__device__ int   g_cursor[NN];
__device__ int   g_ptr[NN + 1];
__device__ int   g_csrsrc[EE];
__device__ float g_pool[GG * D3];
__device__ float g_fc1[GG * HID];

__device__ __forceinline__ float lrelu(float x) { return x > 0.f ? x : NEG * x; }

__device__ __forceinline__ uint32_t f2tf(float f) {
    uint32_t r;
    asm("cvt.rna.tf32.f32 %0, %1;" : "=r"(r) : "f"(f));
    return r;
}
__device__ __forceinline__ float tf32r(float f) { return __uint_as_float(f2tf(f)); }

__device__ __forceinline__ const float* sel_cf(int sel, const float* ext) {
    switch (sel) {
        case 1:  return g_bufA;
        case 2:  return g_bufB;
        case 3:  return g_pool;
        case 4:  return g_fc1;
        case 5:  return g_xpad;
        case 7:  return g_w1r;
        case 8:  return g_w2r;
        case 9:  return g_w3r;
        case 10: return g_fc1r;
        case 11: return g_fc2r;
        default: return ext;
    }
}
__device__ __forceinline__ float* sel_f(int sel, float* ext) {
    switch (sel) {
        case 1:  return g_bufA;
        case 2:  return g_bufB;
        case 3:  return g_pool;
        case 4:  return g_fc1;
        case 7:  return g_w1r;
        case 8:  return g_w2r;
        case 9:  return g_w3r;
        case 10: return g_fc1r;
        case 11: return g_fc2r;
        default: return ext;
    }
}

// ----------------------------------------------------------------------------
// CSR construction (edge_index is int32)
// ----------------------------------------------------------------------------
__global__ void zero_counts_kernel() {
    int i = blockIdx.x * blockDim.x + threadIdx.x;
    if (i < NN) { g_counts[i] = 0; g_cursor[i] = 0; }
}

__global__ void hist_kernel(const int* __restrict__ ei) {
    int e = blockIdx.x * blockDim.x + threadIdx.x;
    if (e < EE) atomicAdd(&g_counts[ei[EE + e]], 1);
}

__global__ void scan_kernel() {
    __shared__ int sh[1024];
    __shared__ int s_off;
    int tid = threadIdx.x;
    if (tid == 0) { s_off = 0; g_ptr[0] = 0; }
    __syncthreads();
    for (int base = 0; base < NN; base += 1024) {
        int v = (base + tid < NN) ? g_counts[base + tid] : 0;
        sh[tid] = v;
        __syncthreads();
        for (int s = 1; s < 1024; s <<= 1) {
            int t = (tid >= s) ? sh[tid - s] : 0;
            __syncthreads();
            sh[tid] += t;
            __syncthreads();
        }
        int off = s_off;
        if (base + tid < NN) g_ptr[base + tid + 1] = off + sh[tid];
        __syncthreads();
        if (tid == 0) s_off = off + sh[1023];
        __syncthreads();
    }
}

__global__ void csr_fill_kernel(const int* __restrict__ ei) {
    int e = blockIdx.x * blockDim.x + threadIdx.x;
    if (e < EE) {
        int r = ei[e];
        int c = ei[EE + e];
        int pos = g_ptr[c] + atomicAdd(&g_cursor[c], 1);
        g_csrsrc[pos] = r;
    }
}

// ----------------------------------------------------------------------------
// Operand preparation
// ----------------------------------------------------------------------------
__global__ void pad_x_kernel(const float* __restrict__ x) {
    int idx = blockIdx.x * blockDim.x + threadIdx.x;
    if (idx < NN * K1PAD) {
        int n = idx / K1PAD, k = idx - n * K1PAD;
        g_xpad[idx] = (k < D1) ? tf32r(x[(size_t)n * D1 + k]) : 0.f;
    }
}

__global__ void round_copy_kernel(const float* __restrict__ W,
                                  int K, int N, int NP, int dsel) {
    float* dst = sel_f(dsel, nullptr);
    int idx = blockIdx.x * blockDim.x + threadIdx.x;
    if (idx < K * N) {
        int k = idx / N, n = idx - k * N;
        dst[(size_t)k * NP + n] = tf32r(W[idx]);
    }
}

__global__ void ws_fill_kernel(const float* __restrict__ W,
                               const float* __restrict__ att_s,
                               const float* __restrict__ att_d,
                               int K, int C, int H, int N, int NP, int dsel) {
    float* dst = sel_f(dsel, nullptr);
    int t = blockIdx.x * blockDim.x + threadIdx.x;
    if (t >= K * 8) return;
    int k = t >> 3, slot = t & 7;
    int h = slot & 3;
    const float* att = (slot >= 4) ? att_d : att_s;
    float v = 0.f;
    if (h < H) {
        const float* wr = W + (size_t)k * N + h * C;
        const float* ar = att + h * C;
        for (int c = 0; c < C; c++) v = fmaf(wr[c], ar[c], v);
    }
    dst[(size_t)k * NP + N + slot] = tf32r(v);
}

// ----------------------------------------------------------------------------
// TF32 tensor-core GEMM with cp.async 3-stage pipeline.
// ----------------------------------------------------------------------------
__device__ __forceinline__ void mma_tf32(float c[4], const uint32_t a[4],
                                         uint32_t b0, uint32_t b1)
{
    asm volatile(
        "mma.sync.aligned.m16n8k8.row.col.f32.tf32.tf32.f32 "
        "{%0,%1,%2,%3}, {%4,%5,%6,%7}, {%8,%9}, {%0,%1,%2,%3};"
        : "+f"(c[0]), "+f"(c[1]), "+f"(c[2]), "+f"(c[3])
        : "r"(a[0]), "r"(a[1]), "r"(a[2]), "r"(a[3]), "r"(b0), "r"(b1));
}

#define CA_AP    36
#define CA_ASZ   (128 * CA_AP)
#define CA_BP    136
#define CA_BSZ   (32 * CA_BP)
#define CA_STW   (CA_ASZ + CA_BSZ)
#define CA_SMEM_BYTES (3 * CA_STW * 4)

template<int FUSE, int ROUND>
__global__ void __launch_bounds__(256)
tgemm_ca(const float* Aext, int Asel, int Bsel,
         float* Cext, int Csel, int M, int N, int K,
         const float* __restrict__ bias)
{
    extern __shared__ float smf[];
    uint32_t sb = (uint32_t)__cvta_generic_to_shared(smf);

    const float* A = sel_cf(Asel, Aext);
    const float* B = sel_cf(Bsel, nullptr);
    float* Cm = sel_f(Csel, Cext);

    int tid = threadIdx.x;
    int warpid = tid >> 5, lane = tid & 31;
    int bm = blockIdx.y * 128, bn = blockIdx.x * 128;
    int wm = (warpid >> 1) * 32;
    int wn = (warpid & 1) * 64;
    int grp = lane >> 2, tig = lane & 3;

    float cacc[2][8][4];
#pragma unroll
    for (int mf = 0; mf < 2; mf++)
#pragma unroll
        for (int nf = 0; nf < 8; nf++)
#pragma unroll
            for (int q = 0; q < 4; q++) cacc[mf][nf][q] = 0.f;

    int steps = (K + 31) >> 5;

    auto issue = [&](int st, int k0) {
        uint32_t abase = sb + (uint32_t)(st * CA_STW) * 4;
        uint32_t bbase = abase + CA_ASZ * 4;
#pragma unroll
        for (int q = 0; q < 4; q++) {
            int flat = q * 256 + tid;
            int am = flat >> 3, ak4 = (flat & 7) * 4;
            int gm = bm + am, gk = k0 + ak4;
            bool p = (gm < M) && (gk < K);
            const float* src = p ? (A + (size_t)gm * K + gk) : A;
            uint32_t dst = abase + (uint32_t)(am * CA_AP + ak4) * 4;
            uint32_t sz = p ? 16u : 0u;
            asm volatile("cp.async.cg.shared.global [%0], [%1], 16, %2;"
                         :: "r"(dst), "l"(src), "r"(sz));
        }
#pragma unroll
        for (int q = 0; q < 4; q++) {
            int flat = q * 256 + tid;
            int bk = flat >> 5, n4 = (flat & 31) * 4;
            int gk = k0 + bk, gn = bn + n4;
            bool p = (gk < K) && (gn < N);
            const float* src = p ? (B + (size_t)gk * N + gn) : B;
            uint32_t dst = bbase + (uint32_t)(bk * CA_BP + n4) * 4;
            uint32_t sz = p ? 16u : 0u;
            asm volatile("cp.async.cg.shared.global [%0], [%1], 16, %2;"
                         :: "r"(dst), "l"(src), "r"(sz));
        }
        asm volatile("cp.async.commit_group;");
    };

    issue(0, 0);
    if (steps > 1) issue(1, 32);

    for (int s = 0; s < steps; s++) {
        int buf = s % 3;
        if (s + 1 < steps) asm volatile("cp.async.wait_group 1;");
        else               asm volatile("cp.async.wait_group 0;");
        __syncthreads();
        if (s + 2 < steps) issue((s + 2) % 3, (s + 2) << 5);

        const uint32_t* as = (const uint32_t*)(smf + buf * CA_STW);
        const uint32_t* bs = as + CA_ASZ;
#pragma unroll
        for (int kf = 0; kf < 4; kf++) {
            int kb = kf * 8;
            uint32_t af[2][4];
#pragma unroll
            for (int mf = 0; mf < 2; mf++) {
                int m0 = wm + mf * 16;
                af[mf][0] = as[(m0 + grp    ) * CA_AP + kb + tig    ];
                af[mf][1] = as[(m0 + grp + 8) * CA_AP + kb + tig    ];
                af[mf][2] = as[(m0 + grp    ) * CA_AP + kb + tig + 4];
                af[mf][3] = as[(m0 + grp + 8) * CA_AP + kb + tig + 4];
            }
#pragma unroll
            for (int nf = 0; nf < 8; nf++) {
                int n0 = wn + nf * 8 + grp;
                uint32_t b0 = bs[(kb + tig    ) * CA_BP + n0];
                uint32_t b1 = bs[(kb + tig + 4) * CA_BP + n0];
                mma_tf32(cacc[0][nf], af[0], b0, b1);
                mma_tf32(cacc[1][nf], af[1], b0, b1);
            }
        }
    }

    // epilogue
#pragma unroll
    for (int mf = 0; mf < 2; mf++) {
#pragma unroll
        for (int nf = 0; nf < 8; nf++) {
            int r0 = bm + wm + mf * 16 + grp;
            int c0 = bn + wn + nf * 8 + tig * 2;
            float c[4] = { cacc[mf][nf][0], cacc[mf][nf][1],
                           cacc[mf][nf][2], cacc[mf][nf][3] };
            if (FUSE) {
                float b0 = (c0     < N) ? bias[c0]     : 0.f;
                float b1 = (c0 + 1 < N) ? bias[c0 + 1] : 0.f;
                c[0] = fmaxf(c[0] + b0, 0.f);
                c[1] = fmaxf(c[1] + b1, 0.f);
                c[2] = fmaxf(c[2] + b0, 0.f);
                c[3] = fmaxf(c[3] + b1, 0.f);
            }
            if (ROUND) {
                c[0] = tf32r(c[0]); c[1] = tf32r(c[1]);
                c[2] = tf32r(c[2]); c[3] = tf32r(c[3]);
            }
            if (r0 < M) {
                if (c0 + 1 < N) *(float2*)&Cm[(size_t)r0 * N + c0] = make_float2(c[0], c[1]);
                else if (c0 < N) Cm[(size_t)r0 * N + c0] = c[0];
            }
            if (r0 + 8 < M) {
                if (c0 + 1 < N) *(float2*)&Cm[(size_t)(r0 + 8) * N + c0] = make_float2(c[2], c[3]);
                else if (c0 < N) Cm[(size_t)(r0 + 8) * N + c0] = c[2];
            }
        }
    }
}

// ----------------------------------------------------------------------------
// GAT aggregation: cooperative score staging + online softmax from smem,
// float4 gather with prefetch. Scores live in GEMM output cols [HC..HC+8).
// ----------------------------------------------------------------------------
template<int H, int C, int NP, int NV>
__global__ void __launch_bounds__(128)
gat_agg4(const float* __restrict__ bias)
{
    constexpr int HC  = H * C;
    constexpr int HC4 = HC / 4;
    constexpr int CHUNK = 64;
    int i = blockIdx.x;
    int tid = threadIdx.x;

    __shared__ float s_sc[CHUNK][4];
    __shared__ float s_alpha[CHUNK][4];
    __shared__ int   s_src[CHUNK];

    const float* hbuf = g_bufB;
    float* out = g_bufA;
    const float* row = hbuf + (size_t)i * NP;

    float scS[4], scD[4];
    *(float4*)scS = *(const float4*)&row[HC];
    *(float4*)scD = *(const float4*)&row[HC + 4];

    float adsti[H], m[H], den[H], eself[H], aself[H];
#pragma unroll
    for (int h = 0; h < H; h++) {
        adsti[h] = scD[h];
        eself[h] = lrelu(scS[h] + adsti[h]);
        m[h] = eself[h];
        den[h] = 1.f;
    }

    int beg = g_ptr[i];
    int deg = g_ptr[i + 1] - beg;
    bool single = (deg <= CHUNK);

    // Phase 1: stage scores cooperatively, run softmax stats from smem
    for (int cb = 0; cb < deg; cb += CHUNK) {
        int cn = min(CHUNK, deg - cb);
        if (tid < cn) {
            int s = g_csrsrc[beg + cb + tid];
            s_src[tid] = s;
            *(float4*)s_sc[tid] = *(const float4*)&hbuf[(size_t)s * NP + HC];
        }
        __syncthreads();
        for (int j = 0; j < cn; j++) {
#pragma unroll
            for (int h = 0; h < H; h++) {
                float e = lrelu(s_sc[j][h] + adsti[h]);
                float mo = m[h];
                float mn = fmaxf(mo, e);
                den[h] = den[h] * __expf(mo - mn) + __expf(e - mn);
                m[h] = mn;
            }
        }
        __syncthreads();
    }
#pragma unroll
    for (int h = 0; h < H; h++)
        aself[h] = __expf(eself[h] - m[h]) / (den[h] + 1e-16f);

    int c4i[NV];
    bool val[NV];
    int h0[NV], h1[NV], h2[NV], h3[NV];
#pragma unroll
    for (int t = 0; t < NV; t++) {
        int c4 = tid + t * 128;
        c4i[t] = c4;
        val[t] = (c4 < HC4);
        int c = c4 * 4;
        h0[t] = min(c     / C, H - 1);
        h1[t] = min((c+1) / C, H - 1);
        h2[t] = min((c+2) / C, H - 1);
        h3[t] = min((c+3) / C, H - 1);
    }

    const float4* self4 = (const float4*)row;
    float4 acc[NV];
#pragma unroll
    for (int t = 0; t < NV; t++) {
        if (val[t]) {
            float4 v = self4[c4i[t]];
            acc[t].x = aself[h0[t]] * v.x;
            acc[t].y = aself[h1[t]] * v.y;
            acc[t].z = aself[h2[t]] * v.z;
            acc[t].w = aself[h3[t]] * v.w;
        } else {
            acc[t] = make_float4(0.f, 0.f, 0.f, 0.f);
        }
    }

    // Phase 2: alphas (from staged scores) + gather
    for (int cb = 0; cb < deg; cb += CHUNK) {
        int cn = min(CHUNK, deg - cb);
        __syncthreads();
        if (!single && tid < cn) {
            int s = g_csrsrc[beg + cb + tid];
            s_src[tid] = s;
            *(float4*)s_sc[tid] = *(const float4*)&hbuf[(size_t)s * NP + HC];
        }
        if (!single) __syncthreads();
        if (tid < cn) {
#pragma unroll
            for (int h = 0; h < H; h++) {
                float e = lrelu(s_sc[tid][h] + adsti[h]);
                s_alpha[tid][h] = __expf(e - m[h]) / (den[h] + 1e-16f);
            }
        }
        __syncthreads();

        float4 nxt[NV];
        {
            const float4* hr4 = (const float4*)(hbuf + (size_t)s_src[0] * NP);
#pragma unroll
            for (int t = 0; t < NV; t++)
                if (val[t]) nxt[t] = hr4[c4i[t]];
        }
        for (int j = 0; j < cn; j++) {
            float4 cur[NV];
#pragma unroll
            for (int t = 0; t < NV; t++) cur[t] = nxt[t];
            if (j + 1 < cn) {
                const float4* hn = (const float4*)(hbuf + (size_t)s_src[j + 1] * NP);
#pragma unroll
                for (int t = 0; t < NV; t++)
                    if (val[t]) nxt[t] = hn[c4i[t]];
            }
            float a0 = s_alpha[j][0];
            float a1 = (H > 1) ? s_alpha[j][1] : a0;
            float a2 = (H > 2) ? s_alpha[j][2] : a0;
            float a3 = (H > 3) ? s_alpha[j][3] : a0;
            float al[4] = { a0, a1, a2, a3 };
#pragma unroll
            for (int t = 0; t < NV; t++) {
                if (!val[t]) continue;
                acc[t].x = fmaf(al[h0[t]], cur[t].x, acc[t].x);
                acc[t].y = fmaf(al[h1[t]], cur[t].y, acc[t].y);
                acc[t].z = fmaf(al[h2[t]], cur[t].z, acc[t].z);
                acc[t].w = fmaf(al[h3[t]], cur[t].w, acc[t].w);
            }
        }
    }

    const float4* bias4 = (const float4*)bias;
    float4* out4 = (float4*)(out + (size_t)i * HC);
#pragma unroll
    for (int t = 0; t < NV; t++) {
        if (!val[t]) continue;
        float4 b = bias4[c4i[t]];
        float4 v;
        v.x = tf32r(fmaxf(acc[t].x + b.x, 0.f));
        v.y = tf32r(fmaxf(acc[t].y + b.y, 0.f));
        v.z = tf32r(fmaxf(acc[t].z + b.z, 0.f));
        v.w = tf32r(fmaxf(acc[t].w + b.w, 0.f));
        out4[c4i[t]] = v;
    }
}

// ----------------------------------------------------------------------------
// Global max pool, float4, 2-way unrolled, tf32-rounded output
// ----------------------------------------------------------------------------
__global__ void pool_max(const int* __restrict__ batch)
{
    int g = blockIdx.x;
    int c4 = blockIdx.y * 128 + threadIdx.x;

    int lo = 0, hi = NN;
    while (lo < hi) { int mid = (lo + hi) >> 1; if (batch[mid] < g) lo = mid + 1; else hi = mid; }
    int start = lo;
    lo = start; hi = NN;
    while (lo < hi) { int mid = (lo + hi) >> 1; if (batch[mid] < g + 1) lo = mid + 1; else hi = mid; }
    int end = lo;

    if (c4 < D3 / 4) {
        float4 mv0 = make_float4(0.f, 0.f, 0.f, 0.f);
        float4 mv1 = make_float4(0.f, 0.f, 0.f, 0.f);
        int n = start;
        for (; n + 1 < end; n += 2) {
            float4 v0 = *(const float4*)&g_bufA[(size_t)n * D3 + c4 * 4];
            float4 v1 = *(const float4*)&g_bufA[(size_t)(n + 1) * D3 + c4 * 4];
            mv0.x = fmaxf(mv0.x, v0.x); mv0.y = fmaxf(mv0.y, v0.y);
            mv0.z = fmaxf(mv0.z, v0.z); mv0.w = fmaxf(mv0.w, v0.w);
            mv1.x = fmaxf(mv1.x, v1.x); mv1.y = fmaxf(mv1.y, v1.y);
            mv1.z = fmaxf(mv1.z, v1.z); mv1.w = fmaxf(mv1.w, v1.w);
        }
        if (n < end) {
            float4 v0 = *(const float4*)&g_bufA[(size_t)n * D3 + c4 * 4];
            mv0.x = fmaxf(mv0.x, v0.x); mv0.y = fmaxf(mv0.y, v0.y);
            mv0.z = fmaxf(mv0.z, v0.z); mv0.w = fmaxf(mv0.w, v0.w);
        }
        float4 mv;
        mv.x = tf32r(fmaxf(mv0.x, mv1.x));
        mv.y = tf32r(fmaxf(mv0.y, mv1.y));
        mv.z = tf32r(fmaxf(mv0.z, mv1.z));
        mv.w = tf32r(fmaxf(mv0.w, mv1.w));
        *(float4*)&g_pool[g * D3 + c4 * 4] = mv;
    }
}

// ----------------------------------------------------------------------------
// launch
// ----------------------------------------------------------------------------
extern "C" void kernel_launch(void* const* d_in, const int* in_sizes, int n_in,
                              void* d_out, int out_size)
{
    const float* x     = (const float*)d_in[0];
    const int*   ei    = (const int*)d_in[1];
    const int*   batch = (const int*)d_in[2];
    const float* W1 = (const float*)d_in[3];
    const float* as1 = (const float*)d_in[4];
    const float* ad1 = (const float*)d_in[5];
    const float* b1 = (const float*)d_in[6];
    const float* W2 = (const float*)d_in[7];
    const float* as2 = (const float*)d_in[8];
    const float* ad2 = (const float*)d_in[9];
    const float* b2 = (const float*)d_in[10];
    const float* W3 = (const float*)d_in[11];
    const float* as3 = (const float*)d_in[12];
    const float* ad3 = (const float*)d_in[13];
    const float* b3 = (const float*)d_in[14];
    const float* fc1_w = (const float*)d_in[15];
    const float* fc1_b = (const float*)d_in[16];
    const float* fc2_w = (const float*)d_in[17];
    const float* fc2_b = (const float*)d_in[18];
    float* outp = (float*)d_out;

    cudaFuncSetAttribute(tgemm_ca<0, 0>,
                         cudaFuncAttributeMaxDynamicSharedMemorySize, CA_SMEM_BYTES);
    cudaFuncSetAttribute(tgemm_ca<1, 1>,
                         cudaFuncAttributeMaxDynamicSharedMemorySize, CA_SMEM_BYTES);
    cudaFuncSetAttribute(tgemm_ca<1, 0>,
                         cudaFuncAttributeMaxDynamicSharedMemorySize, CA_SMEM_BYTES);

    // --- CSR build + operand prep ---
    zero_counts_kernel<<<(NN + 255) / 256, 256>>>();
    hist_kernel<<<(EE + 255) / 256, 256>>>(ei);
    scan_kernel<<<1, 1024>>>();
    csr_fill_kernel<<<(EE + 255) / 256, 256>>>(ei);
    pad_x_kernel<<<(NN * K1PAD + 255) / 256, 256>>>(x);
    round_copy_kernel<<<(D1 * 312 + 255) / 256, 256>>>(W1, D1, 312, NP1, 7);
    ws_fill_kernel<<<(D1 * 8 + 255) / 256, 256>>>(W1, as1, ad1, D1, D1, HEADS, 312, NP1, 7);
    round_copy_kernel<<<(D2 * D3 + 255) / 256, 256>>>(W2, D2, D3, NP23, 8);
    ws_fill_kernel<<<(D2 * 8 + 255) / 256, 256>>>(W2, as2, ad2, D2, D2, HEADS, D3, NP23, 8);
    round_copy_kernel<<<(D3 * D3 + 255) / 256, 256>>>(W3, D3, D3, NP23, 9);
    ws_fill_kernel<<<(D3 * 8 + 255) / 256, 256>>>(W3, as3, ad3, D3, D3, 1, D3, NP23, 9);
    round_copy_kernel<<<(D3 * HID + 255) / 256, 256>>>(fc1_w, D3, HID, HID, 10);
    round_copy_kernel<<<(HID * OUTD + 255) / 256, 256>>>(fc2_w, HID, OUTD, OUTD, 11);

    dim3 blk(256);
    // --- layer 1: bufB[N,320] = xpad @ w1r  (K=80) ---
    {
        dim3 grid((NP1 + 127) / 128, (NN + 127) / 128);
        tgemm_ca<0, 0><<<grid, blk, CA_SMEM_BYTES>>>(
            nullptr, 5, 7, nullptr, 2, NN, NP1, K1PAD, nullptr);
        gat_agg4<HEADS, D1, NP1, 1><<<NN, 128>>>(b1);
    }
    // --- layer 2: bufB[N,1256] = bufA @ w2r  (K=312) ---
    {
        dim3 grid((NP23 + 127) / 128, (NN + 127) / 128);
        tgemm_ca<0, 0><<<grid, blk, CA_SMEM_BYTES>>>(
            nullptr, 1, 8, nullptr, 2, NN, NP23, D2, nullptr);
        gat_agg4<HEADS, D2, NP23, 3><<<NN, 128>>>(b2);
    }
    // --- layer 3: bufB[N,1256] = bufA @ w3r  (K=1248) ---
    {
        dim3 grid((NP23 + 127) / 128, (NN + 127) / 128);
        tgemm_ca<0, 0><<<grid, blk, CA_SMEM_BYTES>>>(
            nullptr, 1, 9, nullptr, 2, NN, NP23, D3, nullptr);
        gat_agg4<1, D3, NP23, 3><<<NN, 128>>>(b3);
    }
    // --- pool + FC (tensor path, fused bias+relu) ---
    {
        dim3 pg(GG, (D3 / 4 + 127) / 128);
        pool_max<<<pg, 128>>>(batch);
        dim3 g1((HID + 127) / 128, (GG + 127) / 128);
        tgemm_ca<1, 1><<<g1, blk, CA_SMEM_BYTES>>>(
            nullptr, 3, 10, nullptr, 4, GG, HID, D3, fc1_b);
        dim3 g2((OUTD + 127) / 128, (GG + 127) / 128);
        tgemm_ca<1, 0><<<g2, blk, CA_SMEM_BYTES>>>(
            nullptr, 4, 11, outp, 0, GG, OUTD, HID, fc2_b);
    }
    (void)n_in; (void)in_sizes; (void)out_size;
}

// round 13
// speedup vs baseline: 4.6308x; 1.2549x over previous
#include <cuda_runtime.h>
#include <cuda_fp16.h>
#include <math.h>
#include <stdint.h>

#define NN     50000
#define EE     200000
#define HEADS  4
#define GG     512
#define HID    1024
#define OUTD   128
#define D1     78
#define D2     312
#define D3     1248
#define NEG    0.2f
#define K1PAD  80
#define NP1    320
#define NP23   1256

__device__ __align__(16) __half g_bufA_h[(size_t)NN * D3];
__device__ __align__(16) __half g_bufB_h[(size_t)NN * NP23];
__device__ __align__(16) __half g_xpad_h[(size_t)NN * K1PAD];
__device__ __align__(16) __half g_pool_h[GG * D3];
__device__ __align__(16) __half g_fc1_h[GG * HID];
__device__ __align__(16) uint32_t g_w1p[(K1PAD / 2) * NP1];
__device__ __align__(16) uint32_t g_w2p[(D2 / 2) * NP23];
__device__ __align__(16) uint32_t g_w3p[(size_t)(D3 / 2) * NP23];
__device__ __align__(16) uint32_t g_fc1p[(D3 / 2) * HID];
__device__ __align__(16) uint32_t g_fc2p[(HID / 2) * OUTD];
__device__ int   g_counts[NN];
__device__ int   g_cursor[NN];
__device__ int   g_ptr[NN + 1];
__device__ int   g_csrsrc[EE];

__device__ __forceinline__ float lrelu(float x) { return x > 0.f ? x : NEG * x; }

__device__ __forceinline__ const __half* sel_h(int s) {
    switch (s) {
        case 1: return g_bufA_h;
        case 2: return g_bufB_h;
        case 3: return g_pool_h;
        case 4: return g_fc1_h;
        case 5: return g_xpad_h;
        default: return g_bufA_h;
    }
}
__device__ __forceinline__ __half* sel_hw(int s) {
    switch (s) {
        case 1: return g_bufA_h;
        case 2: return g_bufB_h;
        case 3: return g_pool_h;
        case 4: return g_fc1_h;
        default: return g_bufA_h;
    }
}
__device__ __forceinline__ const uint32_t* sel_w(int s) {
    switch (s) {
        case 7:  return g_w1p;
        case 8:  return g_w2p;
        case 9:  return g_w3p;
        case 10: return g_fc1p;
        default: return g_fc2p;
    }
}
__device__ __forceinline__ uint32_t* sel_ww(int s) {
    switch (s) {
        case 7:  return g_w1p;
        case 8:  return g_w2p;
        case 9:  return g_w3p;
        case 10: return g_fc1p;
        default: return g_fc2p;
    }
}

// ---------------- CSR ----------------
__global__ void zero_counts_kernel() {
    int i = blockIdx.x * blockDim.x + threadIdx.x;
    if (i < NN) { g_counts[i] = 0; g_cursor[i] = 0; }
}
__global__ void hist_kernel(const int* __restrict__ ei) {
    int e = blockIdx.x * blockDim.x + threadIdx.x;
    if (e < EE) atomicAdd(&g_counts[ei[EE + e]], 1);
}
__global__ void scan_kernel() {
    __shared__ int sh[1024];
    __shared__ int s_off;
    int tid = threadIdx.x;
    if (tid == 0) { s_off = 0; g_ptr[0] = 0; }
    __syncthreads();
    for (int base = 0; base < NN; base += 1024) {
        int v = (base + tid < NN) ? g_counts[base + tid] : 0;
        sh[tid] = v;
        __syncthreads();
        for (int s = 1; s < 1024; s <<= 1) {
            int t = (tid >= s) ? sh[tid - s] : 0;
            __syncthreads();
            sh[tid] += t;
            __syncthreads();
        }
        int off = s_off;
        if (base + tid < NN) g_ptr[base + tid + 1] = off + sh[tid];
        __syncthreads();
        if (tid == 0) s_off = off + sh[1023];
        __syncthreads();
    }
}
__global__ void csr_fill_kernel(const int* __restrict__ ei) {
    int e = blockIdx.x * blockDim.x + threadIdx.x;
    if (e < EE) {
        int r = ei[e];
        int c = ei[EE + e];
        int pos = g_ptr[c] + atomicAdd(&g_cursor[c], 1);
        g_csrsrc[pos] = r;
    }
}

// ---------------- operand prep ----------------
__global__ void pad_x_kernel(const float* __restrict__ x) {
    int idx = blockIdx.x * blockDim.x + threadIdx.x;
    if (idx < NN * K1PAD) {
        int n = idx / K1PAD, k = idx - n * K1PAD;
        g_xpad_h[idx] = __float2half_rn((k < D1) ? x[(size_t)n * D1 + k] : 0.f);
    }
}

// pack k-pairs; rows >= KREAL are zero (KPAD may exceed KREAL)
__global__ void pack_w_kernel(const float* __restrict__ W,
                              int KPAD, int KREAL, int N, int NP, int dsel) {
    uint32_t* dst = sel_ww(dsel);
    int idx = blockIdx.x * blockDim.x + threadIdx.x;
    int K2 = KPAD >> 1;
    if (idx < K2 * N) {
        int kk = idx / N, n = idx - kk * N;
        float v0 = (2 * kk     < KREAL) ? W[(size_t)(2 * kk) * N + n] : 0.f;
        float v1 = (2 * kk + 1 < KREAL) ? W[(size_t)(2 * kk + 1) * N + n] : 0.f;
        __half2 h = __floats2half2_rn(v0, v1);
        dst[(size_t)kk * NP + n] = *(uint32_t*)&h;
    }
}

__global__ void ws_fill_kernel(const float* __restrict__ W,
                               const float* __restrict__ att_s,
                               const float* __restrict__ att_d,
                               int KPAD, int KREAL, int C, int H,
                               int N, int NP, int dsel) {
    uint32_t* dst = sel_ww(dsel);
    int t = blockIdx.x * blockDim.x + threadIdx.x;
    int K2 = KPAD >> 1;
    if (t >= K2 * 8) return;
    int kk = t >> 3, slot = t & 7;
    int h = slot & 3;
    const float* att = (slot >= 4) ? att_d : att_s;
    float v0 = 0.f, v1 = 0.f;
    if (h < H) {
        const float* ar = att + h * C;
        if (2 * kk < KREAL) {
            const float* w0 = W + (size_t)(2 * kk) * N + h * C;
            for (int c = 0; c < C; c++) v0 = fmaf(w0[c], ar[c], v0);
        }
        if (2 * kk + 1 < KREAL) {
            const float* w1 = W + (size_t)(2 * kk + 1) * N + h * C;
            for (int c = 0; c < C; c++) v1 = fmaf(w1[c], ar[c], v1);
        }
    }
    __half2 hp = __floats2half2_rn(v0, v1);
    dst[(size_t)kk * NP + N + slot] = *(uint32_t*)&hp;
}

// ---------------- FP16 GEMM (mma.m16n8k16, cp.async 3-stage) ----------------
__device__ __forceinline__ void mma_fp16(float c[4], const uint32_t a[4],
                                         uint32_t b0, uint32_t b1)
{
    asm volatile(
        "mma.sync.aligned.m16n8k16.row.col.f32.f16.f16.f32 "
        "{%0,%1,%2,%3}, {%4,%5,%6,%7}, {%8,%9}, {%0,%1,%2,%3};"
        : "+f"(c[0]), "+f"(c[1]), "+f"(c[2]), "+f"(c[3])
        : "r"(a[0]), "r"(a[1]), "r"(a[2]), "r"(a[3]), "r"(b0), "r"(b1));
}

#define CA_AP    20
#define CA_ASZ   (128 * CA_AP)
#define CA_BP    136
#define CA_BSZ   (16 * CA_BP)
#define CA_STW   (CA_ASZ + CA_BSZ)
#define CA_SMEM_BYTES (3 * CA_STW * 4)

template<int FUSE, int OUTF32>
__global__ void __launch_bounds__(256)
hgemm_ca(int Asel, int Bsel, float* Cext, int Csel, int M, int N, int K,
         const float* __restrict__ bias)
{
    extern __shared__ uint32_t smw[];
    uint32_t sb = (uint32_t)__cvta_generic_to_shared(smw);

    const __half* A = sel_h(Asel);
    const uint32_t* Bp = sel_w(Bsel);
    __half* Ch = sel_hw(Csel);

    int tid = threadIdx.x;
    int warpid = tid >> 5, lane = tid & 31;
    int bm = blockIdx.y * 128, bn = blockIdx.x * 128;
    int wm = (warpid >> 1) * 32;
    int wn = (warpid & 1) * 64;
    int grp = lane >> 2, tig = lane & 3;

    float cacc[2][8][4];
#pragma unroll
    for (int mf = 0; mf < 2; mf++)
#pragma unroll
        for (int nf = 0; nf < 8; nf++)
#pragma unroll
            for (int q = 0; q < 4; q++) cacc[mf][nf][q] = 0.f;

    int steps = (K + 31) >> 5;
    int K2 = K >> 1;

    auto issue = [&](int st, int k0) {
        uint32_t abase = sb + (uint32_t)(st * CA_STW) * 4;
        uint32_t bbase = abase + CA_ASZ * 4;
#pragma unroll
        for (int q = 0; q < 2; q++) {
            int flat = q * 256 + tid;
            int row = flat >> 2, kc = (flat & 3) * 8;
            int gm = bm + row, gk = k0 + kc;
            bool p = (gm < M) && (gk < K);
            const __half* src = p ? (A + (size_t)gm * K + gk) : A;
            uint32_t dst = abase + (uint32_t)(row * CA_AP + (kc >> 1)) * 4;
            uint32_t sz = p ? 16u : 0u;
            asm volatile("cp.async.cg.shared.global [%0], [%1], 16, %2;"
                         :: "r"(dst), "l"(src), "r"(sz));
        }
#pragma unroll
        for (int q = 0; q < 2; q++) {
            int flat = q * 256 + tid;
            int kkw = flat >> 5, n4 = (flat & 31) * 4;
            int gkk = (k0 >> 1) + kkw, gn = bn + n4;
            bool p = (gkk < K2) && (gn < N);
            const uint32_t* src = p ? (Bp + (size_t)gkk * N + gn) : Bp;
            uint32_t dst = bbase + (uint32_t)(kkw * CA_BP + n4) * 4;
            uint32_t sz = p ? 16u : 0u;
            asm volatile("cp.async.cg.shared.global [%0], [%1], 16, %2;"
                         :: "r"(dst), "l"(src), "r"(sz));
        }
        asm volatile("cp.async.commit_group;");
    };

    issue(0, 0);
    if (steps > 1) issue(1, 32);

    for (int s = 0; s < steps; s++) {
        int buf = s % 3;
        if (s + 1 < steps) asm volatile("cp.async.wait_group 1;");
        else               asm volatile("cp.async.wait_group 0;");
        __syncthreads();
        if (s + 2 < steps) issue((s + 2) % 3, (s + 2) << 5);

        const uint32_t* as = smw + buf * CA_STW;
        const uint32_t* bs = as + CA_ASZ;
#pragma unroll
        for (int kf = 0; kf < 2; kf++) {
            int kw = kf * 8;
            uint32_t af[2][4];
#pragma unroll
            for (int mf = 0; mf < 2; mf++) {
                int m0 = wm + mf * 16;
                af[mf][0] = as[(m0 + grp    ) * CA_AP + kw + tig    ];
                af[mf][1] = as[(m0 + grp + 8) * CA_AP + kw + tig    ];
                af[mf][2] = as[(m0 + grp    ) * CA_AP + kw + tig + 4];
                af[mf][3] = as[(m0 + grp + 8) * CA_AP + kw + tig + 4];
            }
#pragma unroll
            for (int nf = 0; nf < 8; nf++) {
                int n0 = wn + nf * 8 + grp;
                uint32_t b0 = bs[(kw + tig    ) * CA_BP + n0];
                uint32_t b1 = bs[(kw + tig + 4) * CA_BP + n0];
                mma_fp16(cacc[0][nf], af[0], b0, b1);
                mma_fp16(cacc[1][nf], af[1], b0, b1);
            }
        }
    }

#pragma unroll
    for (int mf = 0; mf < 2; mf++) {
#pragma unroll
        for (int nf = 0; nf < 8; nf++) {
            int r0 = bm + wm + mf * 16 + grp;
            int c0 = bn + wn + nf * 8 + tig * 2;
            float c[4] = { cacc[mf][nf][0], cacc[mf][nf][1],
                           cacc[mf][nf][2], cacc[mf][nf][3] };
            if (FUSE) {
                float b0 = (c0     < N) ? bias[c0]     : 0.f;
                float b1 = (c0 + 1 < N) ? bias[c0 + 1] : 0.f;
                c[0] = fmaxf(c[0] + b0, 0.f);
                c[1] = fmaxf(c[1] + b1, 0.f);
                c[2] = fmaxf(c[2] + b0, 0.f);
                c[3] = fmaxf(c[3] + b1, 0.f);
            }
            if (c0 < N) {
                if (OUTF32) {
                    if (r0 < M)     *(float2*)&Cext[(size_t)r0 * N + c0] = make_float2(c[0], c[1]);
                    if (r0 + 8 < M) *(float2*)&Cext[(size_t)(r0 + 8) * N + c0] = make_float2(c[2], c[3]);
                } else {
                    if (r0 < M) {
                        __half2 h = __floats2half2_rn(c[0], c[1]);
                        *(uint32_t*)&Ch[(size_t)r0 * N + c0] = *(uint32_t*)&h;
                    }
                    if (r0 + 8 < M) {
                        __half2 h = __floats2half2_rn(c[2], c[3]);
                        *(uint32_t*)&Ch[(size_t)(r0 + 8) * N + c0] = *(uint32_t*)&h;
                    }
                }
            }
        }
    }
}

// ---------------- GAT aggregation (fp16 rows) ----------------
template<int H, int C, int NP, int NV>
__global__ void __launch_bounds__(128)
gat_agg_h(const float* __restrict__ bias)
{
    constexpr int HC  = H * C;
    constexpr int HC8 = HC / 8;
    constexpr int CHUNK = 64;
    int i = blockIdx.x;
    int tid = threadIdx.x;

    __shared__ float s_sc[CHUNK][4];
    __shared__ float s_alpha[CHUNK][4];
    __shared__ int   s_src[CHUNK];

    const __half* hbuf = g_bufB_h;
    __half* out = g_bufA_h;
    const __half* row = hbuf + (size_t)i * NP;

    float scS[4], scD[4];
    {
        uint4 v = *(const uint4*)&row[HC];
        __half2* p = (__half2*)&v;
        float2 f0 = __half22float2(p[0]), f1 = __half22float2(p[1]);
        float2 f2 = __half22float2(p[2]), f3 = __half22float2(p[3]);
        scS[0] = f0.x; scS[1] = f0.y; scS[2] = f1.x; scS[3] = f1.y;
        scD[0] = f2.x; scD[1] = f2.y; scD[2] = f3.x; scD[3] = f3.y;
    }

    float adsti[H], m[H], den[H], eself[H], aself[H];
#pragma unroll
    for (int h = 0; h < H; h++) {
        adsti[h] = scD[h];
        eself[h] = lrelu(scS[h] + adsti[h]);
        m[h] = eself[h];
        den[h] = 1.f;
    }

    int beg = g_ptr[i];
    int deg = g_ptr[i + 1] - beg;
    bool single = (deg <= CHUNK);

    for (int cb = 0; cb < deg; cb += CHUNK) {
        int cn = min(CHUNK, deg - cb);
        if (tid < cn) {
            int s = g_csrsrc[beg + cb + tid];
            s_src[tid] = s;
            uint2 v = *(const uint2*)&hbuf[(size_t)s * NP + HC];
            __half2* p = (__half2*)&v;
            float2 f0 = __half22float2(p[0]), f1 = __half22float2(p[1]);
            s_sc[tid][0] = f0.x; s_sc[tid][1] = f0.y;
            s_sc[tid][2] = f1.x; s_sc[tid][3] = f1.y;
        }
        __syncthreads();
        for (int j = 0; j < cn; j++) {
#pragma unroll
            for (int h = 0; h < H; h++) {
                float e = lrelu(s_sc[j][h] + adsti[h]);
                float mo = m[h];
                float mn = fmaxf(mo, e);
                den[h] = den[h] * __expf(mo - mn) + __expf(e - mn);
                m[h] = mn;
            }
        }
        __syncthreads();
    }
#pragma unroll
    for (int h = 0; h < H; h++)
        aself[h] = __expf(eself[h] - m[h]) / (den[h] + 1e-16f);

    int c8i[NV];
    bool val[NV];
    int he[NV][8];
#pragma unroll
    for (int t = 0; t < NV; t++) {
        int c8 = tid + t * 128;
        c8i[t] = c8;
        val[t] = (c8 < HC8);
#pragma unroll
        for (int e = 0; e < 8; e++)
            he[t][e] = min((c8 * 8 + e) / C, H - 1);
    }

    float acc[NV][8];
#pragma unroll
    for (int t = 0; t < NV; t++) {
        if (val[t]) {
            uint4 v = *(const uint4*)&row[c8i[t] * 8];
            __half2* p = (__half2*)&v;
            float2 q0 = __half22float2(p[0]), q1 = __half22float2(p[1]);
            float2 q2 = __half22float2(p[2]), q3 = __half22float2(p[3]);
            float f[8] = { q0.x, q0.y, q1.x, q1.y, q2.x, q2.y, q3.x, q3.y };
#pragma unroll
            for (int e = 0; e < 8; e++) acc[t][e] = aself[he[t][e]] * f[e];
        } else {
#pragma unroll
            for (int e = 0; e < 8; e++) acc[t][e] = 0.f;
        }
    }

    for (int cb = 0; cb < deg; cb += CHUNK) {
        int cn = min(CHUNK, deg - cb);
        __syncthreads();
        if (!single && tid < cn) {
            int s = g_csrsrc[beg + cb + tid];
            s_src[tid] = s;
            uint2 v = *(const uint2*)&hbuf[(size_t)s * NP + HC];
            __half2* p = (__half2*)&v;
            float2 f0 = __half22float2(p[0]), f1 = __half22float2(p[1]);
            s_sc[tid][0] = f0.x; s_sc[tid][1] = f0.y;
            s_sc[tid][2] = f1.x; s_sc[tid][3] = f1.y;
        }
        if (!single) __syncthreads();
        if (tid < cn) {
#pragma unroll
            for (int h = 0; h < H; h++) {
                float e = lrelu(s_sc[tid][h] + adsti[h]);
                s_alpha[tid][h] = __expf(e - m[h]) / (den[h] + 1e-16f);
            }
        }
        __syncthreads();

        uint4 nxt[NV];
        {
            const uint4* hr = (const uint4*)(hbuf + (size_t)s_src[0] * NP);
#pragma unroll
            for (int t = 0; t < NV; t++)
                if (val[t]) nxt[t] = hr[c8i[t]];
        }
        for (int j = 0; j < cn; j++) {
            uint4 cur[NV];
#pragma unroll
            for (int t = 0; t < NV; t++) cur[t] = nxt[t];
            if (j + 1 < cn) {
                const uint4* hn = (const uint4*)(hbuf + (size_t)s_src[j + 1] * NP);
#pragma unroll
                for (int t = 0; t < NV; t++)
                    if (val[t]) nxt[t] = hn[c8i[t]];
            }
            float a0 = s_alpha[j][0];
            float a1 = (H > 1) ? s_alpha[j][1] : a0;
            float a2 = (H > 2) ? s_alpha[j][2] : a0;
            float a3 = (H > 3) ? s_alpha[j][3] : a0;
            float al[4] = { a0, a1, a2, a3 };
#pragma unroll
            for (int t = 0; t < NV; t++) {
                if (!val[t]) continue;
                __half2* p = (__half2*)&cur[t];
                float2 q0 = __half22float2(p[0]), q1 = __half22float2(p[1]);
                float2 q2 = __half22float2(p[2]), q3 = __half22float2(p[3]);
                float f[8] = { q0.x, q0.y, q1.x, q1.y, q2.x, q2.y, q3.x, q3.y };
#pragma unroll
                for (int e = 0; e < 8; e++)
                    acc[t][e] = fmaf(al[he[t][e]], f[e], acc[t][e]);
            }
        }
    }

    __half* orow = out + (size_t)i * HC;
#pragma unroll
    for (int t = 0; t < NV; t++) {
        if (!val[t]) continue;
        int cb0 = c8i[t] * 8;
        float4 b0 = *(const float4*)&bias[cb0];
        float4 b1 = *(const float4*)&bias[cb0 + 4];
        float o[8];
        o[0] = fmaxf(acc[t][0] + b0.x, 0.f);
        o[1] = fmaxf(acc[t][1] + b0.y, 0.f);
        o[2] = fmaxf(acc[t][2] + b0.z, 0.f);
        o[3] = fmaxf(acc[t][3] + b0.w, 0.f);
        o[4] = fmaxf(acc[t][4] + b1.x, 0.f);
        o[5] = fmaxf(acc[t][5] + b1.y, 0.f);
        o[6] = fmaxf(acc[t][6] + b1.z, 0.f);
        o[7] = fmaxf(acc[t][7] + b1.w, 0.f);
        uint4 ov;
        __half2 h0 = __floats2half2_rn(o[0], o[1]);
        __half2 h1 = __floats2half2_rn(o[2], o[3]);
        __half2 h2 = __floats2half2_rn(o[4], o[5]);
        __half2 h3 = __floats2half2_rn(o[6], o[7]);
        ov.x = *(uint32_t*)&h0; ov.y = *(uint32_t*)&h1;
        ov.z = *(uint32_t*)&h2; ov.w = *(uint32_t*)&h3;
        *(uint4*)&orow[cb0] = ov;
    }
}

// ---------------- pool ----------------
__global__ void pool_max(const int* __restrict__ batch)
{
    int g = blockIdx.x;
    int c8 = blockIdx.y * 128 + threadIdx.x;

    int lo = 0, hi = NN;
    while (lo < hi) { int mid = (lo + hi) >> 1; if (batch[mid] < g) lo = mid + 1; else hi = mid; }
    int start = lo;
    lo = start; hi = NN;
    while (lo < hi) { int mid = (lo + hi) >> 1; if (batch[mid] < g + 1) lo = mid + 1; else hi = mid; }
    int end = lo;

    if (c8 < D3 / 8) {
        float mv[8];
#pragma unroll
        for (int e = 0; e < 8; e++) mv[e] = 0.f;
        for (int n = start; n < end; n++) {
            uint4 v = *(const uint4*)&g_bufA_h[(size_t)n * D3 + c8 * 8];
            __half2* p = (__half2*)&v;
            float2 q0 = __half22float2(p[0]), q1 = __half22float2(p[1]);
            float2 q2 = __half22float2(p[2]), q3 = __half22float2(p[3]);
            mv[0] = fmaxf(mv[0], q0.x); mv[1] = fmaxf(mv[1], q0.y);
            mv[2] = fmaxf(mv[2], q1.x); mv[3] = fmaxf(mv[3], q1.y);
            mv[4] = fmaxf(mv[4], q2.x); mv[5] = fmaxf(mv[5], q2.y);
            mv[6] = fmaxf(mv[6], q3.x); mv[7] = fmaxf(mv[7], q3.y);
        }
        uint4 ov;
        __half2 h0 = __floats2half2_rn(mv[0], mv[1]);
        __half2 h1 = __floats2half2_rn(mv[2], mv[3]);
        __half2 h2 = __floats2half2_rn(mv[4], mv[5]);
        __half2 h3 = __floats2half2_rn(mv[6], mv[7]);
        ov.x = *(uint32_t*)&h0; ov.y = *(uint32_t*)&h1;
        ov.z = *(uint32_t*)&h2; ov.w = *(uint32_t*)&h3;
        *(uint4*)&g_pool_h[g * D3 + c8 * 8] = ov;
    }
}

// ---------------- launch ----------------
extern "C" void kernel_launch(void* const* d_in, const int* in_sizes, int n_in,
                              void* d_out, int out_size)
{
    const float* x     = (const float*)d_in[0];
    const int*   ei    = (const int*)d_in[1];
    const int*   batch = (const int*)d_in[2];
    const float* W1 = (const float*)d_in[3];
    const float* as1 = (const float*)d_in[4];
    const float* ad1 = (const float*)d_in[5];
    const float* b1 = (const float*)d_in[6];
    const float* W2 = (const float*)d_in[7];
    const float* as2 = (const float*)d_in[8];
    const float* ad2 = (const float*)d_in[9];
    const float* b2 = (const float*)d_in[10];
    const float* W3 = (const float*)d_in[11];
    const float* as3 = (const float*)d_in[12];
    const float* ad3 = (const float*)d_in[13];
    const float* b3 = (const float*)d_in[14];
    const float* fc1_w = (const float*)d_in[15];
    const float* fc1_b = (const float*)d_in[16];
    const float* fc2_w = (const float*)d_in[17];
    const float* fc2_b = (const float*)d_in[18];
    float* outp = (float*)d_out;

    cudaFuncSetAttribute(hgemm_ca<0, 0>,
                         cudaFuncAttributeMaxDynamicSharedMemorySize, CA_SMEM_BYTES);
    cudaFuncSetAttribute(hgemm_ca<1, 0>,
                         cudaFuncAttributeMaxDynamicSharedMemorySize, CA_SMEM_BYTES);
    cudaFuncSetAttribute(hgemm_ca<1, 1>,
                         cudaFuncAttributeMaxDynamicSharedMemorySize, CA_SMEM_BYTES);

    zero_counts_kernel<<<(NN + 255) / 256, 256>>>();
    hist_kernel<<<(EE + 255) / 256, 256>>>(ei);
    scan_kernel<<<1, 1024>>>();
    csr_fill_kernel<<<(EE + 255) / 256, 256>>>(ei);
    pad_x_kernel<<<(NN * K1PAD + 255) / 256, 256>>>(x);
    pack_w_kernel<<<((K1PAD/2) * 312 + 255) / 256, 256>>>(W1, K1PAD, D1, 312, NP1, 7);
    ws_fill_kernel<<<((K1PAD/2) * 8 + 255) / 256, 256>>>(W1, as1, ad1, K1PAD, D1, D1, HEADS, 312, NP1, 7);
    pack_w_kernel<<<((D2/2) * D3 + 255) / 256, 256>>>(W2, D2, D2, D3, NP23, 8);
    ws_fill_kernel<<<((D2/2) * 8 + 255) / 256, 256>>>(W2, as2, ad2, D2, D2, D2, HEADS, D3, NP23, 8);
    pack_w_kernel<<<((D3/2) * D3 + 255) / 256, 256>>>(W3, D3, D3, D3, NP23, 9);
    ws_fill_kernel<<<((D3/2) * 8 + 255) / 256, 256>>>(W3, as3, ad3, D3, D3, D3, 1, D3, NP23, 9);
    pack_w_kernel<<<((D3/2) * HID + 255) / 256, 256>>>(fc1_w, D3, D3, HID, HID, 10);
    pack_w_kernel<<<((HID/2) * OUTD + 255) / 256, 256>>>(fc2_w, HID, HID, OUTD, OUTD, 11);

    dim3 blk(256);
    {
        dim3 grid((NP1 + 127) / 128, (NN + 127) / 128);
        hgemm_ca<0, 0><<<grid, blk, CA_SMEM_BYTES>>>(5, 7, nullptr, 2, NN, NP1, K1PAD, nullptr);
        gat_agg_h<HEADS, D1, NP1, 1><<<NN, 128>>>(b1);
    }
    {
        dim3 grid((NP23 + 127) / 128, (NN + 127) / 128);
        hgemm_ca<0, 0><<<grid, blk, CA_SMEM_BYTES>>>(1, 8, nullptr, 2, NN, NP23, D2, nullptr);
        gat_agg_h<HEADS, D2, NP23, 2><<<NN, 128>>>(b2);
    }
    {
        dim3 grid((NP23 + 127) / 128, (NN + 127) / 128);
        hgemm_ca<0, 0><<<grid, blk, CA_SMEM_BYTES>>>(1, 9, nullptr, 2, NN, NP23, D3, nullptr);
        gat_agg_h<1, D3, NP23, 2><<<NN, 128>>>(b3);
    }
    {
        dim3 pg(GG, (D3 / 8 + 127) / 128);
        pool_max<<<pg, 128>>>(batch);
        dim3 g1((HID + 127) / 128, (GG + 127) / 128);
        hgemm_ca<1, 0><<<g1, blk, CA_SMEM_BYTES>>>(3, 10, nullptr, 4, GG, HID, D3, fc1_b);
        dim3 g2((OUTD + 127) / 128, (GG + 127) / 128);
        hgemm_ca<1, 1><<<g2, blk, CA_SMEM_BYTES>>>(4, 11, outp, 0, GG, OUTD, HID, fc2_b);
    }
    (void)n_in; (void)in_sizes; (void)out_size;
}

// round 14
// speedup vs baseline: 4.7874x; 1.0338x over previous
#include <cuda_runtime.h>
#include <cuda_fp16.h>
#include <math.h>
#include <stdint.h>

#define NN     50000
#define EE     200000
#define HEADS  4
#define GG     512
#define HID    1024
#define OUTD   128
#define D1     78
#define D2     312
#define D3     1248
#define NEG    0.2f
#define K1PAD  80
#define NP1    320
#define NP23   1256

__device__ __align__(16) __half g_bufA_h[(size_t)NN * D3];
__device__ __align__(16) __half g_bufB_h[(size_t)NN * NP23];
__device__ __align__(16) __half g_xpad_h[(size_t)NN * K1PAD];
__device__ __align__(16) __half g_pool_h[GG * D3];
__device__ __align__(16) __half g_fc1_h[GG * HID];
__device__ __align__(16) uint32_t g_w1p[(K1PAD / 2) * NP1];
__device__ __align__(16) uint32_t g_w2p[(D2 / 2) * NP23];
__device__ __align__(16) uint32_t g_w3p[(size_t)(D3 / 2) * NP23];
__device__ __align__(16) uint32_t g_fc1p[(D3 / 2) * HID];
__device__ __align__(16) uint32_t g_fc2p[(HID / 2) * OUTD];
__device__ int   g_counts[NN];
__device__ int   g_cursor[NN];
__device__ int   g_ptr[NN + 1];
__device__ int   g_csrsrc[EE];

__device__ __forceinline__ float lrelu(float x) { return x > 0.f ? x : NEG * x; }

__device__ __forceinline__ const __half* sel_h(int s) {
    switch (s) {
        case 1: return g_bufA_h;
        case 2: return g_bufB_h;
        case 3: return g_pool_h;
        case 4: return g_fc1_h;
        case 5: return g_xpad_h;
        default: return g_bufA_h;
    }
}
__device__ __forceinline__ __half* sel_hw(int s) {
    switch (s) {
        case 1: return g_bufA_h;
        case 2: return g_bufB_h;
        case 3: return g_pool_h;
        case 4: return g_fc1_h;
        default: return g_bufA_h;
    }
}
__device__ __forceinline__ const uint32_t* sel_w(int s) {
    switch (s) {
        case 7:  return g_w1p;
        case 8:  return g_w2p;
        case 9:  return g_w3p;
        case 10: return g_fc1p;
        default: return g_fc2p;
    }
}

// ---------------- CSR ----------------
__global__ void zero_counts_kernel() {
    int i = blockIdx.x * blockDim.x + threadIdx.x;
    if (i < NN) { g_counts[i] = 0; g_cursor[i] = 0; }
}
__global__ void hist_kernel(const int* __restrict__ ei) {
    int e = blockIdx.x * blockDim.x + threadIdx.x;
    if (e < EE) atomicAdd(&g_counts[ei[EE + e]], 1);
}
__global__ void scan_kernel() {
    __shared__ int sh[1024];
    __shared__ int s_off;
    int tid = threadIdx.x;
    if (tid == 0) { s_off = 0; g_ptr[0] = 0; }
    __syncthreads();
    for (int base = 0; base < NN; base += 1024) {
        int v = (base + tid < NN) ? g_counts[base + tid] : 0;
        sh[tid] = v;
        __syncthreads();
        for (int s = 1; s < 1024; s <<= 1) {
            int t = (tid >= s) ? sh[tid - s] : 0;
            __syncthreads();
            sh[tid] += t;
            __syncthreads();
        }
        int off = s_off;
        if (base + tid < NN) g_ptr[base + tid + 1] = off + sh[tid];
        __syncthreads();
        if (tid == 0) s_off = off + sh[1023];
        __syncthreads();
    }
}
__global__ void csr_fill_kernel(const int* __restrict__ ei) {
    int e = blockIdx.x * blockDim.x + threadIdx.x;
    if (e < EE) {
        int r = ei[e];
        int c = ei[EE + e];
        int pos = g_ptr[c] + atomicAdd(&g_cursor[c], 1);
        g_csrsrc[pos] = r;
    }
}

// ---------------- fused operand prep ----------------
#define S0 (NN * K1PAD)                   // pad_x
#define S1 ((K1PAD / 2) * 312)            // W1 pack
#define S2 ((D2 / 2) * D3)                // W2 pack
#define S3 ((D3 / 2) * D3)                // W3 pack
#define S4 ((D3 / 2) * HID)               // fc1 pack
#define S5 ((HID / 2) * OUTD)             // fc2 pack
#define PREP_TOTAL (S0 + S1 + S2 + S3 + S4 + S5)

__device__ __forceinline__ void pack_one(const float* W, uint32_t* dst,
                                         int idx, int KREAL, int N, int NP) {
    int kk = idx / N, n = idx - kk * N;
    float v0 = (2 * kk     < KREAL) ? W[(size_t)(2 * kk) * N + n] : 0.f;
    float v1 = (2 * kk + 1 < KREAL) ? W[(size_t)(2 * kk + 1) * N + n] : 0.f;
    __half2 h = __floats2half2_rn(v0, v1);
    dst[(size_t)kk * NP + n] = *(uint32_t*)&h;
}

__global__ void prep_pack(const float* __restrict__ x,
                          const float* __restrict__ W1,
                          const float* __restrict__ W2,
                          const float* __restrict__ W3,
                          const float* __restrict__ fc1w,
                          const float* __restrict__ fc2w)
{
    int idx = blockIdx.x * blockDim.x + threadIdx.x;
    if (idx < S0) {
        int n = idx / K1PAD, k = idx - n * K1PAD;
        g_xpad_h[idx] = __float2half_rn((k < D1) ? x[(size_t)n * D1 + k] : 0.f);
        return;
    }
    idx -= S0;
    if (idx < S1) { pack_one(W1, g_w1p, idx, D1, 312, NP1); return; }
    idx -= S1;
    if (idx < S2) { pack_one(W2, g_w2p, idx, D2, D3, NP23); return; }
    idx -= S2;
    if (idx < S3) { pack_one(W3, g_w3p, idx, D3, D3, NP23); return; }
    idx -= S3;
    if (idx < S4) { pack_one(fc1w, g_fc1p, idx, D3, HID, HID); return; }
    idx -= S4;
    if (idx < S5) { pack_one(fc2w, g_fc2p, idx, HID, OUTD, OUTD); }
}

// score columns for all 3 layers, one warp per packed output word
#define WS1 (((K1PAD / 2)) * 8)    // 320
#define WS2 (((D2 / 2)) * 8)       // 1248
#define WS3 (((D3 / 2)) * 8)       // 4992
#define WS_TOTAL (WS1 + WS2 + WS3)

__global__ void ws_all(const float* __restrict__ W1,
                       const float* __restrict__ as1, const float* __restrict__ ad1,
                       const float* __restrict__ W2,
                       const float* __restrict__ as2, const float* __restrict__ ad2,
                       const float* __restrict__ W3,
                       const float* __restrict__ as3, const float* __restrict__ ad3)
{
    int warp = (blockIdx.x * blockDim.x + threadIdx.x) >> 5;
    int lane = threadIdx.x & 31;
    if (warp >= WS_TOTAL) return;

    const float *W, *att_s, *att_d;
    uint32_t* dst;
    int C, H, N, NP, KREAL, w;
    if (warp < WS1) {
        w = warp; W = W1; att_s = as1; att_d = ad1;
        C = D1; H = HEADS; N = 312; NP = NP1; KREAL = D1;
        dst = g_w1p;
    } else if (warp < WS1 + WS2) {
        w = warp - WS1; W = W2; att_s = as2; att_d = ad2;
        C = D2; H = HEADS; N = D3; NP = NP23; KREAL = D2;
        dst = g_w2p;
    } else {
        w = warp - WS1 - WS2; W = W3; att_s = as3; att_d = ad3;
        C = D3; H = 1; N = D3; NP = NP23; KREAL = D3;
        dst = g_w3p;
    }
    int kk = w >> 3, slot = w & 7;
    int h = slot & 3;
    const float* att = (slot >= 4) ? att_d : att_s;

    float v0 = 0.f, v1 = 0.f;
    if (h < H) {
        const float* ar = att + h * C;
        const float* w0 = W + (size_t)(2 * kk) * N + h * C;
        const float* w1 = W + (size_t)(2 * kk + 1) * N + h * C;
        bool ok0 = (2 * kk < KREAL), ok1 = (2 * kk + 1 < KREAL);
        for (int c = lane; c < C; c += 32) {
            float a = ar[c];
            if (ok0) v0 = fmaf(w0[c], a, v0);
            if (ok1) v1 = fmaf(w1[c], a, v1);
        }
#pragma unroll
        for (int o = 16; o; o >>= 1) {
            v0 += __shfl_down_sync(0xFFFFFFFFu, v0, o);
            v1 += __shfl_down_sync(0xFFFFFFFFu, v1, o);
        }
    }
    if (lane == 0) {
        __half2 hp = __floats2half2_rn(v0, v1);
        dst[(size_t)kk * NP + N + slot] = *(uint32_t*)&hp;
    }
}

// ---------------- FP16 GEMM (mma.m16n8k16, cp.async 3-stage) ----------------
__device__ __forceinline__ void mma_fp16(float c[4], const uint32_t a[4],
                                         uint32_t b0, uint32_t b1)
{
    asm volatile(
        "mma.sync.aligned.m16n8k16.row.col.f32.f16.f16.f32 "
        "{%0,%1,%2,%3}, {%4,%5,%6,%7}, {%8,%9}, {%0,%1,%2,%3};"
        : "+f"(c[0]), "+f"(c[1]), "+f"(c[2]), "+f"(c[3])
        : "r"(a[0]), "r"(a[1]), "r"(a[2]), "r"(a[3]), "r"(b0), "r"(b1));
}

#define CA_AP    20
#define CA_ASZ   (128 * CA_AP)
#define CA_BP    136
#define CA_BSZ   (16 * CA_BP)
#define CA_STW   (CA_ASZ + CA_BSZ)
#define CA_SMEM_BYTES (3 * CA_STW * 4)

template<int FUSE, int OUTF32>
__global__ void __launch_bounds__(256)
hgemm_ca(int Asel, int Bsel, float* Cext, int Csel, int M, int N, int K,
         const float* __restrict__ bias)
{
    extern __shared__ uint32_t smw[];
    uint32_t sb = (uint32_t)__cvta_generic_to_shared(smw);

    const __half* A = sel_h(Asel);
    const uint32_t* Bp = sel_w(Bsel);
    __half* Ch = sel_hw(Csel);

    int tid = threadIdx.x;
    int warpid = tid >> 5, lane = tid & 31;
    int bm = blockIdx.y * 128, bn = blockIdx.x * 128;
    int wm = (warpid >> 1) * 32;
    int wn = (warpid & 1) * 64;
    int grp = lane >> 2, tig = lane & 3;

    float cacc[2][8][4];
#pragma unroll
    for (int mf = 0; mf < 2; mf++)
#pragma unroll
        for (int nf = 0; nf < 8; nf++)
#pragma unroll
            for (int q = 0; q < 4; q++) cacc[mf][nf][q] = 0.f;

    int steps = (K + 31) >> 5;
    int K2 = K >> 1;

    auto issue = [&](int st, int k0) {
        uint32_t abase = sb + (uint32_t)(st * CA_STW) * 4;
        uint32_t bbase = abase + CA_ASZ * 4;
#pragma unroll
        for (int q = 0; q < 2; q++) {
            int flat = q * 256 + tid;
            int row = flat >> 2, kc = (flat & 3) * 8;
            int gm = bm + row, gk = k0 + kc;
            bool p = (gm < M) && (gk < K);
            const __half* src = p ? (A + (size_t)gm * K + gk) : A;
            uint32_t dst = abase + (uint32_t)(row * CA_AP + (kc >> 1)) * 4;
            uint32_t sz = p ? 16u : 0u;
            asm volatile("cp.async.cg.shared.global [%0], [%1], 16, %2;"
                         :: "r"(dst), "l"(src), "r"(sz));
        }
#pragma unroll
        for (int q = 0; q < 2; q++) {
            int flat = q * 256 + tid;
            int kkw = flat >> 5, n4 = (flat & 31) * 4;
            int gkk = (k0 >> 1) + kkw, gn = bn + n4;
            bool p = (gkk < K2) && (gn < N);
            const uint32_t* src = p ? (Bp + (size_t)gkk * N + gn) : Bp;
            uint32_t dst = bbase + (uint32_t)(kkw * CA_BP + n4) * 4;
            uint32_t sz = p ? 16u : 0u;
            asm volatile("cp.async.cg.shared.global [%0], [%1], 16, %2;"
                         :: "r"(dst), "l"(src), "r"(sz));
        }
        asm volatile("cp.async.commit_group;");
    };

    issue(0, 0);
    if (steps > 1) issue(1, 32);

    for (int s = 0; s < steps; s++) {
        int buf = s % 3;
        if (s + 1 < steps) asm volatile("cp.async.wait_group 1;");
        else               asm volatile("cp.async.wait_group 0;");
        __syncthreads();
        if (s + 2 < steps) issue((s + 2) % 3, (s + 2) << 5);

        const uint32_t* as = smw + buf * CA_STW;
        const uint32_t* bs = as + CA_ASZ;
#pragma unroll
        for (int kf = 0; kf < 2; kf++) {
            int kw = kf * 8;
            uint32_t af[2][4];
#pragma unroll
            for (int mf = 0; mf < 2; mf++) {
                int m0 = wm + mf * 16;
                af[mf][0] = as[(m0 + grp    ) * CA_AP + kw + tig    ];
                af[mf][1] = as[(m0 + grp + 8) * CA_AP + kw + tig    ];
                af[mf][2] = as[(m0 + grp    ) * CA_AP + kw + tig + 4];
                af[mf][3] = as[(m0 + grp + 8) * CA_AP + kw + tig + 4];
            }
#pragma unroll
            for (int nf = 0; nf < 8; nf++) {
                int n0 = wn + nf * 8 + grp;
                uint32_t b0 = bs[(kw + tig    ) * CA_BP + n0];
                uint32_t b1 = bs[(kw + tig + 4) * CA_BP + n0];
                mma_fp16(cacc[0][nf], af[0], b0, b1);
                mma_fp16(cacc[1][nf], af[1], b0, b1);
            }
        }
    }

#pragma unroll
    for (int mf = 0; mf < 2; mf++) {
#pragma unroll
        for (int nf = 0; nf < 8; nf++) {
            int r0 = bm + wm + mf * 16 + grp;
            int c0 = bn + wn + nf * 8 + tig * 2;
            float c[4] = { cacc[mf][nf][0], cacc[mf][nf][1],
                           cacc[mf][nf][2], cacc[mf][nf][3] };
            if (FUSE) {
                float b0 = (c0     < N) ? bias[c0]     : 0.f;
                float b1 = (c0 + 1 < N) ? bias[c0 + 1] : 0.f;
                c[0] = fmaxf(c[0] + b0, 0.f);
                c[1] = fmaxf(c[1] + b1, 0.f);
                c[2] = fmaxf(c[2] + b0, 0.f);
                c[3] = fmaxf(c[3] + b1, 0.f);
            }
            if (c0 < N) {
                if (OUTF32) {
                    if (r0 < M)     *(float2*)&Cext[(size_t)r0 * N + c0] = make_float2(c[0], c[1]);
                    if (r0 + 8 < M) *(float2*)&Cext[(size_t)(r0 + 8) * N + c0] = make_float2(c[2], c[3]);
                } else {
                    if (r0 < M) {
                        __half2 h = __floats2half2_rn(c[0], c[1]);
                        *(uint32_t*)&Ch[(size_t)r0 * N + c0] = *(uint32_t*)&h;
                    }
                    if (r0 + 8 < M) {
                        __half2 h = __floats2half2_rn(c[2], c[3]);
                        *(uint32_t*)&Ch[(size_t)(r0 + 8) * N + c0] = *(uint32_t*)&h;
                    }
                }
            }
        }
    }
}

// ---------------- GAT aggregation (fp16 rows, 2-edge-deep pipeline) --------
template<int H, int C, int NP, int NV>
__global__ void __launch_bounds__(128)
gat_agg_h(const float* __restrict__ bias)
{
    constexpr int HC  = H * C;
    constexpr int HC8 = HC / 8;
    constexpr int CHUNK = 64;
    int i = blockIdx.x;
    int tid = threadIdx.x;

    __shared__ float s_sc[CHUNK][4];
    __shared__ float s_alpha[CHUNK][4];
    __shared__ int   s_src[CHUNK];

    const __half* hbuf = g_bufB_h;
    __half* out = g_bufA_h;
    const __half* row = hbuf + (size_t)i * NP;

    float scS[4], scD[4];
    {
        uint4 v = *(const uint4*)&row[HC];
        __half2* p = (__half2*)&v;
        float2 f0 = __half22float2(p[0]), f1 = __half22float2(p[1]);
        float2 f2 = __half22float2(p[2]), f3 = __half22float2(p[3]);
        scS[0] = f0.x; scS[1] = f0.y; scS[2] = f1.x; scS[3] = f1.y;
        scD[0] = f2.x; scD[1] = f2.y; scD[2] = f3.x; scD[3] = f3.y;
    }

    float adsti[H], m[H], den[H], eself[H], aself[H];
#pragma unroll
    for (int h = 0; h < H; h++) {
        adsti[h] = scD[h];
        eself[h] = lrelu(scS[h] + adsti[h]);
        m[h] = eself[h];
        den[h] = 1.f;
    }

    int beg = g_ptr[i];
    int deg = g_ptr[i + 1] - beg;
    bool single = (deg <= CHUNK);

    for (int cb = 0; cb < deg; cb += CHUNK) {
        int cn = min(CHUNK, deg - cb);
        if (tid < cn) {
            int s = g_csrsrc[beg + cb + tid];
            s_src[tid] = s;
            uint2 v = *(const uint2*)&hbuf[(size_t)s * NP + HC];
            __half2* p = (__half2*)&v;
            float2 f0 = __half22float2(p[0]), f1 = __half22float2(p[1]);
            s_sc[tid][0] = f0.x; s_sc[tid][1] = f0.y;
            s_sc[tid][2] = f1.x; s_sc[tid][3] = f1.y;
        }
        __syncthreads();
        for (int j = 0; j < cn; j++) {
#pragma unroll
            for (int h = 0; h < H; h++) {
                float e = lrelu(s_sc[j][h] + adsti[h]);
                float mo = m[h];
                float mn = fmaxf(mo, e);
                den[h] = den[h] * __expf(mo - mn) + __expf(e - mn);
                m[h] = mn;
            }
        }
        __syncthreads();
    }
#pragma unroll
    for (int h = 0; h < H; h++)
        aself[h] = __expf(eself[h] - m[h]) / (den[h] + 1e-16f);

    int c8i[NV];
    bool val[NV];
    int he[NV][8];
#pragma unroll
    for (int t = 0; t < NV; t++) {
        int c8 = tid + t * 128;
        c8i[t] = c8;
        val[t] = (c8 < HC8);
#pragma unroll
        for (int e = 0; e < 8; e++)
            he[t][e] = min((c8 * 8 + e) / C, H - 1);
    }

    float acc[NV][8];
#pragma unroll
    for (int t = 0; t < NV; t++) {
        if (val[t]) {
            uint4 v = *(const uint4*)&row[c8i[t] * 8];
            __half2* p = (__half2*)&v;
            float2 q0 = __half22float2(p[0]), q1 = __half22float2(p[1]);
            float2 q2 = __half22float2(p[2]), q3 = __half22float2(p[3]);
            float f[8] = { q0.x, q0.y, q1.x, q1.y, q2.x, q2.y, q3.x, q3.y };
#pragma unroll
            for (int e = 0; e < 8; e++) acc[t][e] = aself[he[t][e]] * f[e];
        } else {
#pragma unroll
            for (int e = 0; e < 8; e++) acc[t][e] = 0.f;
        }
    }

    for (int cb = 0; cb < deg; cb += CHUNK) {
        int cn = min(CHUNK, deg - cb);
        __syncthreads();
        if (!single && tid < cn) {
            int s = g_csrsrc[beg + cb + tid];
            s_src[tid] = s;
            uint2 v = *(const uint2*)&hbuf[(size_t)s * NP + HC];
            __half2* p = (__half2*)&v;
            float2 f0 = __half22float2(p[0]), f1 = __half22float2(p[1]);
            s_sc[tid][0] = f0.x; s_sc[tid][1] = f0.y;
            s_sc[tid][2] = f1.x; s_sc[tid][3] = f1.y;
        }
        if (!single) __syncthreads();
        if (tid < cn) {
#pragma unroll
            for (int h = 0; h < H; h++) {
                float e = lrelu(s_sc[tid][h] + adsti[h]);
                s_alpha[tid][h] = __expf(e - m[h]) / (den[h] + 1e-16f);
            }
        }
        __syncthreads();

        // 2-edge-deep software pipeline
        uint4 nxt0[NV], nxt1[NV];
        {
            const uint4* h0p = (const uint4*)(hbuf + (size_t)s_src[0] * NP);
            const uint4* h1p = (const uint4*)(hbuf + (size_t)s_src[cn > 1 ? 1 : 0] * NP);
#pragma unroll
            for (int t = 0; t < NV; t++) {
                if (val[t]) { nxt0[t] = h0p[c8i[t]]; nxt1[t] = h1p[c8i[t]]; }
            }
        }
        for (int j = 0; j < cn; j += 2) {
            uint4 cur0[NV], cur1[NV];
#pragma unroll
            for (int t = 0; t < NV; t++) { cur0[t] = nxt0[t]; cur1[t] = nxt1[t]; }
            if (j + 2 < cn) {
                const uint4* h0p = (const uint4*)(hbuf + (size_t)s_src[j + 2] * NP);
                const uint4* h1p = (const uint4*)(hbuf + (size_t)s_src[j + 3 < cn ? j + 3 : j + 2] * NP);
#pragma unroll
                for (int t = 0; t < NV; t++) {
                    if (val[t]) { nxt0[t] = h0p[c8i[t]]; nxt1[t] = h1p[c8i[t]]; }
                }
            }
            {
                float a0 = s_alpha[j][0];
                float a1 = (H > 1) ? s_alpha[j][1] : a0;
                float a2 = (H > 2) ? s_alpha[j][2] : a0;
                float a3 = (H > 3) ? s_alpha[j][3] : a0;
                float al[4] = { a0, a1, a2, a3 };
#pragma unroll
                for (int t = 0; t < NV; t++) {
                    if (!val[t]) continue;
                    __half2* p = (__half2*)&cur0[t];
                    float2 q0 = __half22float2(p[0]), q1 = __half22float2(p[1]);
                    float2 q2 = __half22float2(p[2]), q3 = __half22float2(p[3]);
                    float f[8] = { q0.x, q0.y, q1.x, q1.y, q2.x, q2.y, q3.x, q3.y };
#pragma unroll
                    for (int e = 0; e < 8; e++)
                        acc[t][e] = fmaf(al[he[t][e]], f[e], acc[t][e]);
                }
            }
            if (j + 1 < cn) {
                float a0 = s_alpha[j + 1][0];
                float a1 = (H > 1) ? s_alpha[j + 1][1] : a0;
                float a2 = (H > 2) ? s_alpha[j + 1][2] : a0;
                float a3 = (H > 3) ? s_alpha[j + 1][3] : a0;
                float al[4] = { a0, a1, a2, a3 };
#pragma unroll
                for (int t = 0; t < NV; t++) {
                    if (!val[t]) continue;
                    __half2* p = (__half2*)&cur1[t];
                    float2 q0 = __half22float2(p[0]), q1 = __half22float2(p[1]);
                    float2 q2 = __half22float2(p[2]), q3 = __half22float2(p[3]);
                    float f[8] = { q0.x, q0.y, q1.x, q1.y, q2.x, q2.y, q3.x, q3.y };
#pragma unroll
                    for (int e = 0; e < 8; e++)
                        acc[t][e] = fmaf(al[he[t][e]], f[e], acc[t][e]);
                }
            }
        }
    }

    __half* orow = out + (size_t)i * HC;
#pragma unroll
    for (int t = 0; t < NV; t++) {
        if (!val[t]) continue;
        int cb0 = c8i[t] * 8;
        float4 b0 = *(const float4*)&bias[cb0];
        float4 b1 = *(const float4*)&bias[cb0 + 4];
        float o[8];
        o[0] = fmaxf(acc[t][0] + b0.x, 0.f);
        o[1] = fmaxf(acc[t][1] + b0.y, 0.f);
        o[2] = fmaxf(acc[t][2] + b0.z, 0.f);
        o[3] = fmaxf(acc[t][3] + b0.w, 0.f);
        o[4] = fmaxf(acc[t][4] + b1.x, 0.f);
        o[5] = fmaxf(acc[t][5] + b1.y, 0.f);
        o[6] = fmaxf(acc[t][6] + b1.z, 0.f);
        o[7] = fmaxf(acc[t][7] + b1.w, 0.f);
        uint4 ov;
        __half2 h0 = __floats2half2_rn(o[0], o[1]);
        __half2 h1 = __floats2half2_rn(o[2], o[3]);
        __half2 h2 = __floats2half2_rn(o[4], o[5]);
        __half2 h3 = __floats2half2_rn(o[6], o[7]);
        ov.x = *(uint32_t*)&h0; ov.y = *(uint32_t*)&h1;
        ov.z = *(uint32_t*)&h2; ov.w = *(uint32_t*)&h3;
        *(uint4*)&orow[cb0] = ov;
    }
}

// ---------------- pool ----------------
__global__ void pool_max(const int* __restrict__ batch)
{
    int g = blockIdx.x;
    int c8 = blockIdx.y * 128 + threadIdx.x;

    int lo = 0, hi = NN;
    while (lo < hi) { int mid = (lo + hi) >> 1; if (batch[mid] < g) lo = mid + 1; else hi = mid; }
    int start = lo;
    lo = start; hi = NN;
    while (lo < hi) { int mid = (lo + hi) >> 1; if (batch[mid] < g + 1) lo = mid + 1; else hi = mid; }
    int end = lo;

    if (c8 < D3 / 8) {
        float mv[8];
#pragma unroll
        for (int e = 0; e < 8; e++) mv[e] = 0.f;
        for (int n = start; n < end; n++) {
            uint4 v = *(const uint4*)&g_bufA_h[(size_t)n * D3 + c8 * 8];
            __half2* p = (__half2*)&v;
            float2 q0 = __half22float2(p[0]), q1 = __half22float2(p[1]);
            float2 q2 = __half22float2(p[2]), q3 = __half22float2(p[3]);
            mv[0] = fmaxf(mv[0], q0.x); mv[1] = fmaxf(mv[1], q0.y);
            mv[2] = fmaxf(mv[2], q1.x); mv[3] = fmaxf(mv[3], q1.y);
            mv[4] = fmaxf(mv[4], q2.x); mv[5] = fmaxf(mv[5], q2.y);
            mv[6] = fmaxf(mv[6], q3.x); mv[7] = fmaxf(mv[7], q3.y);
        }
        uint4 ov;
        __half2 h0 = __floats2half2_rn(mv[0], mv[1]);
        __half2 h1 = __floats2half2_rn(mv[2], mv[3]);
        __half2 h2 = __floats2half2_rn(mv[4], mv[5]);
        __half2 h3 = __floats2half2_rn(mv[6], mv[7]);
        ov.x = *(uint32_t*)&h0; ov.y = *(uint32_t*)&h1;
        ov.z = *(uint32_t*)&h2; ov.w = *(uint32_t*)&h3;
        *(uint4*)&g_pool_h[g * D3 + c8 * 8] = ov;
    }
}

// ---------------- launch ----------------
extern "C" void kernel_launch(void* const* d_in, const int* in_sizes, int n_in,
                              void* d_out, int out_size)
{
    const float* x     = (const float*)d_in[0];
    const int*   ei    = (const int*)d_in[1];
    const int*   batch = (const int*)d_in[2];
    const float* W1 = (const float*)d_in[3];
    const float* as1 = (const float*)d_in[4];
    const float* ad1 = (const float*)d_in[5];
    const float* b1 = (const float*)d_in[6];
    const float* W2 = (const float*)d_in[7];
    const float* as2 = (const float*)d_in[8];
    const float* ad2 = (const float*)d_in[9];
    const float* b2 = (const float*)d_in[10];
    const float* W3 = (const float*)d_in[11];
    const float* as3 = (const float*)d_in[12];
    const float* ad3 = (const float*)d_in[13];
    const float* b3 = (const float*)d_in[14];
    const float* fc1_w = (const float*)d_in[15];
    const float* fc1_b = (const float*)d_in[16];
    const float* fc2_w = (const float*)d_in[17];
    const float* fc2_b = (const float*)d_in[18];
    float* outp = (float*)d_out;

    cudaFuncSetAttribute(hgemm_ca<0, 0>,
                         cudaFuncAttributeMaxDynamicSharedMemorySize, CA_SMEM_BYTES);
    cudaFuncSetAttribute(hgemm_ca<1, 0>,
                         cudaFuncAttributeMaxDynamicSharedMemorySize, CA_SMEM_BYTES);
    cudaFuncSetAttribute(hgemm_ca<1, 1>,
                         cudaFuncAttributeMaxDynamicSharedMemorySize, CA_SMEM_BYTES);

    // CSR + fused prep
    zero_counts_kernel<<<(NN + 255) / 256, 256>>>();
    hist_kernel<<<(EE + 255) / 256, 256>>>(ei);
    scan_kernel<<<1, 1024>>>();
    csr_fill_kernel<<<(EE + 255) / 256, 256>>>(ei);
    prep_pack<<<(PREP_TOTAL + 255) / 256, 256>>>(x, W1, W2, W3, fc1_w, fc2_w);
    ws_all<<<(WS_TOTAL * 32 + 255) / 256, 256>>>(W1, as1, ad1, W2, as2, ad2, W3, as3, ad3);

    dim3 blk(256);
    {
        dim3 grid((NP1 + 127) / 128, (NN + 127) / 128);
        hgemm_ca<0, 0><<<grid, blk, CA_SMEM_BYTES>>>(5, 7, nullptr, 2, NN, NP1, K1PAD, nullptr);
        gat_agg_h<HEADS, D1, NP1, 1><<<NN, 128>>>(b1);
    }
    {
        dim3 grid((NP23 + 127) / 128, (NN + 127) / 128);
        hgemm_ca<0, 0><<<grid, blk, CA_SMEM_BYTES>>>(1, 8, nullptr, 2, NN, NP23, D2, nullptr);
        gat_agg_h<HEADS, D2, NP23, 2><<<NN, 128>>>(b2);
    }
    {
        dim3 grid((NP23 + 127) / 128, (NN + 127) / 128);
        hgemm_ca<0, 0><<<grid, blk, CA_SMEM_BYTES>>>(1, 9, nullptr, 2, NN, NP23, D3, nullptr);
        gat_agg_h<1, D3, NP23, 2><<<NN, 128>>>(b3);
    }
    {
        dim3 pg(GG, (D3 / 8 + 127) / 128);
        pool_max<<<pg, 128>>>(batch);
        dim3 g1((HID + 127) / 128, (GG + 127) / 128);
        hgemm_ca<1, 0><<<g1, blk, CA_SMEM_BYTES>>>(3, 10, nullptr, 4, GG, HID, D3, fc1_b);
        dim3 g2((OUTD + 127) / 128, (GG + 127) / 128);
        hgemm_ca<1, 1><<<g2, blk, CA_SMEM_BYTES>>>(4, 11, outp, 0, GG, OUTD, HID, fc2_b);
    }
    (void)n_in; (void)in_sizes; (void)out_size;
}

// round 15
// speedup vs baseline: 5.1978x; 1.0857x over previous
#include <cuda_runtime.h>
#include <cuda_fp16.h>
#include <math.h>
#include <stdint.h>

#define NN     50000
#define EE     200000
#define HEADS  4
#define GG     512
#define HID    1024
#define OUTD   128
#define D1     78
#define D2     312
#define D3     1248
#define NEG    0.2f
#define K1PAD  80
#define NP1    320
#define NP23   1256

__device__ __align__(16) __half g_bufA_h[(size_t)NN * D3];
__device__ __align__(16) __half g_bufB_h[(size_t)NN * NP23];
__device__ __align__(16) __half g_xpad_h[(size_t)NN * K1PAD];
__device__ __align__(16) __half g_pool_h[GG * D3];
__device__ __align__(16) __half g_fc1_h[GG * HID];
__device__ __align__(16) uint32_t g_w1p[(K1PAD / 2) * NP1];
__device__ __align__(16) uint32_t g_w2p[(D2 / 2) * NP23];
__device__ __align__(16) uint32_t g_w3p[(size_t)(D3 / 2) * NP23];
__device__ __align__(16) uint32_t g_fc1p[(D3 / 2) * HID];
__device__ __align__(16) uint32_t g_fc2p[(HID / 2) * OUTD];
__device__ int   g_counts[NN];
__device__ int   g_cursor[NN];
__device__ int   g_ptr[NN + 1];
__device__ int   g_csrsrc[EE];

__device__ __forceinline__ float lrelu(float x) { return x > 0.f ? x : NEG * x; }

__device__ __forceinline__ const __half* sel_h(int s) {
    switch (s) {
        case 1: return g_bufA_h;
        case 2: return g_bufB_h;
        case 3: return g_pool_h;
        case 4: return g_fc1_h;
        case 5: return g_xpad_h;
        default: return g_bufA_h;
    }
}
__device__ __forceinline__ __half* sel_hw(int s) {
    switch (s) {
        case 1: return g_bufA_h;
        case 2: return g_bufB_h;
        case 3: return g_pool_h;
        case 4: return g_fc1_h;
        default: return g_bufA_h;
    }
}
__device__ __forceinline__ const uint32_t* sel_w(int s) {
    switch (s) {
        case 7:  return g_w1p;
        case 8:  return g_w2p;
        case 9:  return g_w3p;
        case 10: return g_fc1p;
        default: return g_fc2p;
    }
}

// ---------------- CSR ----------------
__global__ void zero_counts_kernel() {
    int i = blockIdx.x * blockDim.x + threadIdx.x;
    if (i < NN) { g_counts[i] = 0; g_cursor[i] = 0; }
}
__global__ void hist_kernel(const int* __restrict__ ei) {
    int e = blockIdx.x * blockDim.x + threadIdx.x;
    if (e < EE) atomicAdd(&g_counts[ei[EE + e]], 1);
}
__global__ void scan_kernel() {
    __shared__ int sh[1024];
    __shared__ int s_off;
    int tid = threadIdx.x;
    if (tid == 0) { s_off = 0; g_ptr[0] = 0; }
    __syncthreads();
    for (int base = 0; base < NN; base += 1024) {
        int v = (base + tid < NN) ? g_counts[base + tid] : 0;
        sh[tid] = v;
        __syncthreads();
        for (int s = 1; s < 1024; s <<= 1) {
            int t = (tid >= s) ? sh[tid - s] : 0;
            __syncthreads();
            sh[tid] += t;
            __syncthreads();
        }
        int off = s_off;
        if (base + tid < NN) g_ptr[base + tid + 1] = off + sh[tid];
        __syncthreads();
        if (tid == 0) s_off = off + sh[1023];
        __syncthreads();
    }
}
__global__ void csr_fill_kernel(const int* __restrict__ ei) {
    int e = blockIdx.x * blockDim.x + threadIdx.x;
    if (e < EE) {
        int r = ei[e];
        int c = ei[EE + e];
        int pos = g_ptr[c] + atomicAdd(&g_cursor[c], 1);
        g_csrsrc[pos] = r;
    }
}

// ---------------- fused operand prep ----------------
#define S0 (NN * K1PAD)
#define S1 ((K1PAD / 2) * 312)
#define S2 ((D2 / 2) * D3)
#define S3 ((D3 / 2) * D3)
#define S4 ((D3 / 2) * HID)
#define S5 ((HID / 2) * OUTD)
#define PREP_TOTAL (S0 + S1 + S2 + S3 + S4 + S5)

__device__ __forceinline__ void pack_one(const float* W, uint32_t* dst,
                                         int idx, int KREAL, int N, int NP) {
    int kk = idx / N, n = idx - kk * N;
    float v0 = (2 * kk     < KREAL) ? W[(size_t)(2 * kk) * N + n] : 0.f;
    float v1 = (2 * kk + 1 < KREAL) ? W[(size_t)(2 * kk + 1) * N + n] : 0.f;
    __half2 h = __floats2half2_rn(v0, v1);
    dst[(size_t)kk * NP + n] = *(uint32_t*)&h;
}

__global__ void prep_pack(const float* __restrict__ x,
                          const float* __restrict__ W1,
                          const float* __restrict__ W2,
                          const float* __restrict__ W3,
                          const float* __restrict__ fc1w,
                          const float* __restrict__ fc2w)
{
    int idx = blockIdx.x * blockDim.x + threadIdx.x;
    if (idx < S0) {
        int n = idx / K1PAD, k = idx - n * K1PAD;
        g_xpad_h[idx] = __float2half_rn((k < D1) ? x[(size_t)n * D1 + k] : 0.f);
        return;
    }
    idx -= S0;
    if (idx < S1) { pack_one(W1, g_w1p, idx, D1, 312, NP1); return; }
    idx -= S1;
    if (idx < S2) { pack_one(W2, g_w2p, idx, D2, D3, NP23); return; }
    idx -= S2;
    if (idx < S3) { pack_one(W3, g_w3p, idx, D3, D3, NP23); return; }
    idx -= S3;
    if (idx < S4) { pack_one(fc1w, g_fc1p, idx, D3, HID, HID); return; }
    idx -= S4;
    if (idx < S5) { pack_one(fc2w, g_fc2p, idx, HID, OUTD, OUTD); }
}

#define WS1 (((K1PAD / 2)) * 8)
#define WS2 (((D2 / 2)) * 8)
#define WS3 (((D3 / 2)) * 8)
#define WS_TOTAL (WS1 + WS2 + WS3)

__global__ void ws_all(const float* __restrict__ W1,
                       const float* __restrict__ as1, const float* __restrict__ ad1,
                       const float* __restrict__ W2,
                       const float* __restrict__ as2, const float* __restrict__ ad2,
                       const float* __restrict__ W3,
                       const float* __restrict__ as3, const float* __restrict__ ad3)
{
    int warp = (blockIdx.x * blockDim.x + threadIdx.x) >> 5;
    int lane = threadIdx.x & 31;
    if (warp >= WS_TOTAL) return;

    const float *W, *att_s, *att_d;
    uint32_t* dst;
    int C, H, N, NP, KREAL, w;
    if (warp < WS1) {
        w = warp; W = W1; att_s = as1; att_d = ad1;
        C = D1; H = HEADS; N = 312; NP = NP1; KREAL = D1;
        dst = g_w1p;
    } else if (warp < WS1 + WS2) {
        w = warp - WS1; W = W2; att_s = as2; att_d = ad2;
        C = D2; H = HEADS; N = D3; NP = NP23; KREAL = D2;
        dst = g_w2p;
    } else {
        w = warp - WS1 - WS2; W = W3; att_s = as3; att_d = ad3;
        C = D3; H = 1; N = D3; NP = NP23; KREAL = D3;
        dst = g_w3p;
    }
    int kk = w >> 3, slot = w & 7;
    int h = slot & 3;
    const float* att = (slot >= 4) ? att_d : att_s;

    float v0 = 0.f, v1 = 0.f;
    if (h < H) {
        const float* ar = att + h * C;
        const float* w0 = W + (size_t)(2 * kk) * N + h * C;
        const float* w1 = W + (size_t)(2 * kk + 1) * N + h * C;
        bool ok0 = (2 * kk < KREAL), ok1 = (2 * kk + 1 < KREAL);
        for (int c = lane; c < C; c += 32) {
            float a = ar[c];
            if (ok0) v0 = fmaf(w0[c], a, v0);
            if (ok1) v1 = fmaf(w1[c], a, v1);
        }
#pragma unroll
        for (int o = 16; o; o >>= 1) {
            v0 += __shfl_down_sync(0xFFFFFFFFu, v0, o);
            v1 += __shfl_down_sync(0xFFFFFFFFu, v1, o);
        }
    }
    if (lane == 0) {
        __half2 hp = __floats2half2_rn(v0, v1);
        dst[(size_t)kk * NP + N + slot] = *(uint32_t*)&hp;
    }
}

// ---------------- FP16 GEMM (mma.m16n8k16, cp.async, ldmatrix A) -----------
__device__ __forceinline__ void mma_fp16(float c[4], const uint32_t a[4],
                                         uint32_t b0, uint32_t b1)
{
    asm volatile(
        "mma.sync.aligned.m16n8k16.row.col.f32.f16.f16.f32 "
        "{%0,%1,%2,%3}, {%4,%5,%6,%7}, {%8,%9}, {%0,%1,%2,%3};"
        : "+f"(c[0]), "+f"(c[1]), "+f"(c[2]), "+f"(c[3])
        : "r"(a[0]), "r"(a[1]), "r"(a[2]), "r"(a[3]), "r"(b0), "r"(b1));
}

#define CA_AP    20
#define CA_ASZ   (128 * CA_AP)
#define CA_BP    136
#define CA_BSZ   (16 * CA_BP)
#define CA_STW   (CA_ASZ + CA_BSZ)
#define CA_SMEM_BYTES (3 * CA_STW * 4)

template<int FUSE, int OUTF32>
__global__ void __launch_bounds__(256)
hgemm_ca(int Asel, int Bsel, float* Cext, int Csel, int M, int N, int K,
         const float* __restrict__ bias)
{
    extern __shared__ uint32_t smw[];
    uint32_t sb = (uint32_t)__cvta_generic_to_shared(smw);

    const __half* A = sel_h(Asel);
    const uint32_t* Bp = sel_w(Bsel);
    __half* Ch = sel_hw(Csel);

    int tid = threadIdx.x;
    int warpid = tid >> 5, lane = tid & 31;
    int bm = blockIdx.y * 128, bn = blockIdx.x * 128;
    int wm = (warpid >> 1) * 32;
    int wn = (warpid & 1) * 64;
    int grp = lane >> 2, tig = lane & 3;

    // ldmatrix lane mapping for A (m16k16 .x4)
    int lm_row = (lane & 7) + ((lane >> 3) & 1) * 8;   // m offset within 16
    int lm_kw  = ((lane >> 4) & 1) * 4;                // +0 or +4 words (k half)

    float cacc[2][8][4];
#pragma unroll
    for (int mf = 0; mf < 2; mf++)
#pragma unroll
        for (int nf = 0; nf < 8; nf++)
#pragma unroll
            for (int q = 0; q < 4; q++) cacc[mf][nf][q] = 0.f;

    int steps = (K + 31) >> 5;
    int K2 = K >> 1;

    auto issue = [&](int st, int k0) {
        uint32_t abase = sb + (uint32_t)(st * CA_STW) * 4;
        uint32_t bbase = abase + CA_ASZ * 4;
#pragma unroll
        for (int q = 0; q < 2; q++) {
            int flat = q * 256 + tid;
            int row = flat >> 2, kc = (flat & 3) * 8;
            int gm = bm + row, gk = k0 + kc;
            bool p = (gm < M) && (gk < K);
            const __half* src = p ? (A + (size_t)gm * K + gk) : A;
            uint32_t dst = abase + (uint32_t)(row * CA_AP + (kc >> 1)) * 4;
            uint32_t sz = p ? 16u : 0u;
            asm volatile("cp.async.cg.shared.global [%0], [%1], 16, %2;"
                         :: "r"(dst), "l"(src), "r"(sz));
        }
#pragma unroll
        for (int q = 0; q < 2; q++) {
            int flat = q * 256 + tid;
            int kkw = flat >> 5, n4 = (flat & 31) * 4;
            int gkk = (k0 >> 1) + kkw, gn = bn + n4;
            bool p = (gkk < K2) && (gn < N);
            const uint32_t* src = p ? (Bp + (size_t)gkk * N + gn) : Bp;
            uint32_t dst = bbase + (uint32_t)(kkw * CA_BP + n4) * 4;
            uint32_t sz = p ? 16u : 0u;
            asm volatile("cp.async.cg.shared.global [%0], [%1], 16, %2;"
                         :: "r"(dst), "l"(src), "r"(sz));
        }
        asm volatile("cp.async.commit_group;");
    };

    issue(0, 0);
    if (steps > 1) issue(1, 32);

    for (int s = 0; s < steps; s++) {
        int buf = s % 3;
        if (s + 1 < steps) asm volatile("cp.async.wait_group 1;");
        else               asm volatile("cp.async.wait_group 0;");
        __syncthreads();
        if (s + 2 < steps) issue((s + 2) % 3, (s + 2) << 5);

        uint32_t abase = sb + (uint32_t)(buf * CA_STW) * 4;
        const uint32_t* bs = smw + buf * CA_STW + CA_ASZ;
#pragma unroll
        for (int kf = 0; kf < 2; kf++) {
            int kw = kf * 8;
            uint32_t af[2][4];
#pragma unroll
            for (int mf = 0; mf < 2; mf++) {
                int m0 = wm + mf * 16;
                uint32_t aaddr = abase +
                    (uint32_t)((m0 + lm_row) * CA_AP + kw + lm_kw) * 4;
                asm volatile(
                    "ldmatrix.sync.aligned.m8n8.x4.shared.b16 {%0,%1,%2,%3}, [%4];"
                    : "=r"(af[mf][0]), "=r"(af[mf][1]),
                      "=r"(af[mf][2]), "=r"(af[mf][3])
                    : "r"(aaddr));
            }
#pragma unroll
            for (int nf = 0; nf < 8; nf++) {
                int n0 = wn + nf * 8 + grp;
                uint32_t b0 = bs[(kw + tig    ) * CA_BP + n0];
                uint32_t b1 = bs[(kw + tig + 4) * CA_BP + n0];
                mma_fp16(cacc[0][nf], af[0], b0, b1);
                mma_fp16(cacc[1][nf], af[1], b0, b1);
            }
        }
    }

#pragma unroll
    for (int mf = 0; mf < 2; mf++) {
#pragma unroll
        for (int nf = 0; nf < 8; nf++) {
            int r0 = bm + wm + mf * 16 + grp;
            int c0 = bn + wn + nf * 8 + tig * 2;
            float c[4] = { cacc[mf][nf][0], cacc[mf][nf][1],
                           cacc[mf][nf][2], cacc[mf][nf][3] };
            if (FUSE) {
                float b0 = (c0     < N) ? bias[c0]     : 0.f;
                float b1 = (c0 + 1 < N) ? bias[c0 + 1] : 0.f;
                c[0] = fmaxf(c[0] + b0, 0.f);
                c[1] = fmaxf(c[1] + b1, 0.f);
                c[2] = fmaxf(c[2] + b0, 0.f);
                c[3] = fmaxf(c[3] + b1, 0.f);
            }
            if (c0 < N) {
                if (OUTF32) {
                    if (r0 < M)     *(float2*)&Cext[(size_t)r0 * N + c0] = make_float2(c[0], c[1]);
                    if (r0 + 8 < M) *(float2*)&Cext[(size_t)(r0 + 8) * N + c0] = make_float2(c[2], c[3]);
                } else {
                    if (r0 < M) {
                        __half2 h = __floats2half2_rn(c[0], c[1]);
                        *(uint32_t*)&Ch[(size_t)r0 * N + c0] = *(uint32_t*)&h;
                    }
                    if (r0 + 8 < M) {
                        __half2 h = __floats2half2_rn(c[2], c[3]);
                        *(uint32_t*)&Ch[(size_t)(r0 + 8) * N + c0] = *(uint32_t*)&h;
                    }
                }
            }
        }
    }
}

// ---------------- GAT aggregation (fp16 rows, 2-edge pipeline) -------------
template<int H, int C, int NP, int NV, int TPB>
__global__ void __launch_bounds__(TPB)
gat_agg_h(const float* __restrict__ bias)
{
    constexpr int HC  = H * C;
    constexpr int HC8 = HC / 8;
    constexpr int CHUNK = 64;
    int i = blockIdx.x;
    int tid = threadIdx.x;

    __shared__ float s_sc[CHUNK][4];
    __shared__ float s_alpha[CHUNK][4];
    __shared__ int   s_src[CHUNK];

    const __half* hbuf = g_bufB_h;
    __half* out = g_bufA_h;
    const __half* row = hbuf + (size_t)i * NP;

    float scS[4], scD[4];
    {
        uint4 v = *(const uint4*)&row[HC];
        __half2* p = (__half2*)&v;
        float2 f0 = __half22float2(p[0]), f1 = __half22float2(p[1]);
        float2 f2 = __half22float2(p[2]), f3 = __half22float2(p[3]);
        scS[0] = f0.x; scS[1] = f0.y; scS[2] = f1.x; scS[3] = f1.y;
        scD[0] = f2.x; scD[1] = f2.y; scD[2] = f3.x; scD[3] = f3.y;
    }

    float adsti[H], m[H], den[H], eself[H], aself[H];
#pragma unroll
    for (int h = 0; h < H; h++) {
        adsti[h] = scD[h];
        eself[h] = lrelu(scS[h] + adsti[h]);
        m[h] = eself[h];
        den[h] = 1.f;
    }

    int beg = g_ptr[i];
    int deg = g_ptr[i + 1] - beg;
    bool single = (deg <= CHUNK);

    for (int cb = 0; cb < deg; cb += CHUNK) {
        int cn = min(CHUNK, deg - cb);
        for (int t = tid; t < cn; t += TPB) {
            int s = g_csrsrc[beg + cb + t];
            s_src[t] = s;
            uint2 v = *(const uint2*)&hbuf[(size_t)s * NP + HC];
            __half2* p = (__half2*)&v;
            float2 f0 = __half22float2(p[0]), f1 = __half22float2(p[1]);
            s_sc[t][0] = f0.x; s_sc[t][1] = f0.y;
            s_sc[t][2] = f1.x; s_sc[t][3] = f1.y;
        }
        __syncthreads();
        for (int j = 0; j < cn; j++) {
#pragma unroll
            for (int h = 0; h < H; h++) {
                float e = lrelu(s_sc[j][h] + adsti[h]);
                float mo = m[h];
                float mn = fmaxf(mo, e);
                den[h] = den[h] * __expf(mo - mn) + __expf(e - mn);
                m[h] = mn;
            }
        }
        __syncthreads();
    }
#pragma unroll
    for (int h = 0; h < H; h++)
        aself[h] = __expf(eself[h] - m[h]) / (den[h] + 1e-16f);

    int c8i[NV];
    bool val[NV];
    int he[NV][8];
#pragma unroll
    for (int t = 0; t < NV; t++) {
        int c8 = tid + t * TPB;
        c8i[t] = c8;
        val[t] = (c8 < HC8);
#pragma unroll
        for (int e = 0; e < 8; e++)
            he[t][e] = min((c8 * 8 + e) / C, H - 1);
    }

    float acc[NV][8];
#pragma unroll
    for (int t = 0; t < NV; t++) {
        if (val[t]) {
            uint4 v = *(const uint4*)&row[c8i[t] * 8];
            __half2* p = (__half2*)&v;
            float2 q0 = __half22float2(p[0]), q1 = __half22float2(p[1]);
            float2 q2 = __half22float2(p[2]), q3 = __half22float2(p[3]);
            float f[8] = { q0.x, q0.y, q1.x, q1.y, q2.x, q2.y, q3.x, q3.y };
#pragma unroll
            for (int e = 0; e < 8; e++) acc[t][e] = aself[he[t][e]] * f[e];
        } else {
#pragma unroll
            for (int e = 0; e < 8; e++) acc[t][e] = 0.f;
        }
    }

    for (int cb = 0; cb < deg; cb += CHUNK) {
        int cn = min(CHUNK, deg - cb);
        __syncthreads();
        if (!single) {
            for (int t = tid; t < cn; t += TPB) {
                int s = g_csrsrc[beg + cb + t];
                s_src[t] = s;
                uint2 v = *(const uint2*)&hbuf[(size_t)s * NP + HC];
                __half2* p = (__half2*)&v;
                float2 f0 = __half22float2(p[0]), f1 = __half22float2(p[1]);
                s_sc[t][0] = f0.x; s_sc[t][1] = f0.y;
                s_sc[t][2] = f1.x; s_sc[t][3] = f1.y;
            }
            __syncthreads();
        }
        for (int t = tid; t < cn; t += TPB) {
#pragma unroll
            for (int h = 0; h < H; h++) {
                float e = lrelu(s_sc[t][h] + adsti[h]);
                s_alpha[t][h] = __expf(e - m[h]) / (den[h] + 1e-16f);
            }
        }
        __syncthreads();

        uint4 nxt0[NV], nxt1[NV];
        {
            const uint4* h0p = (const uint4*)(hbuf + (size_t)s_src[0] * NP);
            const uint4* h1p = (const uint4*)(hbuf + (size_t)s_src[cn > 1 ? 1 : 0] * NP);
#pragma unroll
            for (int t = 0; t < NV; t++) {
                if (val[t]) { nxt0[t] = h0p[c8i[t]]; nxt1[t] = h1p[c8i[t]]; }
            }
        }
        for (int j = 0; j < cn; j += 2) {
            uint4 cur0[NV], cur1[NV];
#pragma unroll
            for (int t = 0; t < NV; t++) { cur0[t] = nxt0[t]; cur1[t] = nxt1[t]; }
            if (j + 2 < cn) {
                const uint4* h0p = (const uint4*)(hbuf + (size_t)s_src[j + 2] * NP);
                const uint4* h1p = (const uint4*)(hbuf + (size_t)s_src[j + 3 < cn ? j + 3 : j + 2] * NP);
#pragma unroll
                for (int t = 0; t < NV; t++) {
                    if (val[t]) { nxt0[t] = h0p[c8i[t]]; nxt1[t] = h1p[c8i[t]]; }
                }
            }
            {
                float a0 = s_alpha[j][0];
                float a1 = (H > 1) ? s_alpha[j][1] : a0;
                float a2 = (H > 2) ? s_alpha[j][2] : a0;
                float a3 = (H > 3) ? s_alpha[j][3] : a0;
                float al[4] = { a0, a1, a2, a3 };
#pragma unroll
                for (int t = 0; t < NV; t++) {
                    if (!val[t]) continue;
                    __half2* p = (__half2*)&cur0[t];
                    float2 q0 = __half22float2(p[0]), q1 = __half22float2(p[1]);
                    float2 q2 = __half22float2(p[2]), q3 = __half22float2(p[3]);
                    float f[8] = { q0.x, q0.y, q1.x, q1.y, q2.x, q2.y, q3.x, q3.y };
#pragma unroll
                    for (int e = 0; e < 8; e++)
                        acc[t][e] = fmaf(al[he[t][e]], f[e], acc[t][e]);
                }
            }
            if (j + 1 < cn) {
                float a0 = s_alpha[j + 1][0];
                float a1 = (H > 1) ? s_alpha[j + 1][1] : a0;
                float a2 = (H > 2) ? s_alpha[j + 1][2] : a0;
                float a3 = (H > 3) ? s_alpha[j + 1][3] : a0;
                float al[4] = { a0, a1, a2, a3 };
#pragma unroll
                for (int t = 0; t < NV; t++) {
                    if (!val[t]) continue;
                    __half2* p = (__half2*)&cur1[t];
                    float2 q0 = __half22float2(p[0]), q1 = __half22float2(p[1]);
                    float2 q2 = __half22float2(p[2]), q3 = __half22float2(p[3]);
                    float f[8] = { q0.x, q0.y, q1.x, q1.y, q2.x, q2.y, q3.x, q3.y };
#pragma unroll
                    for (int e = 0; e < 8; e++)
                        acc[t][e] = fmaf(al[he[t][e]], f[e], acc[t][e]);
                }
            }
        }
    }

    __half* orow = out + (size_t)i * HC;
#pragma unroll
    for (int t = 0; t < NV; t++) {
        if (!val[t]) continue;
        int cb0 = c8i[t] * 8;
        float4 b0 = *(const float4*)&bias[cb0];
        float4 b1 = *(const float4*)&bias[cb0 + 4];
        float o[8];
        o[0] = fmaxf(acc[t][0] + b0.x, 0.f);
        o[1] = fmaxf(acc[t][1] + b0.y, 0.f);
        o[2] = fmaxf(acc[t][2] + b0.z, 0.f);
        o[3] = fmaxf(acc[t][3] + b0.w, 0.f);
        o[4] = fmaxf(acc[t][4] + b1.x, 0.f);
        o[5] = fmaxf(acc[t][5] + b1.y, 0.f);
        o[6] = fmaxf(acc[t][6] + b1.z, 0.f);
        o[7] = fmaxf(acc[t][7] + b1.w, 0.f);
        uint4 ov;
        __half2 h0 = __floats2half2_rn(o[0], o[1]);
        __half2 h1 = __floats2half2_rn(o[2], o[3]);
        __half2 h2 = __floats2half2_rn(o[4], o[5]);
        __half2 h3 = __floats2half2_rn(o[6], o[7]);
        ov.x = *(uint32_t*)&h0; ov.y = *(uint32_t*)&h1;
        ov.z = *(uint32_t*)&h2; ov.w = *(uint32_t*)&h3;
        *(uint4*)&orow[cb0] = ov;
    }
}

// ---------------- pool ----------------
__global__ void pool_max(const int* __restrict__ batch)
{
    int g = blockIdx.x;
    int c8 = blockIdx.y * 128 + threadIdx.x;

    int lo = 0, hi = NN;
    while (lo < hi) { int mid = (lo + hi) >> 1; if (batch[mid] < g) lo = mid + 1; else hi = mid; }
    int start = lo;
    lo = start; hi = NN;
    while (lo < hi) { int mid = (lo + hi) >> 1; if (batch[mid] < g + 1) lo = mid + 1; else hi = mid; }
    int end = lo;

    if (c8 < D3 / 8) {
        float mv[8];
#pragma unroll
        for (int e = 0; e < 8; e++) mv[e] = 0.f;
        for (int n = start; n < end; n++) {
            uint4 v = *(const uint4*)&g_bufA_h[(size_t)n * D3 + c8 * 8];
            __half2* p = (__half2*)&v;
            float2 q0 = __half22float2(p[0]), q1 = __half22float2(p[1]);
            float2 q2 = __half22float2(p[2]), q3 = __half22float2(p[3]);
            mv[0] = fmaxf(mv[0], q0.x); mv[1] = fmaxf(mv[1], q0.y);
            mv[2] = fmaxf(mv[2], q1.x); mv[3] = fmaxf(mv[3], q1.y);
            mv[4] = fmaxf(mv[4], q2.x); mv[5] = fmaxf(mv[5], q2.y);
            mv[6] = fmaxf(mv[6], q3.x); mv[7] = fmaxf(mv[7], q3.y);
        }
        uint4 ov;
        __half2 h0 = __floats2half2_rn(mv[0], mv[1]);
        __half2 h1 = __floats2half2_rn(mv[2], mv[3]);
        __half2 h2 = __floats2half2_rn(mv[4], mv[5]);
        __half2 h3 = __floats2half2_rn(mv[6], mv[7]);
        ov.x = *(uint32_t*)&h0; ov.y = *(uint32_t*)&h1;
        ov.z = *(uint32_t*)&h2; ov.w = *(uint32_t*)&h3;
        *(uint4*)&g_pool_h[g * D3 + c8 * 8] = ov;
    }
}

// ---------------- launch ----------------
extern "C" void kernel_launch(void* const* d_in, const int* in_sizes, int n_in,
                              void* d_out, int out_size)
{
    const float* x     = (const float*)d_in[0];
    const int*   ei    = (const int*)d_in[1];
    const int*   batch = (const int*)d_in[2];
    const float* W1 = (const float*)d_in[3];
    const float* as1 = (const float*)d_in[4];
    const float* ad1 = (const float*)d_in[5];
    const float* b1 = (const float*)d_in[6];
    const float* W2 = (const float*)d_in[7];
    const float* as2 = (const float*)d_in[8];
    const float* ad2 = (const float*)d_in[9];
    const float* b2 = (const float*)d_in[10];
    const float* W3 = (const float*)d_in[11];
    const float* as3 = (const float*)d_in[12];
    const float* ad3 = (const float*)d_in[13];
    const float* b3 = (const float*)d_in[14];
    const float* fc1_w = (const float*)d_in[15];
    const float* fc1_b = (const float*)d_in[16];
    const float* fc2_w = (const float*)d_in[17];
    const float* fc2_b = (const float*)d_in[18];
    float* outp = (float*)d_out;

    cudaFuncSetAttribute(hgemm_ca<0, 0>,
                         cudaFuncAttributeMaxDynamicSharedMemorySize, CA_SMEM_BYTES);
    cudaFuncSetAttribute(hgemm_ca<1, 0>,
                         cudaFuncAttributeMaxDynamicSharedMemorySize, CA_SMEM_BYTES);
    cudaFuncSetAttribute(hgemm_ca<1, 1>,
                         cudaFuncAttributeMaxDynamicSharedMemorySize, CA_SMEM_BYTES);

    zero_counts_kernel<<<(NN + 255) / 256, 256>>>();
    hist_kernel<<<(EE + 255) / 256, 256>>>(ei);
    scan_kernel<<<1, 1024>>>();
    csr_fill_kernel<<<(EE + 255) / 256, 256>>>(ei);
    prep_pack<<<(PREP_TOTAL + 255) / 256, 256>>>(x, W1, W2, W3, fc1_w, fc2_w);
    ws_all<<<(WS_TOTAL * 32 + 255) / 256, 256>>>(W1, as1, ad1, W2, as2, ad2, W3, as3, ad3);

    dim3 blk(256);
    {
        dim3 grid((NP1 + 127) / 128, (NN + 127) / 128);
        hgemm_ca<0, 0><<<grid, blk, CA_SMEM_BYTES>>>(5, 7, nullptr, 2, NN, NP1, K1PAD, nullptr);
        gat_agg_h<HEADS, D1, NP1, 1, 64><<<NN, 64>>>(b1);
    }
    {
        dim3 grid((NP23 + 127) / 128, (NN + 127) / 128);
        hgemm_ca<0, 0><<<grid, blk, CA_SMEM_BYTES>>>(1, 8, nullptr, 2, NN, NP23, D2, nullptr);
        gat_agg_h<HEADS, D2, NP23, 2, 128><<<NN, 128>>>(b2);
    }
    {
        dim3 grid((NP23 + 127) / 128, (NN + 127) / 128);
        hgemm_ca<0, 0><<<grid, blk, CA_SMEM_BYTES>>>(1, 9, nullptr, 2, NN, NP23, D3, nullptr);
        gat_agg_h<1, D3, NP23, 2, 128><<<NN, 128>>>(b3);
    }
    {
        dim3 pg(GG, (D3 / 8 + 127) / 128);
        pool_max<<<pg, 128>>>(batch);
        dim3 g1((HID + 127) / 128, (GG + 127) / 128);
        hgemm_ca<1, 0><<<g1, blk, CA_SMEM_BYTES>>>(3, 10, nullptr, 4, GG, HID, D3, fc1_b);
        dim3 g2((OUTD + 127) / 128, (GG + 127) / 128);
        hgemm_ca<1, 1><<<g2, blk, CA_SMEM_BYTES>>>(4, 11, outp, 0, GG, OUTD, HID, fc2_b);
    }
    (void)n_in; (void)in_sizes; (void)out_size;
}